// round 3
// baseline (speedup 1.0000x reference)
#include <cuda_runtime.h>
#include <cstdint>
#include <cstddef>

// ---------------------------------------------------------------------------
// Problem constants
// ---------------------------------------------------------------------------
#define BB    256      // batch
#define SS    32       // seq len
#define II    128      // input dim
#define HH    256      // hidden
#define LBL   200      // label
#define NSUB  491
#define NATOMS 8000
#define NMOL  600

// ---------------------------------------------------------------------------
// Scratch (static __device__ — no allocation anywhere)
// ---------------------------------------------------------------------------
__device__ float g_xp[2 * BB * SS * 3 * HH];       // GRU input projections (both GRUs) ~50MB
__device__ float g_h[2][2 * BB * HH];              // ping-pong hidden state [pp][g*B*H]
__device__ float g_hlast[2 * BB * HH];             // h at last-visit index
__device__ int   g_idxlast[BB];
__device__ int   g_molstart[NMOL + 1];
__device__ float g_pat[BB * 2 * HH];               // relu(concat(h_c, h_p))
__device__ float g_query[BB * HH];
__device__ float g_v[NATOMS * HH];
__device__ float g_hv[NATOMS * HH];
__device__ float g_molsum[NMOL * HH];
__device__ float g_emb[LBL * HH];
__device__ float g_match[BB * LBL];
__device__ float g_att[BB * LBL];
__device__ float g_bip[BB * NSUB];
__device__ float g_wm[NSUB * LBL];

// ---------------------------------------------------------------------------
// Helpers: packed dual-fp32 FMA (Blackwell f32x2 path)
// ---------------------------------------------------------------------------
__device__ __forceinline__ unsigned long long ffma2(unsigned long long a,
                                                    unsigned long long b,
                                                    unsigned long long c) {
#if defined(__CUDA_ARCH__) && (__CUDA_ARCH__ >= 1000)
    unsigned long long d;
    asm("fma.rn.f32x2 %0, %1, %2, %3;" : "=l"(d) : "l"(a), "l"(b), "l"(c));
    return d;
#else
    float2 af, bf, cf, df;
    af = *reinterpret_cast<float2*>(&a);
    bf = *reinterpret_cast<float2*>(&b);
    cf = *reinterpret_cast<float2*>(&c);
    df.x = fmaf(af.x, bf.x, cf.x);
    df.y = fmaf(af.y, bf.y, cf.y);
    return *reinterpret_cast<unsigned long long*>(&df);
#endif
}

__device__ __forceinline__ unsigned long long lds64(const float* p) {
    return *reinterpret_cast<const unsigned long long*>(p);
}

__device__ __forceinline__ float unpack_sum(unsigned long long u) {
    return __uint_as_float((unsigned)u) + __uint_as_float((unsigned)(u >> 32));
}

__device__ __forceinline__ float sigmoidf_(float x) {
    return 1.f / (1.f + expf(-x));
}

// ---------------------------------------------------------------------------
// Generic tiled GEMM: C[M,N] = act( A[M,K] * op(B) + bias ) (* mul)
//   transB=1: C[i][j] = sum_k A[i*K+k] * B[j*K+k]   (B row-major [N,K])
//   transB=0: C[i][j] = sum_k A[i*K+k] * B[k*N+j]   (B row-major [K,N])
//   act: 0 none, 1 relu, 2 sigmoid.  mul: optional elementwise [M,N] multiplier.
// 64x64 tile, K-tile 32, 256 threads, 4x4 register tile, f32x2 inner loop.
// ---------------------------------------------------------------------------
__global__ void gemm_kernel(const float* __restrict__ A, const float* __restrict__ Bm,
                            const float* __restrict__ bias, const float* __restrict__ mul,
                            float* __restrict__ C,
                            int M, int N, int K, int transB, int act)
{
    __shared__ float As[64][34];   // [row][k], pitch 34 (even -> 8B aligned rows)
    __shared__ float Bs[64][34];   // [col][k]
    const int tid = threadIdx.x;
    const int tx = tid & 15, ty = tid >> 4;
    const int m0 = blockIdx.y * 64, n0 = blockIdx.x * 64;

    unsigned long long acc[4][4];
#pragma unroll
    for (int q = 0; q < 4; q++)
#pragma unroll
        for (int p = 0; p < 4; p++) acc[q][p] = 0ull;

    for (int k0 = 0; k0 < K; k0 += 32) {
        // stage A tile 64x32
        for (int idx = tid; idx < 64 * 32; idx += 256) {
            int r = idx >> 5, k = idx & 31;
            int gm = m0 + r, gk = k0 + k;
            As[r][k] = (gm < M && gk < K) ? A[(size_t)gm * K + gk] : 0.f;
        }
        // stage B tile 64x32 as Bs[col][k]
        if (transB) {
            for (int idx = tid; idx < 64 * 32; idx += 256) {
                int cJ = idx >> 5, k = idx & 31;
                int gn = n0 + cJ, gk = k0 + k;
                Bs[cJ][k] = (gn < N && gk < K) ? Bm[(size_t)gn * K + gk] : 0.f;
            }
        } else {
            for (int idx = tid; idx < 64 * 32; idx += 256) {
                int k = idx >> 6, cJ = idx & 63;
                int gn = n0 + cJ, gk = k0 + k;
                Bs[cJ][k] = (gn < N && gk < K) ? Bm[(size_t)gk * N + gn] : 0.f;
            }
        }
        __syncthreads();

#pragma unroll 4
        for (int k2 = 0; k2 < 16; k2++) {
            unsigned long long a2[4], b2[4];
#pragma unroll
            for (int q = 0; q < 4; q++) a2[q] = lds64(&As[ty + 16 * q][2 * k2]);
#pragma unroll
            for (int p = 0; p < 4; p++) b2[p] = lds64(&Bs[tx + 16 * p][2 * k2]);
#pragma unroll
            for (int q = 0; q < 4; q++)
#pragma unroll
                for (int p = 0; p < 4; p++)
                    acc[q][p] = ffma2(a2[q], b2[p], acc[q][p]);
        }
        __syncthreads();
    }

#pragma unroll
    for (int q = 0; q < 4; q++) {
        int gm = m0 + ty + 16 * q;
        if (gm >= M) continue;
#pragma unroll
        for (int p = 0; p < 4; p++) {
            int gn = n0 + tx + 16 * p;
            if (gn >= N) continue;
            float v = unpack_sum(acc[q][p]);
            if (bias) v += bias[gn];
            if (act == 1) v = fmaxf(v, 0.f);
            else if (act == 2) v = sigmoidf_(v);
            if (mul) v *= mul[(size_t)gm * N + gn];
            C[(size_t)gm * N + gn] = v;
        }
    }
}

// ---------------------------------------------------------------------------
// Small prep kernels
// ---------------------------------------------------------------------------
__global__ void prep_idx_kernel(const int* __restrict__ mask) {
    int b = threadIdx.x;
    if (b < BB) {
        int s = 0;
        for (int j = 0; j < SS; j++) s += mask[b * SS + j];
        g_idxlast[b] = s - 1;
    }
}

__global__ void molstart_kernel(const int* __restrict__ seg) {
    int stride = gridDim.x * blockDim.x;
    for (int i = blockIdx.x * blockDim.x + threadIdx.x; i < NATOMS; i += stride) {
        if (i == 0) {
            g_molstart[seg[0]] = 0;
            g_molstart[NMOL] = NATOMS;
        } else if (seg[i] != seg[i - 1]) {
            g_molstart[seg[i]] = i;
        }
    }
}

__global__ void zero_h_kernel() {
    int i = blockIdx.x * blockDim.x + threadIdx.x;
    if (i < 2 * BB * HH) g_h[0][i] = 0.f;
}

// ---------------------------------------------------------------------------
// GRU step: for both GRUs (z-dim), gates = h_prev @ w_hh^T + b_hh, fused update.
// Tile: 32 batches x 16 hcols (=> 48 gate rows), K staged in 64-chunks.
// 128 threads: thread -> (c = tid&15, bq = tid>>4), computes 4 batches x 3 gates.
// ---------------------------------------------------------------------------
__global__ void gru_step_kernel(const float* __restrict__ whh_c,
                                const float* __restrict__ whh_p,
                                const float* __restrict__ bhh_c,
                                const float* __restrict__ bhh_p,
                                int t)
{
    __shared__ float h_s[32][66];
    __shared__ float w_s[48][66];
    const int tid = threadIdx.x;
    const int c = tid & 15;
    const int bq = tid >> 4;
    const int g = blockIdx.z;
    const int c0 = blockIdx.x * 16;
    const int b0 = blockIdx.y * 32;
    const float* whh = g ? whh_p : whh_c;
    const float* bhh = g ? bhh_p : bhh_c;
    const float* hsrc = g_h[t & 1] + g * (BB * HH);
    float*       hdst = g_h[(t + 1) & 1] + g * (BB * HH);

    unsigned long long acc[4][3];
#pragma unroll
    for (int i = 0; i < 4; i++)
#pragma unroll
        for (int gt = 0; gt < 3; gt++) acc[i][gt] = 0ull;

    for (int k0 = 0; k0 < HH; k0 += 64) {
        for (int idx = tid; idx < 32 * 64; idx += 128) {
            int b = idx >> 6, k = idx & 63;
            h_s[b][k] = hsrc[(b0 + b) * HH + k0 + k];
        }
        for (int idx = tid; idx < 48 * 64; idx += 128) {
            int gr = idx >> 6, k = idx & 63;
            int grow = (gr >> 4) * HH + c0 + (gr & 15);
            w_s[gr][k] = whh[grow * HH + k0 + k];
        }
        __syncthreads();

#pragma unroll 4
        for (int k2 = 0; k2 < 32; k2++) {
            unsigned long long h2[4], w2[3];
#pragma unroll
            for (int i = 0; i < 4; i++) h2[i] = lds64(&h_s[bq + 8 * i][2 * k2]);
#pragma unroll
            for (int gt = 0; gt < 3; gt++) w2[gt] = lds64(&w_s[gt * 16 + c][2 * k2]);
#pragma unroll
            for (int i = 0; i < 4; i++)
#pragma unroll
                for (int gt = 0; gt < 3; gt++)
                    acc[i][gt] = ffma2(h2[i], w2[gt], acc[i][gt]);
        }
        __syncthreads();
    }

    const int col = c0 + c;
#pragma unroll
    for (int i = 0; i < 4; i++) {
        int b = b0 + bq + 8 * i;
        float hr = unpack_sum(acc[i][0]) + bhh[col];
        float hz = unpack_sum(acc[i][1]) + bhh[HH + col];
        float hn = unpack_sum(acc[i][2]) + bhh[2 * HH + col];
        const float* xp = g_xp + ((size_t)g * BB * SS + (size_t)b * SS + t) * (3 * HH);
        float r = sigmoidf_(xp[col] + hr);
        float z = sigmoidf_(xp[HH + col] + hz);
        float n = tanhf(xp[2 * HH + col] + r * hn);
        float hp = hsrc[b * HH + col];
        float hnew = (1.f - z) * n + z * hp;
        hdst[b * HH + col] = hnew;
        if (t == g_idxlast[b]) g_hlast[g * (BB * HH) + b * HH + col] = hnew;
    }
}

// ---------------------------------------------------------------------------
// relu(concat(h_c_last, h_p_last)) -> g_pat[B, 2H]
// ---------------------------------------------------------------------------
__global__ void concat_relu_kernel() {
    int b = blockIdx.x, tid = threadIdx.x;   // 512 threads
    int g = tid >> 8, cc = tid & 255;
    float v = g_hlast[g * (BB * HH) + b * HH + cc];
    g_pat[b * (2 * HH) + tid] = fmaxf(v, 0.f);
}

// ---------------------------------------------------------------------------
// Fingerprint gather: v = embed_fp[fingerprints]
// ---------------------------------------------------------------------------
__global__ void gather_kernel(const float* __restrict__ embed_fp,
                              const int* __restrict__ fp) {
    int a = blockIdx.x, c = threadIdx.x;
    g_v[a * HH + c] = embed_fp[(size_t)fp[a] * HH + c];
}

// ---------------------------------------------------------------------------
// Block-diagonal adjacency: v_out = hv + adj_block @ hv (per molecule)
// ---------------------------------------------------------------------------
__global__ void adj_kernel(const float* __restrict__ adj) {
    int m = blockIdx.x, tid = threadIdx.x;   // 256 threads = H columns
    int s = g_molstart[m], e = g_molstart[m + 1];
    int na = e - s;                           // <= 14
    __shared__ float hs[14][HH];
    __shared__ float as[14][14];
    for (int a = 0; a < na; a++) hs[a][tid] = g_hv[(s + a) * HH + tid];
    for (int idx = tid; idx < na * na; idx += 256) {
        int i = idx / na, j = idx - i * na;
        as[i][j] = adj[(size_t)(s + i) * NATOMS + (s + j)];
    }
    __syncthreads();
    for (int i = 0; i < na; i++) {
        float acc = hs[i][tid];
        for (int j = 0; j < na; j++) acc = fmaf(as[i][j], hs[j][tid], acc);
        g_v[(s + i) * HH + tid] = acc;
    }
}

// ---------------------------------------------------------------------------
// Per-molecule segment sum
// ---------------------------------------------------------------------------
__global__ void molsum_kernel() {
    int m = blockIdx.x, c = threadIdx.x;
    int s = g_molstart[m], e = g_molstart[m + 1];
    float acc = 0.f;
    for (int i = s; i < e; i++) acc += g_v[i * HH + c];
    g_molsum[m * HH + c] = acc;
}

// ---------------------------------------------------------------------------
// x2 = match + match @ w_out + b_out; layernorm -> g_att  (block per batch)
// ---------------------------------------------------------------------------
__global__ void att_kernel(const float* __restrict__ w_out, const float* __restrict__ b_out,
                           const float* __restrict__ gamma, const float* __restrict__ beta)
{
    int b = blockIdx.x, tid = threadIdx.x;   // 256 threads, 200 active
    __shared__ float mrow[LBL];
    __shared__ float red[256];
    if (tid < LBL) mrow[tid] = g_match[b * LBL + tid];
    __syncthreads();
    float x2 = 0.f;
    if (tid < LBL) {
        float acc = 0.f;
        for (int k = 0; k < LBL; k++) acc = fmaf(mrow[k], w_out[k * LBL + tid], acc);
        x2 = mrow[tid] + acc + b_out[tid];
    }
    red[tid] = (tid < LBL) ? x2 : 0.f;
    __syncthreads();
    for (int s2 = 128; s2 > 0; s2 >>= 1) {
        if (tid < s2) red[tid] += red[tid + s2];
        __syncthreads();
    }
    float mean = red[0] * (1.f / LBL);
    __syncthreads();
    float d = x2 - mean;
    red[tid] = (tid < LBL) ? d * d : 0.f;
    __syncthreads();
    for (int s2 = 128; s2 > 0; s2 >>= 1) {
        if (tid < s2) red[tid] += red[tid + s2];
        __syncthreads();
    }
    float var = red[0] * (1.f / LBL);
    if (tid < LBL)
        g_att[b * LBL + tid] = d * rsqrtf(var + 1e-5f) * gamma[tid] + beta[tid];
}

// ---------------------------------------------------------------------------
// Masked bipartite weight: wm[k][j] = w_masklin[k][j] * ddi[j][k]
// ---------------------------------------------------------------------------
__global__ void wm_kernel(const float* __restrict__ w_masklin,
                          const float* __restrict__ ddi) {
    int idx = blockIdx.x * blockDim.x + threadIdx.x;
    if (idx < NSUB * LBL) {
        int k = idx / LBL, j = idx - k * LBL;
        g_wm[idx] = w_masklin[idx] * ddi[j * NSUB + k];
    }
}

// ---------------------------------------------------------------------------
// Launch orchestration
// ---------------------------------------------------------------------------
extern "C" void kernel_launch(void* const* d_in, const int* in_sizes, int n_in,
                              void* d_out, int out_size) {
    // inputs in metadata order (= setup_inputs dict order)
    const float* x_c      = (const float*)d_in[0];
    const float* x_p      = (const float*)d_in[1];
    const int*   mask     = (const int*)  d_in[2];
    const float* w_ih_c   = (const float*)d_in[3];
    const float* w_hh_c   = (const float*)d_in[4];
    const float* b_ih_c   = (const float*)d_in[5];
    const float* b_hh_c   = (const float*)d_in[6];
    const float* w_ih_p   = (const float*)d_in[7];
    const float* w_hh_p   = (const float*)d_in[8];
    const float* b_ih_p   = (const float*)d_in[9];
    const float* b_hh_p   = (const float*)d_in[10];
    const float* w_query  = (const float*)d_in[11];
    const float* b_query  = (const float*)d_in[12];
    const float* w_bip    = (const float*)d_in[13];
    const float* b_bip    = (const float*)d_in[14];
    const float* w_mlin   = (const float*)d_in[15];
    const float* ddi      = (const float*)d_in[16];
    const float* embed_fp = (const float*)d_in[17];
    const int*   fp       = (const int*)  d_in[18];
    const float* adj      = (const float*)d_in[19];
    const int*   seg      = (const int*)  d_in[20];
    const float* w_g0     = (const float*)d_in[21];
    const float* b_g0     = (const float*)d_in[22];
    const float* w_g1     = (const float*)d_in[23];
    const float* b_g1     = (const float*)d_in[24];
    const float* avgproj  = (const float*)d_in[25];
    const float* w_out    = (const float*)d_in[26];
    const float* b_out    = (const float*)d_in[27];
    const float* ln_g     = (const float*)d_in[28];
    const float* ln_b     = (const float*)d_in[29];
    float* outp = (float*)d_out;

    float *xp, *pat, *query, *v, *hv, *molsumv, *emb, *match, *bip, *wm, *att;
    cudaGetSymbolAddress((void**)&xp,      g_xp);
    cudaGetSymbolAddress((void**)&pat,     g_pat);
    cudaGetSymbolAddress((void**)&query,   g_query);
    cudaGetSymbolAddress((void**)&v,       g_v);
    cudaGetSymbolAddress((void**)&hv,      g_hv);
    cudaGetSymbolAddress((void**)&molsumv, g_molsum);
    cudaGetSymbolAddress((void**)&emb,     g_emb);
    cudaGetSymbolAddress((void**)&match,   g_match);
    cudaGetSymbolAddress((void**)&bip,     g_bip);
    cudaGetSymbolAddress((void**)&wm,      g_wm);
    cudaGetSymbolAddress((void**)&att,     g_att);

    // prep
    prep_idx_kernel<<<1, 256>>>(mask);
    molstart_kernel<<<32, 256>>>(seg);
    zero_h_kernel<<<(2 * BB * HH + 255) / 256, 256>>>();

    // GRU input projections: xp = x @ w_ih^T + b_ih (M=8192, N=768, K=128)
    {
        dim3 grid((3 * HH + 63) / 64, (BB * SS + 63) / 64);
        gemm_kernel<<<grid, 256>>>(x_c, w_ih_c, b_ih_c, nullptr, xp,
                                   BB * SS, 3 * HH, II, 1, 0);
        gemm_kernel<<<grid, 256>>>(x_p, w_ih_p, b_ih_p, nullptr,
                                   xp + (size_t)BB * SS * 3 * HH,
                                   BB * SS, 3 * HH, II, 1, 0);
    }

    // GRU recurrence: 32 sequential steps, both GRUs per launch
    {
        dim3 grid(HH / 16, BB / 32, 2);
        for (int t = 0; t < SS; t++)
            gru_step_kernel<<<grid, 128>>>(w_hh_c, w_hh_p, b_hh_c, b_hh_p, t);
    }

    // query = relu(concat) @ w_query + b_query   (M=256, N=256, K=512)
    concat_relu_kernel<<<BB, 512>>>();
    gemm_kernel<<<dim3(4, 4), 256>>>(pat, w_query, b_query, nullptr, query,
                                     BB, HH, 2 * HH, 0, 0);

    // MPNN
    gather_kernel<<<NATOMS, HH>>>(embed_fp, fp);
    {
        dim3 grid((HH + 63) / 64, (NATOMS + 63) / 64);
        gemm_kernel<<<grid, 256>>>(v, w_g0, b_g0, nullptr, hv, NATOMS, HH, HH, 0, 1);
        adj_kernel<<<NMOL, HH>>>(adj);
        gemm_kernel<<<grid, 256>>>(v, w_g1, b_g1, nullptr, hv, NATOMS, HH, HH, 0, 1);
        adj_kernel<<<NMOL, HH>>>(adj);
    }
    molsum_kernel<<<NMOL, HH>>>();
    // mpnn_emb = avgproj @ molsum   (M=200, N=256, K=600)
    gemm_kernel<<<dim3(4, 4), 256>>>(avgproj, molsumv, nullptr, nullptr, emb,
                                     LBL, HH, NMOL, 0, 0);

    // match = sigmoid(query @ emb^T)   (M=256, N=200, K=256)
    gemm_kernel<<<dim3(4, 4), 256>>>(query, emb, nullptr, nullptr, match,
                                     BB, LBL, HH, 1, 2);
    // x2 + layernorm -> g_att
    att_kernel<<<BB, 256>>>(w_out, b_out, ln_g, ln_b);

    // bip = query @ w_bip + b_bip   (M=256, N=491, K=256)
    gemm_kernel<<<dim3(8, 4), 256>>>(query, w_bip, b_bip, nullptr, bip,
                                     BB, NSUB, HH, 0, 0);
    // masked weight
    wm_kernel<<<(NSUB * LBL + 255) / 256, 256>>>(w_mlin, ddi);
    // out = (bip @ wm) * mpnn_att   (M=256, N=200, K=491)
    gemm_kernel<<<dim3(4, 4), 256>>>(bip, wm, nullptr, att, outp,
                                     BB, LBL, NSUB, 0, 0);
}

// round 4
// speedup vs baseline: 1.7244x; 1.7244x over previous
#include <cuda_runtime.h>
#include <cstdint>
#include <cstddef>

// ---------------------------------------------------------------------------
// Problem constants
// ---------------------------------------------------------------------------
#define BB    256      // batch
#define SS    32       // seq len
#define II    128      // input dim
#define HH    256      // hidden
#define LBL   200      // label
#define NSUB  491
#define NATOMS 8000
#define NMOL  600

// ---------------------------------------------------------------------------
// Scratch (static __device__ — no allocation anywhere)
// ---------------------------------------------------------------------------
__device__ __align__(16) float g_xp[2 * BB * SS * 3 * HH];
__device__ __align__(16) float g_h[2][2 * BB * HH];
__device__ __align__(16) float g_hlast[2 * BB * HH];
__device__ int   g_idxlast[BB];
__device__ int   g_molstart[NMOL + 1];
__device__ __align__(16) float g_pat[BB * 2 * HH];
__device__ __align__(16) float g_query[BB * HH];
__device__ __align__(16) float g_v[NATOMS * HH];
__device__ __align__(16) float g_hv[NATOMS * HH];
__device__ __align__(16) float g_molsumT[HH * NMOL];   // transposed [H][NMOL]
__device__ __align__(16) float g_emb[LBL * HH];
__device__ __align__(16) float g_match[BB * LBL];
__device__ __align__(16) float g_att[BB * LBL];
__device__ __align__(16) float g_bip[BB * NSUB];
__device__ __align__(16) float g_wm[NSUB * LBL];
// pre-transposed weights (so all fast GEMMs are transB with K-contiguous rows)
__device__ __align__(16) float g_wqT[HH * 2 * HH];     // [256][512]
__device__ __align__(16) float g_wg0T[HH * HH];
__device__ __align__(16) float g_wg1T[HH * HH];
__device__ __align__(16) float g_wbipT[NSUB * HH];     // [491][256]

// ---------------------------------------------------------------------------
// Helpers
// ---------------------------------------------------------------------------
__device__ __forceinline__ unsigned long long ffma2(unsigned long long a,
                                                    unsigned long long b,
                                                    unsigned long long c) {
#if defined(__CUDA_ARCH__) && (__CUDA_ARCH__ >= 1000)
    unsigned long long d;
    asm("fma.rn.f32x2 %0, %1, %2, %3;" : "=l"(d) : "l"(a), "l"(b), "l"(c));
    return d;
#else
    float2 af = *reinterpret_cast<float2*>(&a);
    float2 bf = *reinterpret_cast<float2*>(&b);
    float2 cf = *reinterpret_cast<float2*>(&c);
    float2 df;
    df.x = fmaf(af.x, bf.x, cf.x);
    df.y = fmaf(af.y, bf.y, cf.y);
    return *reinterpret_cast<unsigned long long*>(&df);
#endif
}

__device__ __forceinline__ unsigned long long lds64(const float* p) {
    return *reinterpret_cast<const unsigned long long*>(p);
}

__device__ __forceinline__ float unpack_sum(unsigned long long u) {
    return __uint_as_float((unsigned)u) + __uint_as_float((unsigned)(u >> 32));
}

__device__ __forceinline__ float sigmoidf_(float x) {
    return 1.f / (1.f + expf(-x));
}

__device__ __forceinline__ void cp16(float* dst, const float* src, bool p) {
    unsigned s = (unsigned)__cvta_generic_to_shared(dst);
    int n = p ? 16 : 0;
    asm volatile("cp.async.ca.shared.global [%0], [%1], 16, %2;"
                 :: "r"(s), "l"(src), "r"(n));
}
__device__ __forceinline__ void cp8(float* dst, const float* src, bool p) {
    unsigned s = (unsigned)__cvta_generic_to_shared(dst);
    int n = p ? 8 : 0;
    asm volatile("cp.async.ca.shared.global [%0], [%1], 8, %2;"
                 :: "r"(s), "l"(src), "r"(n));
}
__device__ __forceinline__ void cp_commit() { asm volatile("cp.async.commit_group;"); }
__device__ __forceinline__ void cp_wait0()  { asm volatile("cp.async.wait_group 0;"); }

// ---------------------------------------------------------------------------
// Fast GEMM (transB only): C[M,N] = act( A[M,K] * B[N,K]^T + bias ) (* mul)
// Requires K % 4 == 0 and A/B rows 16B-aligned (K*4 % 16 == 0).
// 256 threads, block tile 128x64, K-chunk 32, double-buffered cp.async,
// 8x4 f32x2 register tile, XOR-swizzled float4 smem.
// ---------------------------------------------------------------------------
__global__ void __launch_bounds__(256, 1)
gemm_f(const float* __restrict__ A, const float* __restrict__ Bm,
       const float* __restrict__ bias, const float* __restrict__ mul,
       float* __restrict__ C, int M, int N, int K, int act)
{
    extern __shared__ float sm[];
    float* As = sm;              // [2][128][32]
    float* Bs = sm + 2 * 128 * 32; // [2][64][32]
    const int tid = threadIdx.x;
    const int tx = tid & 15, ty = tid >> 4;
    const int m0 = blockIdx.y * 128, n0 = blockIdx.x * 64;
    const int nchunks = (K + 31) / 32;

    unsigned long long acc[8][4];
#pragma unroll
    for (int q = 0; q < 8; q++)
#pragma unroll
        for (int p = 0; p < 4; p++) acc[q][p] = 0ull;

    // stage chunk k0 into buffer buf
    auto stage = [&](int buf, int k0) {
        float* Ab = As + buf * (128 * 32);
        float* Bb = Bs + buf * (64 * 32);
#pragma unroll
        for (int j = 0; j < 4; j++) {                    // A: 1024 float4
            int idx = tid + 256 * j;
            int r = idx >> 3, kf4 = idx & 7;
            int gm = m0 + r, gk = k0 + kf4 * 4;
            bool pr = (gm < M) && (gk < K);
            const float* src = pr ? (A + (size_t)gm * K + gk) : A;
            cp16(Ab + r * 32 + ((kf4 ^ (r & 7)) << 2), src, pr);
        }
#pragma unroll
        for (int j = 0; j < 2; j++) {                    // B: 512 float4
            int idx = tid + 256 * j;
            int r = idx >> 3, kf4 = idx & 7;
            int gn = n0 + r, gk = k0 + kf4 * 4;
            bool pr = (gn < N) && (gk < K);
            const float* src = pr ? (Bm + (size_t)gn * K + gk) : Bm;
            cp16(Bb + r * 32 + ((kf4 ^ (r & 7)) << 2), src, pr);
        }
        cp_commit();
    };

    stage(0, 0);
    int buf = 0;
    for (int c = 0; c < nchunks; c++) {
        cp_wait0();
        __syncthreads();
        if (c + 1 < nchunks) stage(buf ^ 1, (c + 1) * 32);
        const float* Ab = As + buf * (128 * 32);
        const float* Bb = Bs + buf * (64 * 32);
#pragma unroll
        for (int k4 = 0; k4 < 8; k4++) {
            ulonglong2 a[8], b[4];
#pragma unroll
            for (int q = 0; q < 8; q++) {
                int r = ty + 16 * q;
                a[q] = *reinterpret_cast<const ulonglong2*>(
                    Ab + r * 32 + ((k4 ^ (r & 7)) << 2));
            }
#pragma unroll
            for (int p = 0; p < 4; p++) {
                int r = tx + 16 * p;
                b[p] = *reinterpret_cast<const ulonglong2*>(
                    Bb + r * 32 + ((k4 ^ (r & 7)) << 2));
            }
#pragma unroll
            for (int q = 0; q < 8; q++)
#pragma unroll
                for (int p = 0; p < 4; p++) {
                    acc[q][p] = ffma2(a[q].x, b[p].x, acc[q][p]);
                    acc[q][p] = ffma2(a[q].y, b[p].y, acc[q][p]);
                }
        }
        buf ^= 1;
    }

#pragma unroll
    for (int q = 0; q < 8; q++) {
        int gm = m0 + ty + 16 * q;
        if (gm >= M) continue;
#pragma unroll
        for (int p = 0; p < 4; p++) {
            int gn = n0 + tx + 16 * p;
            if (gn >= N) continue;
            float v = unpack_sum(acc[q][p]);
            if (bias) v += bias[gn];
            if (act == 1) v = fmaxf(v, 0.f);
            else if (act == 2) v = sigmoidf_(v);
            if (mul) v *= mul[(size_t)gm * N + gn];
            C[(size_t)gm * N + gn] = v;
        }
    }
}

// ---------------------------------------------------------------------------
// Generic (slow) GEMM — kept only for the odd-K final matmul (K=491, transB=0)
// ---------------------------------------------------------------------------
__global__ void gemm_kernel(const float* __restrict__ A, const float* __restrict__ Bm,
                            const float* __restrict__ bias, const float* __restrict__ mul,
                            float* __restrict__ C,
                            int M, int N, int K, int transB, int act)
{
    __shared__ float As[64][34];
    __shared__ float Bs[64][34];
    const int tid = threadIdx.x;
    const int tx = tid & 15, ty = tid >> 4;
    const int m0 = blockIdx.y * 64, n0 = blockIdx.x * 64;

    unsigned long long acc[4][4];
#pragma unroll
    for (int q = 0; q < 4; q++)
#pragma unroll
        for (int p = 0; p < 4; p++) acc[q][p] = 0ull;

    for (int k0 = 0; k0 < K; k0 += 32) {
        for (int idx = tid; idx < 64 * 32; idx += 256) {
            int r = idx >> 5, k = idx & 31;
            int gm = m0 + r, gk = k0 + k;
            As[r][k] = (gm < M && gk < K) ? A[(size_t)gm * K + gk] : 0.f;
        }
        if (transB) {
            for (int idx = tid; idx < 64 * 32; idx += 256) {
                int cJ = idx >> 5, k = idx & 31;
                int gn = n0 + cJ, gk = k0 + k;
                Bs[cJ][k] = (gn < N && gk < K) ? Bm[(size_t)gn * K + gk] : 0.f;
            }
        } else {
            for (int idx = tid; idx < 64 * 32; idx += 256) {
                int k = idx >> 6, cJ = idx & 63;
                int gn = n0 + cJ, gk = k0 + k;
                Bs[cJ][k] = (gn < N && gk < K) ? Bm[(size_t)gk * N + gn] : 0.f;
            }
        }
        __syncthreads();
#pragma unroll 4
        for (int k2 = 0; k2 < 16; k2++) {
            unsigned long long a2[4], b2[4];
#pragma unroll
            for (int q = 0; q < 4; q++) a2[q] = lds64(&As[ty + 16 * q][2 * k2]);
#pragma unroll
            for (int p = 0; p < 4; p++) b2[p] = lds64(&Bs[tx + 16 * p][2 * k2]);
#pragma unroll
            for (int q = 0; q < 4; q++)
#pragma unroll
                for (int p = 0; p < 4; p++)
                    acc[q][p] = ffma2(a2[q], b2[p], acc[q][p]);
        }
        __syncthreads();
    }

#pragma unroll
    for (int q = 0; q < 4; q++) {
        int gm = m0 + ty + 16 * q;
        if (gm >= M) continue;
#pragma unroll
        for (int p = 0; p < 4; p++) {
            int gn = n0 + tx + 16 * p;
            if (gn >= N) continue;
            float v = unpack_sum(acc[q][p]);
            if (bias) v += bias[gn];
            if (act == 1) v = fmaxf(v, 0.f);
            else if (act == 2) v = sigmoidf_(v);
            if (mul) v *= mul[(size_t)gm * N + gn];
            C[(size_t)gm * N + gn] = v;
        }
    }
}

// ---------------------------------------------------------------------------
// Transpose: out[C x R] = in[R x C]^T
// ---------------------------------------------------------------------------
__global__ void transpose_kernel(const float* __restrict__ in, float* __restrict__ out,
                                 int R, int C)
{
    __shared__ float tile[32][33];
    int bx = blockIdx.x * 32, by = blockIdx.y * 32;
    int x = bx + threadIdx.x;
#pragma unroll
    for (int j = 0; j < 32; j += 8) {
        int y = by + threadIdx.y + j;
        if (x < C && y < R) tile[threadIdx.y + j][threadIdx.x] = in[(size_t)y * C + x];
    }
    __syncthreads();
    int x2 = by + threadIdx.x;
#pragma unroll
    for (int j = 0; j < 32; j += 8) {
        int y2 = bx + threadIdx.y + j;
        if (x2 < R && y2 < C) out[(size_t)y2 * R + x2] = tile[threadIdx.x][threadIdx.y + j];
    }
}

// ---------------------------------------------------------------------------
// Small prep kernels
// ---------------------------------------------------------------------------
__global__ void prep_idx_kernel(const int* __restrict__ mask) {
    int b = threadIdx.x;
    if (b < BB) {
        int s = 0;
        for (int j = 0; j < SS; j++) s += mask[b * SS + j];
        g_idxlast[b] = s - 1;
    }
}

__global__ void molstart_kernel(const int* __restrict__ seg) {
    int stride = gridDim.x * blockDim.x;
    for (int i = blockIdx.x * blockDim.x + threadIdx.x; i < NATOMS; i += stride) {
        if (i == 0) {
            g_molstart[seg[0]] = 0;
            g_molstart[NMOL] = NATOMS;
        } else if (seg[i] != seg[i - 1]) {
            g_molstart[seg[i]] = i;
        }
    }
}

__global__ void zero_h_kernel() {
    int i = blockIdx.x * blockDim.x + threadIdx.x;
    if (i < 2 * BB * HH) g_h[0][i] = 0.f;
}

// ---------------------------------------------------------------------------
// GRU step: gates = h_prev @ w_hh^T + b_hh, fused update (both GRUs via z-dim)
// Tile: 16 hcols x 32 batches. 256 threads. Full-K smem via cp.async.
// Thread (c = tid&15, bq = tid>>4) -> 2 batches x 3 gates, f32x2 over K.
// smem: h_s[32][256] + w_s[48][258] = 82304 B (dynamic)
// ---------------------------------------------------------------------------
__global__ void __launch_bounds__(256)
gru_step_kernel(const float* __restrict__ whh_c, const float* __restrict__ whh_p,
                const float* __restrict__ bhh_c, const float* __restrict__ bhh_p,
                int t)
{
    extern __shared__ float sm[];
    float* h_s = sm;               // [32][256]
    float* w_s = sm + 32 * 256;    // [48][258]
    const int tid = threadIdx.x;
    const int c = tid & 15;
    const int bq = tid >> 4;       // 0..15
    const int g = blockIdx.z;
    const int c0 = blockIdx.x * 16;
    const int b0 = blockIdx.y * 32;
    const float* whh = g ? whh_p : whh_c;
    const float* bhh = g ? bhh_p : bhh_c;
    const float* hsrc = g_h[t & 1] + g * (BB * HH);
    float*       hdst = g_h[(t + 1) & 1] + g * (BB * HH);

    // stage h tile: 32 rows x 64 float4 = 2048 -> 8 per thread
#pragma unroll
    for (int j = 0; j < 8; j++) {
        int idx = tid + 256 * j;
        int r = idx >> 6, f4 = idx & 63;
        cp16(h_s + r * 256 + f4 * 4, hsrc + (b0 + r) * HH + f4 * 4, true);
    }
    // stage w tile: 48 rows x 128 float2 = 6144 -> 24 per thread (pitch 258)
#pragma unroll
    for (int j = 0; j < 24; j++) {
        int idx = tid + 256 * j;
        int r = idx >> 7, f2 = idx & 127;
        int grow = (r >> 4) * HH + c0 + (r & 15);
        cp8(w_s + r * 258 + f2 * 2, whh + (size_t)grow * HH + f2 * 2, true);
    }
    cp_commit();
    cp_wait0();
    __syncthreads();

    unsigned long long acc[2][3];
#pragma unroll
    for (int i = 0; i < 2; i++)
#pragma unroll
        for (int gt = 0; gt < 3; gt++) acc[i][gt] = 0ull;

#pragma unroll 8
    for (int k2 = 0; k2 < 128; k2++) {
        unsigned long long h2[2], w2[3];
        h2[0] = lds64(h_s + bq * 256 + 2 * k2);
        h2[1] = lds64(h_s + (bq + 16) * 256 + 2 * k2);
#pragma unroll
        for (int gt = 0; gt < 3; gt++)
            w2[gt] = lds64(w_s + (gt * 16 + c) * 258 + 2 * k2);
#pragma unroll
        for (int i = 0; i < 2; i++)
#pragma unroll
            for (int gt = 0; gt < 3; gt++)
                acc[i][gt] = ffma2(h2[i], w2[gt], acc[i][gt]);
    }

    const int col = c0 + c;
#pragma unroll
    for (int i = 0; i < 2; i++) {
        int b = b0 + bq + 16 * i;
        float hr = unpack_sum(acc[i][0]) + bhh[col];
        float hz = unpack_sum(acc[i][1]) + bhh[HH + col];
        float hn = unpack_sum(acc[i][2]) + bhh[2 * HH + col];
        const float* xp = g_xp + ((size_t)g * BB * SS + (size_t)b * SS + t) * (3 * HH);
        float r = sigmoidf_(xp[col] + hr);
        float z = sigmoidf_(xp[HH + col] + hz);
        float n = tanhf(xp[2 * HH + col] + r * hn);
        float hp = hsrc[b * HH + col];
        float hnew = (1.f - z) * n + z * hp;
        hdst[b * HH + col] = hnew;
        if (t == g_idxlast[b]) g_hlast[g * (BB * HH) + b * HH + col] = hnew;
    }
}

// ---------------------------------------------------------------------------
// relu(concat(h_c_last, h_p_last)) -> g_pat[B, 2H]
// ---------------------------------------------------------------------------
__global__ void concat_relu_kernel() {
    int b = blockIdx.x, tid = threadIdx.x;   // 512 threads
    int g = tid >> 8, cc = tid & 255;
    float v = g_hlast[g * (BB * HH) + b * HH + cc];
    g_pat[b * (2 * HH) + tid] = fmaxf(v, 0.f);
}

// ---------------------------------------------------------------------------
// Fingerprint gather: v = embed_fp[fingerprints]
// ---------------------------------------------------------------------------
__global__ void gather_kernel(const float* __restrict__ embed_fp,
                              const int* __restrict__ fp) {
    int a = blockIdx.x, c = threadIdx.x;
    g_v[a * HH + c] = embed_fp[(size_t)fp[a] * HH + c];
}

// ---------------------------------------------------------------------------
// Block-diagonal adjacency: v_out = hv + adj_block @ hv (per molecule)
// ---------------------------------------------------------------------------
__global__ void adj_kernel(const float* __restrict__ adj) {
    int m = blockIdx.x, tid = threadIdx.x;   // 256 threads = H columns
    int s = g_molstart[m], e = g_molstart[m + 1];
    int na = e - s;                           // <= 14
    __shared__ float hs[14][HH];
    __shared__ float as[14][14];
    for (int a = 0; a < na; a++) hs[a][tid] = g_hv[(s + a) * HH + tid];
    for (int idx = tid; idx < na * na; idx += 256) {
        int i = idx / na, j = idx - i * na;
        as[i][j] = adj[(size_t)(s + i) * NATOMS + (s + j)];
    }
    __syncthreads();
    for (int i = 0; i < na; i++) {
        float acc = hs[i][tid];
        for (int j = 0; j < na; j++) acc = fmaf(as[i][j], hs[j][tid], acc);
        g_v[(s + i) * HH + tid] = acc;
    }
}

// ---------------------------------------------------------------------------
// Per-molecule segment sum -> transposed [H][NMOL]
// ---------------------------------------------------------------------------
__global__ void molsum_kernel() {
    int m = blockIdx.x, c = threadIdx.x;
    int s = g_molstart[m], e = g_molstart[m + 1];
    float acc = 0.f;
    for (int i = s; i < e; i++) acc += g_v[i * HH + c];
    g_molsumT[c * NMOL + m] = acc;
}

// ---------------------------------------------------------------------------
// x2 = match + match @ w_out + b_out; layernorm -> g_att (block per batch)
// ---------------------------------------------------------------------------
__global__ void att_kernel(const float* __restrict__ w_out, const float* __restrict__ b_out,
                           const float* __restrict__ gamma, const float* __restrict__ beta)
{
    int b = blockIdx.x, tid = threadIdx.x;
    __shared__ float mrow[LBL];
    __shared__ float red[256];
    if (tid < LBL) mrow[tid] = g_match[b * LBL + tid];
    __syncthreads();
    float x2 = 0.f;
    if (tid < LBL) {
        float acc = 0.f;
        for (int k = 0; k < LBL; k++) acc = fmaf(mrow[k], w_out[k * LBL + tid], acc);
        x2 = mrow[tid] + acc + b_out[tid];
    }
    red[tid] = (tid < LBL) ? x2 : 0.f;
    __syncthreads();
    for (int s2 = 128; s2 > 0; s2 >>= 1) {
        if (tid < s2) red[tid] += red[tid + s2];
        __syncthreads();
    }
    float mean = red[0] * (1.f / LBL);
    __syncthreads();
    float d = x2 - mean;
    red[tid] = (tid < LBL) ? d * d : 0.f;
    __syncthreads();
    for (int s2 = 128; s2 > 0; s2 >>= 1) {
        if (tid < s2) red[tid] += red[tid + s2];
        __syncthreads();
    }
    float var = red[0] * (1.f / LBL);
    if (tid < LBL)
        g_att[b * LBL + tid] = d * rsqrtf(var + 1e-5f) * gamma[tid] + beta[tid];
}

// ---------------------------------------------------------------------------
// Masked bipartite weight: wm[k][j] = w_masklin[k][j] * ddi[j][k]
// ---------------------------------------------------------------------------
__global__ void wm_kernel(const float* __restrict__ w_masklin,
                          const float* __restrict__ ddi) {
    int idx = blockIdx.x * blockDim.x + threadIdx.x;
    if (idx < NSUB * LBL) {
        int k = idx / LBL, j = idx - k * LBL;
        g_wm[idx] = w_masklin[idx] * ddi[j * NSUB + k];
    }
}

// ---------------------------------------------------------------------------
// Launch orchestration
// ---------------------------------------------------------------------------
extern "C" void kernel_launch(void* const* d_in, const int* in_sizes, int n_in,
                              void* d_out, int out_size) {
    const float* x_c      = (const float*)d_in[0];
    const float* x_p      = (const float*)d_in[1];
    const int*   mask     = (const int*)  d_in[2];
    const float* w_ih_c   = (const float*)d_in[3];
    const float* w_hh_c   = (const float*)d_in[4];
    const float* b_ih_c   = (const float*)d_in[5];
    const float* b_hh_c   = (const float*)d_in[6];
    const float* w_ih_p   = (const float*)d_in[7];
    const float* w_hh_p   = (const float*)d_in[8];
    const float* b_ih_p   = (const float*)d_in[9];
    const float* b_hh_p   = (const float*)d_in[10];
    const float* w_query  = (const float*)d_in[11];
    const float* b_query  = (const float*)d_in[12];
    const float* w_bip    = (const float*)d_in[13];
    const float* b_bip    = (const float*)d_in[14];
    const float* w_mlin   = (const float*)d_in[15];
    const float* ddi      = (const float*)d_in[16];
    const float* embed_fp = (const float*)d_in[17];
    const int*   fp       = (const int*)  d_in[18];
    const float* adj      = (const float*)d_in[19];
    const int*   seg      = (const int*)  d_in[20];
    const float* w_g0     = (const float*)d_in[21];
    const float* b_g0     = (const float*)d_in[22];
    const float* w_g1     = (const float*)d_in[23];
    const float* b_g1     = (const float*)d_in[24];
    const float* avgproj  = (const float*)d_in[25];
    const float* w_out    = (const float*)d_in[26];
    const float* b_out    = (const float*)d_in[27];
    const float* ln_g     = (const float*)d_in[28];
    const float* ln_b     = (const float*)d_in[29];
    float* outp = (float*)d_out;

    float *xp, *pat, *query, *v, *hv, *molsumT, *emb, *match, *bip, *wm, *att;
    float *wqT, *wg0T, *wg1T, *wbipT;
    cudaGetSymbolAddress((void**)&xp,      g_xp);
    cudaGetSymbolAddress((void**)&pat,     g_pat);
    cudaGetSymbolAddress((void**)&query,   g_query);
    cudaGetSymbolAddress((void**)&v,       g_v);
    cudaGetSymbolAddress((void**)&hv,      g_hv);
    cudaGetSymbolAddress((void**)&molsumT, g_molsumT);
    cudaGetSymbolAddress((void**)&emb,     g_emb);
    cudaGetSymbolAddress((void**)&match,   g_match);
    cudaGetSymbolAddress((void**)&bip,     g_bip);
    cudaGetSymbolAddress((void**)&wm,      g_wm);
    cudaGetSymbolAddress((void**)&att,     g_att);
    cudaGetSymbolAddress((void**)&wqT,     g_wqT);
    cudaGetSymbolAddress((void**)&wg0T,    g_wg0T);
    cudaGetSymbolAddress((void**)&wg1T,    g_wg1T);
    cudaGetSymbolAddress((void**)&wbipT,   g_wbipT);

    const int GEMMF_SMEM = (2 * 128 * 32 + 2 * 64 * 32) * 4;        // 49152
    const int GRU_SMEM   = (32 * 256 + 48 * 258) * 4;               // 82304
    cudaFuncSetAttribute(gemm_f, cudaFuncAttributeMaxDynamicSharedMemorySize, GEMMF_SMEM);
    cudaFuncSetAttribute(gru_step_kernel, cudaFuncAttributeMaxDynamicSharedMemorySize, GRU_SMEM);

    // prep
    prep_idx_kernel<<<1, 256>>>(mask);
    molstart_kernel<<<32, 256>>>(seg);
    zero_h_kernel<<<(2 * BB * HH + 255) / 256, 256>>>();

    // weight transposes (so all fast GEMMs are transB=1)
    {
        dim3 blk(32, 8);
        transpose_kernel<<<dim3(8, 16), blk>>>(w_query, wqT, 2 * HH, HH);  // [512,256]->[256,512]
        transpose_kernel<<<dim3(8, 8),  blk>>>(w_g0,   wg0T, HH, HH);
        transpose_kernel<<<dim3(8, 8),  blk>>>(w_g1,   wg1T, HH, HH);
        transpose_kernel<<<dim3(16, 8), blk>>>(w_bip,  wbipT, HH, NSUB);   // [256,491]->[491,256]
    }

    // GRU input projections: xp = x @ w_ih^T + b_ih (M=8192, N=768, K=128)
    {
        dim3 grid(768 / 64, 8192 / 128);
        gemm_f<<<grid, 256, GEMMF_SMEM>>>(x_c, w_ih_c, b_ih_c, nullptr, xp,
                                          BB * SS, 3 * HH, II, 0);
        gemm_f<<<grid, 256, GEMMF_SMEM>>>(x_p, w_ih_p, b_ih_p, nullptr,
                                          xp + (size_t)BB * SS * 3 * HH,
                                          BB * SS, 3 * HH, II, 0);
    }

    // GRU recurrence: 32 sequential steps, both GRUs per launch
    {
        dim3 grid(HH / 16, BB / 32, 2);
        for (int t = 0; t < SS; t++)
            gru_step_kernel<<<grid, 256, GRU_SMEM>>>(w_hh_c, w_hh_p, b_hh_c, b_hh_p, t);
    }

    // query = relu(concat) @ w_query + b_query   (M=256, N=256, K=512)
    concat_relu_kernel<<<BB, 512>>>();
    gemm_f<<<dim3(4, 2), 256, GEMMF_SMEM>>>(pat, wqT, b_query, nullptr, query,
                                            BB, HH, 2 * HH, 0);

    // MPNN
    gather_kernel<<<NATOMS, HH>>>(embed_fp, fp);
    {
        dim3 grid(HH / 64, (NATOMS + 127) / 128);
        gemm_f<<<grid, 256, GEMMF_SMEM>>>(v, wg0T, b_g0, nullptr, hv, NATOMS, HH, HH, 1);
        adj_kernel<<<NMOL, HH>>>(adj);
        gemm_f<<<grid, 256, GEMMF_SMEM>>>(v, wg1T, b_g1, nullptr, hv, NATOMS, HH, HH, 1);
        adj_kernel<<<NMOL, HH>>>(adj);
    }
    molsum_kernel<<<NMOL, HH>>>();

    // mpnn_emb = avgproj @ molsum   (M=200, N=256, K=600; B = molsumT [256][600])
    gemm_f<<<dim3(4, 2), 256, GEMMF_SMEM>>>(avgproj, molsumT, nullptr, nullptr, emb,
                                            LBL, HH, NMOL, 0);

    // match = sigmoid(query @ emb^T)   (M=256, N=200, K=256)
    gemm_f<<<dim3(4, 2), 256, GEMMF_SMEM>>>(query, emb, nullptr, nullptr, match,
                                            BB, LBL, HH, 2);
    // x2 + layernorm -> g_att
    att_kernel<<<BB, 256>>>(w_out, b_out, ln_g, ln_b);

    // bip = query @ w_bip + b_bip   (M=256, N=491, K=256; B = wbipT [491][256])
    gemm_f<<<dim3(8, 2), 256, GEMMF_SMEM>>>(query, wbipT, b_bip, nullptr, bip,
                                            BB, NSUB, HH, 0);
    // masked weight
    wm_kernel<<<(NSUB * LBL + 255) / 256, 256>>>(w_mlin, ddi);
    // out = (bip @ wm) * mpnn_att   (M=256, N=200, K=491) — odd K, generic kernel
    gemm_kernel<<<dim3(4, 4), 256>>>(bip, wm, nullptr, att, outp,
                                     BB, LBL, NSUB, 0, 0);
}

// round 5
// speedup vs baseline: 1.8865x; 1.0940x over previous
#include <cuda_runtime.h>
#include <cstdint>
#include <cstddef>

// ---------------------------------------------------------------------------
// Problem constants
// ---------------------------------------------------------------------------
#define BB    256      // batch
#define SS    32       // seq len
#define II    128      // input dim
#define HH    256      // hidden
#define LBL   200      // label
#define NSUB  491
#define NATOMS 8000
#define NMOL  600

// ---------------------------------------------------------------------------
// Scratch (static __device__ — no allocation anywhere)
// ---------------------------------------------------------------------------
__device__ __align__(16) float g_xp[2 * BB * SS * 3 * HH];
__device__ __align__(16) float g_h[2][2 * BB * HH];
__device__ __align__(16) float g_hlast[2 * BB * HH];
__device__ int   g_idxlast[BB];
__device__ int   g_molstart[NMOL + 1];
__device__ int   g_bar[8 * 32];                        // 8 barrier groups, 128B apart
__device__ __align__(16) float g_pat[BB * 2 * HH];
__device__ __align__(16) float g_query[BB * HH];
__device__ __align__(16) float g_v[NATOMS * HH];
__device__ __align__(16) float g_hv[NATOMS * HH];
__device__ __align__(16) float g_molsumT[HH * NMOL];   // transposed [H][NMOL]
__device__ __align__(16) float g_emb[LBL * HH];
__device__ __align__(16) float g_match[BB * LBL];
__device__ __align__(16) float g_att[BB * LBL];
__device__ __align__(16) float g_bip[BB * NSUB];
__device__ __align__(16) float g_wm[NSUB * LBL];
// pre-transposed weights (so all fast GEMMs are transB with K-contiguous rows)
__device__ __align__(16) float g_wqT[HH * 2 * HH];     // [256][512]
__device__ __align__(16) float g_wg0T[HH * HH];
__device__ __align__(16) float g_wg1T[HH * HH];
__device__ __align__(16) float g_wbipT[NSUB * HH];     // [491][256]

// ---------------------------------------------------------------------------
// Helpers
// ---------------------------------------------------------------------------
__device__ __forceinline__ unsigned long long ffma2(unsigned long long a,
                                                    unsigned long long b,
                                                    unsigned long long c) {
#if defined(__CUDA_ARCH__) && (__CUDA_ARCH__ >= 1000)
    unsigned long long d;
    asm("fma.rn.f32x2 %0, %1, %2, %3;" : "=l"(d) : "l"(a), "l"(b), "l"(c));
    return d;
#else
    float2 af = *reinterpret_cast<float2*>(&a);
    float2 bf = *reinterpret_cast<float2*>(&b);
    float2 cf = *reinterpret_cast<float2*>(&c);
    float2 df;
    df.x = fmaf(af.x, bf.x, cf.x);
    df.y = fmaf(af.y, bf.y, cf.y);
    return *reinterpret_cast<unsigned long long*>(&df);
#endif
}

__device__ __forceinline__ unsigned long long lds64(const float* p) {
    return *reinterpret_cast<const unsigned long long*>(p);
}

__device__ __forceinline__ float unpack_sum(unsigned long long u) {
    return __uint_as_float((unsigned)u) + __uint_as_float((unsigned)(u >> 32));
}

__device__ __forceinline__ float sigmoidf_(float x) {
    return 1.f / (1.f + expf(-x));
}

__device__ __forceinline__ void cp16(float* dst, const float* src, bool p) {
    unsigned s = (unsigned)__cvta_generic_to_shared(dst);
    int n = p ? 16 : 0;
    asm volatile("cp.async.ca.shared.global [%0], [%1], 16, %2;"
                 :: "r"(s), "l"(src), "r"(n));
}
__device__ __forceinline__ void cp8(float* dst, const float* src, bool p) {
    unsigned s = (unsigned)__cvta_generic_to_shared(dst);
    int n = p ? 8 : 0;
    asm volatile("cp.async.ca.shared.global [%0], [%1], 8, %2;"
                 :: "r"(s), "l"(src), "r"(n));
}
__device__ __forceinline__ void cp_commit() { asm volatile("cp.async.commit_group;"); }
__device__ __forceinline__ void cp_wait0()  { asm volatile("cp.async.wait_group 0;"); }

// ---------------------------------------------------------------------------
// Fast GEMM (transB only): C[M,N] = act( A[M,K] * B[N,K]^T + bias ) (* mul)
// ---------------------------------------------------------------------------
__global__ void __launch_bounds__(256, 1)
gemm_f(const float* __restrict__ A, const float* __restrict__ Bm,
       const float* __restrict__ bias, const float* __restrict__ mul,
       float* __restrict__ C, int M, int N, int K, int act)
{
    extern __shared__ float sm[];
    float* As = sm;                 // [2][128][32]
    float* Bs = sm + 2 * 128 * 32;  // [2][64][32]
    const int tid = threadIdx.x;
    const int tx = tid & 15, ty = tid >> 4;
    const int m0 = blockIdx.y * 128, n0 = blockIdx.x * 64;
    const int nchunks = (K + 31) / 32;

    unsigned long long acc[8][4];
#pragma unroll
    for (int q = 0; q < 8; q++)
#pragma unroll
        for (int p = 0; p < 4; p++) acc[q][p] = 0ull;

    auto stage = [&](int buf, int k0) {
        float* Ab = As + buf * (128 * 32);
        float* Bb = Bs + buf * (64 * 32);
#pragma unroll
        for (int j = 0; j < 4; j++) {
            int idx = tid + 256 * j;
            int r = idx >> 3, kf4 = idx & 7;
            int gm = m0 + r, gk = k0 + kf4 * 4;
            bool pr = (gm < M) && (gk < K);
            const float* src = pr ? (A + (size_t)gm * K + gk) : A;
            cp16(Ab + r * 32 + ((kf4 ^ (r & 7)) << 2), src, pr);
        }
#pragma unroll
        for (int j = 0; j < 2; j++) {
            int idx = tid + 256 * j;
            int r = idx >> 3, kf4 = idx & 7;
            int gn = n0 + r, gk = k0 + kf4 * 4;
            bool pr = (gn < N) && (gk < K);
            const float* src = pr ? (Bm + (size_t)gn * K + gk) : Bm;
            cp16(Bb + r * 32 + ((kf4 ^ (r & 7)) << 2), src, pr);
        }
        cp_commit();
    };

    stage(0, 0);
    int buf = 0;
    for (int c = 0; c < nchunks; c++) {
        cp_wait0();
        __syncthreads();
        if (c + 1 < nchunks) stage(buf ^ 1, (c + 1) * 32);
        const float* Ab = As + buf * (128 * 32);
        const float* Bb = Bs + buf * (64 * 32);
#pragma unroll
        for (int k4 = 0; k4 < 8; k4++) {
            ulonglong2 a[8], b[4];
#pragma unroll
            for (int q = 0; q < 8; q++) {
                int r = ty + 16 * q;
                a[q] = *reinterpret_cast<const ulonglong2*>(
                    Ab + r * 32 + ((k4 ^ (r & 7)) << 2));
            }
#pragma unroll
            for (int p = 0; p < 4; p++) {
                int r = tx + 16 * p;
                b[p] = *reinterpret_cast<const ulonglong2*>(
                    Bb + r * 32 + ((k4 ^ (r & 7)) << 2));
            }
#pragma unroll
            for (int q = 0; q < 8; q++)
#pragma unroll
                for (int p = 0; p < 4; p++) {
                    acc[q][p] = ffma2(a[q].x, b[p].x, acc[q][p]);
                    acc[q][p] = ffma2(a[q].y, b[p].y, acc[q][p]);
                }
        }
        buf ^= 1;
    }

#pragma unroll
    for (int q = 0; q < 8; q++) {
        int gm = m0 + ty + 16 * q;
        if (gm >= M) continue;
#pragma unroll
        for (int p = 0; p < 4; p++) {
            int gn = n0 + tx + 16 * p;
            if (gn >= N) continue;
            float v = unpack_sum(acc[q][p]);
            if (bias) v += bias[gn];
            if (act == 1) v = fmaxf(v, 0.f);
            else if (act == 2) v = sigmoidf_(v);
            if (mul) v *= mul[(size_t)gm * N + gn];
            C[(size_t)gm * N + gn] = v;
        }
    }
}

// ---------------------------------------------------------------------------
// Generic GEMM — only for the odd-K final matmul (K=491, transB=0)
// ---------------------------------------------------------------------------
__global__ void gemm_kernel(const float* __restrict__ A, const float* __restrict__ Bm,
                            const float* __restrict__ bias, const float* __restrict__ mul,
                            float* __restrict__ C,
                            int M, int N, int K, int transB, int act)
{
    __shared__ float As[64][34];
    __shared__ float Bs[64][34];
    const int tid = threadIdx.x;
    const int tx = tid & 15, ty = tid >> 4;
    const int m0 = blockIdx.y * 64, n0 = blockIdx.x * 64;

    unsigned long long acc[4][4];
#pragma unroll
    for (int q = 0; q < 4; q++)
#pragma unroll
        for (int p = 0; p < 4; p++) acc[q][p] = 0ull;

    for (int k0 = 0; k0 < K; k0 += 32) {
        for (int idx = tid; idx < 64 * 32; idx += 256) {
            int r = idx >> 5, k = idx & 31;
            int gm = m0 + r, gk = k0 + k;
            As[r][k] = (gm < M && gk < K) ? A[(size_t)gm * K + gk] : 0.f;
        }
        if (transB) {
            for (int idx = tid; idx < 64 * 32; idx += 256) {
                int cJ = idx >> 5, k = idx & 31;
                int gn = n0 + cJ, gk = k0 + k;
                Bs[cJ][k] = (gn < N && gk < K) ? Bm[(size_t)gn * K + gk] : 0.f;
            }
        } else {
            for (int idx = tid; idx < 64 * 32; idx += 256) {
                int k = idx >> 6, cJ = idx & 63;
                int gn = n0 + cJ, gk = k0 + k;
                Bs[cJ][k] = (gn < N && gk < K) ? Bm[(size_t)gk * N + gn] : 0.f;
            }
        }
        __syncthreads();
#pragma unroll 4
        for (int k2 = 0; k2 < 16; k2++) {
            unsigned long long a2[4], b2[4];
#pragma unroll
            for (int q = 0; q < 4; q++) a2[q] = lds64(&As[ty + 16 * q][2 * k2]);
#pragma unroll
            for (int p = 0; p < 4; p++) b2[p] = lds64(&Bs[tx + 16 * p][2 * k2]);
#pragma unroll
            for (int q = 0; q < 4; q++)
#pragma unroll
                for (int p = 0; p < 4; p++)
                    acc[q][p] = ffma2(a2[q], b2[p], acc[q][p]);
        }
        __syncthreads();
    }

#pragma unroll
    for (int q = 0; q < 4; q++) {
        int gm = m0 + ty + 16 * q;
        if (gm >= M) continue;
#pragma unroll
        for (int p = 0; p < 4; p++) {
            int gn = n0 + tx + 16 * p;
            if (gn >= N) continue;
            float v = unpack_sum(acc[q][p]);
            if (bias) v += bias[gn];
            if (act == 1) v = fmaxf(v, 0.f);
            else if (act == 2) v = sigmoidf_(v);
            if (mul) v *= mul[(size_t)gm * N + gn];
            C[(size_t)gm * N + gn] = v;
        }
    }
}

// ---------------------------------------------------------------------------
// Transpose: out[C x R] = in[R x C]^T
// ---------------------------------------------------------------------------
__global__ void transpose_kernel(const float* __restrict__ in, float* __restrict__ out,
                                 int R, int C)
{
    __shared__ float tile[32][33];
    int bx = blockIdx.x * 32, by = blockIdx.y * 32;
    int x = bx + threadIdx.x;
#pragma unroll
    for (int j = 0; j < 32; j += 8) {
        int y = by + threadIdx.y + j;
        if (x < C && y < R) tile[threadIdx.y + j][threadIdx.x] = in[(size_t)y * C + x];
    }
    __syncthreads();
    int x2 = by + threadIdx.x;
#pragma unroll
    for (int j = 0; j < 32; j += 8) {
        int y2 = bx + threadIdx.y + j;
        if (x2 < R && y2 < C) out[(size_t)y2 * R + x2] = tile[threadIdx.x][threadIdx.y + j];
    }
}

// ---------------------------------------------------------------------------
// Small prep kernels
// ---------------------------------------------------------------------------
__global__ void prep_idx_kernel(const int* __restrict__ mask) {
    int b = threadIdx.x;
    if (b < BB) {
        int s = 0;
        for (int j = 0; j < SS; j++) s += mask[b * SS + j];
        g_idxlast[b] = s - 1;
    }
}

__global__ void molstart_kernel(const int* __restrict__ seg) {
    int stride = gridDim.x * blockDim.x;
    for (int i = blockIdx.x * blockDim.x + threadIdx.x; i < NATOMS; i += stride) {
        if (i == 0) {
            g_molstart[seg[0]] = 0;
            g_molstart[NMOL] = NATOMS;
        } else if (seg[i] != seg[i - 1]) {
            g_molstart[seg[i]] = i;
        }
    }
}

__global__ void zero_h_kernel() {
    int i = blockIdx.x * blockDim.x + threadIdx.x;
    if (i < 2 * BB * HH) g_h[0][i] = 0.f;
    if (i < 8 * 32) g_bar[i] = 0;
}

// ---------------------------------------------------------------------------
// Persistent GRU: single launch, 32 steps with inter-block barriers.
// Grid (16 colgroups, 4 batchgroups, 2 grus) = 128 blocks, 256 threads.
// Block tile: 16 hidden cols x 64 batches. Weights staged to smem ONCE.
// Barrier groups: blocks sharing (batchgroup, gru) = 16 blocks per group.
// smem: w_s[48][258] + h_s[64][256] = 115072 B.
// Thread (c=tid&15, bq=tid>>4): 4 batches x 3 gates, f32x2 over K=256.
// ---------------------------------------------------------------------------
__global__ void __launch_bounds__(256)
gru_persist_kernel(const float* __restrict__ whh_c, const float* __restrict__ whh_p,
                   const float* __restrict__ bhh_c, const float* __restrict__ bhh_p)
{
    extern __shared__ float sm[];
    float* w_s = sm;                 // [48][258]
    float* h_s = sm + 48 * 258;      // [64][256]
    const int tid = threadIdx.x;
    const int c = tid & 15;
    const int bq = tid >> 4;         // 0..15
    const int g  = blockIdx.z;
    const int c0 = blockIdx.x * 16;
    const int b0 = blockIdx.y * 64;
    const int grp = blockIdx.y + 4 * blockIdx.z;      // 8 barrier groups of 16 blocks
    const float* whh = g ? whh_p : whh_c;
    const float* bhh = g ? bhh_p : bhh_c;
    const int col = c0 + c;

    // stage weights once: 48 rows x 128 float2 = 6144 -> 24 cp8 per thread
#pragma unroll
    for (int j = 0; j < 24; j++) {
        int idx = tid + 256 * j;
        int r = idx >> 7, f2 = idx & 127;
        int grow = (r >> 4) * HH + c0 + (r & 15);
        cp8(w_s + r * 258 + f2 * 2, whh + (size_t)grow * HH + f2 * 2, true);
    }
    cp_commit();

    const float bh_r = bhh[col];
    const float bh_z = bhh[HH + col];
    const float bh_n = bhh[2 * HH + col];
    const int idxl0 = g_idxlast[b0 + bq];
    const int idxl1 = g_idxlast[b0 + bq + 16];
    const int idxl2 = g_idxlast[b0 + bq + 32];
    const int idxl3 = g_idxlast[b0 + bq + 48];
    const int idxl[4] = {idxl0, idxl1, idxl2, idxl3};

    for (int t = 0; t < SS; t++) {
        // stage h tile: 64 rows x 64 float4 = 4096 -> 16 cp16 per thread
        const float* hsrc = g_h[t & 1] + g * (BB * HH);
#pragma unroll
        for (int j = 0; j < 16; j++) {
            int idx = tid + 256 * j;
            int r = idx >> 6, f4 = idx & 63;
            cp16(h_s + r * 256 + f4 * 4, hsrc + (b0 + r) * HH + f4 * 4, true);
        }
        cp_commit();

        // prefetch xp into regs while copies land
        float xr[4][3];
#pragma unroll
        for (int i = 0; i < 4; i++) {
            int b = b0 + bq + 16 * i;
            const float* xp = g_xp + ((size_t)g * BB * SS + (size_t)b * SS + t) * (3 * HH);
            xr[i][0] = __ldg(xp + col);
            xr[i][1] = __ldg(xp + HH + col);
            xr[i][2] = __ldg(xp + 2 * HH + col);
        }

        cp_wait0();
        __syncthreads();

        unsigned long long acc[4][3];
#pragma unroll
        for (int i = 0; i < 4; i++)
#pragma unroll
            for (int gt = 0; gt < 3; gt++) acc[i][gt] = 0ull;

#pragma unroll 8
        for (int k2 = 0; k2 < 128; k2++) {
            unsigned long long h2[4], w2[3];
#pragma unroll
            for (int i = 0; i < 4; i++)
                h2[i] = lds64(h_s + (bq + 16 * i) * 256 + 2 * k2);
#pragma unroll
            for (int gt = 0; gt < 3; gt++)
                w2[gt] = lds64(w_s + (gt * 16 + c) * 258 + 2 * k2);
#pragma unroll
            for (int i = 0; i < 4; i++)
#pragma unroll
                for (int gt = 0; gt < 3; gt++)
                    acc[i][gt] = ffma2(h2[i], w2[gt], acc[i][gt]);
        }

        float* hdst = g_h[(t + 1) & 1] + g * (BB * HH);
#pragma unroll
        for (int i = 0; i < 4; i++) {
            int b = b0 + bq + 16 * i;
            float hr = unpack_sum(acc[i][0]) + bh_r;
            float hz = unpack_sum(acc[i][1]) + bh_z;
            float hn = unpack_sum(acc[i][2]) + bh_n;
            float r = sigmoidf_(xr[i][0] + hr);
            float z = sigmoidf_(xr[i][1] + hz);
            float n = tanhf(xr[i][2] + r * hn);
            float hp = h_s[(bq + 16 * i) * 256 + col];     // prev h from smem
            float hnew = (1.f - z) * n + z * hp;
            hdst[b * HH + col] = hnew;
            if (t == idxl[i]) g_hlast[g * (BB * HH) + b * HH + col] = hnew;
        }

        if (t + 1 < SS) {
            __threadfence();
            __syncthreads();              // all stores in block issued & fenced
            if (tid == 0) {
                atomicAdd(&g_bar[grp * 32], 1);
                int tgt = 16 * (t + 1);
                while (*(volatile int*)&g_bar[grp * 32] < tgt) { }
            }
            __syncthreads();
            __threadfence();
        }
    }
}

// ---------------------------------------------------------------------------
// relu(concat(h_c_last, h_p_last)) -> g_pat[B, 2H]
// ---------------------------------------------------------------------------
__global__ void concat_relu_kernel() {
    int b = blockIdx.x, tid = threadIdx.x;   // 512 threads
    int g = tid >> 8, cc = tid & 255;
    float v = g_hlast[g * (BB * HH) + b * HH + cc];
    g_pat[b * (2 * HH) + tid] = fmaxf(v, 0.f);
}

// ---------------------------------------------------------------------------
// Fingerprint gather (flat, float4): v = embed_fp[fingerprints]
// ---------------------------------------------------------------------------
__global__ void gather_kernel(const float* __restrict__ embed_fp,
                              const int* __restrict__ fp) {
    int idx = blockIdx.x * blockDim.x + threadIdx.x;   // over NATOMS*64 float4
    if (idx < NATOMS * (HH / 4)) {
        int a = idx >> 6, f4 = idx & 63;
        reinterpret_cast<float4*>(g_v)[(size_t)a * 64 + f4] =
            reinterpret_cast<const float4*>(embed_fp)[(size_t)fp[a] * 64 + f4];
    }
}

// ---------------------------------------------------------------------------
// Block-diagonal adjacency: v_out = hv + adj_block @ hv (per molecule)
// ---------------------------------------------------------------------------
__global__ void adj_kernel(const float* __restrict__ adj) {
    int m = blockIdx.x, tid = threadIdx.x;   // 256 threads = H columns
    int s = g_molstart[m], e = g_molstart[m + 1];
    int na = e - s;                           // <= 14
    __shared__ float hs[14][HH];
    __shared__ float as[14][14];
    for (int a = 0; a < na; a++) hs[a][tid] = g_hv[(s + a) * HH + tid];
    for (int idx = tid; idx < na * na; idx += 256) {
        int i = idx / na, j = idx - i * na;
        as[i][j] = adj[(size_t)(s + i) * NATOMS + (s + j)];
    }
    __syncthreads();
    for (int i = 0; i < na; i++) {
        float acc = hs[i][tid];
        for (int j = 0; j < na; j++) acc = fmaf(as[i][j], hs[j][tid], acc);
        g_v[(s + i) * HH + tid] = acc;
    }
}

// ---------------------------------------------------------------------------
// Per-molecule segment sum -> transposed [H][NMOL]
// ---------------------------------------------------------------------------
__global__ void molsum_kernel() {
    int m = blockIdx.x, c = threadIdx.x;
    int s = g_molstart[m], e = g_molstart[m + 1];
    float acc = 0.f;
    for (int i = s; i < e; i++) acc += g_v[i * HH + c];
    g_molsumT[c * NMOL + m] = acc;
}

// ---------------------------------------------------------------------------
// x2 = match + match @ w_out + b_out; layernorm -> g_att (block per batch)
// ---------------------------------------------------------------------------
__global__ void att_kernel(const float* __restrict__ w_out, const float* __restrict__ b_out,
                           const float* __restrict__ gamma, const float* __restrict__ beta)
{
    int b = blockIdx.x, tid = threadIdx.x;
    __shared__ float mrow[LBL];
    __shared__ float red[256];
    if (tid < LBL) mrow[tid] = g_match[b * LBL + tid];
    __syncthreads();
    float x2 = 0.f;
    if (tid < LBL) {
        float acc = 0.f;
        for (int k = 0; k < LBL; k++) acc = fmaf(mrow[k], w_out[k * LBL + tid], acc);
        x2 = mrow[tid] + acc + b_out[tid];
    }
    red[tid] = (tid < LBL) ? x2 : 0.f;
    __syncthreads();
    for (int s2 = 128; s2 > 0; s2 >>= 1) {
        if (tid < s2) red[tid] += red[tid + s2];
        __syncthreads();
    }
    float mean = red[0] * (1.f / LBL);
    __syncthreads();
    float d = x2 - mean;
    red[tid] = (tid < LBL) ? d * d : 0.f;
    __syncthreads();
    for (int s2 = 128; s2 > 0; s2 >>= 1) {
        if (tid < s2) red[tid] += red[tid + s2];
        __syncthreads();
    }
    float var = red[0] * (1.f / LBL);
    if (tid < LBL)
        g_att[b * LBL + tid] = d * rsqrtf(var + 1e-5f) * gamma[tid] + beta[tid];
}

// ---------------------------------------------------------------------------
// Masked bipartite weight: wm[k][j] = w_masklin[k][j] * ddi[j][k]
// ---------------------------------------------------------------------------
__global__ void wm_kernel(const float* __restrict__ w_masklin,
                          const float* __restrict__ ddi) {
    int idx = blockIdx.x * blockDim.x + threadIdx.x;
    if (idx < NSUB * LBL) {
        int k = idx / LBL, j = idx - k * LBL;
        g_wm[idx] = w_masklin[idx] * ddi[j * NSUB + k];
    }
}

// ---------------------------------------------------------------------------
// Launch orchestration (fork MPNN branch onto side stream, join before tail)
// ---------------------------------------------------------------------------
extern "C" void kernel_launch(void* const* d_in, const int* in_sizes, int n_in,
                              void* d_out, int out_size) {
    const float* x_c      = (const float*)d_in[0];
    const float* x_p      = (const float*)d_in[1];
    const int*   mask     = (const int*)  d_in[2];
    const float* w_ih_c   = (const float*)d_in[3];
    const float* w_hh_c   = (const float*)d_in[4];
    const float* b_ih_c   = (const float*)d_in[5];
    const float* b_hh_c   = (const float*)d_in[6];
    const float* w_ih_p   = (const float*)d_in[7];
    const float* w_hh_p   = (const float*)d_in[8];
    const float* b_ih_p   = (const float*)d_in[9];
    const float* b_hh_p   = (const float*)d_in[10];
    const float* w_query  = (const float*)d_in[11];
    const float* b_query  = (const float*)d_in[12];
    const float* w_bip    = (const float*)d_in[13];
    const float* b_bip    = (const float*)d_in[14];
    const float* w_mlin   = (const float*)d_in[15];
    const float* ddi      = (const float*)d_in[16];
    const float* embed_fp = (const float*)d_in[17];
    const int*   fp       = (const int*)  d_in[18];
    const float* adj      = (const float*)d_in[19];
    const int*   seg      = (const int*)  d_in[20];
    const float* w_g0     = (const float*)d_in[21];
    const float* b_g0     = (const float*)d_in[22];
    const float* w_g1     = (const float*)d_in[23];
    const float* b_g1     = (const float*)d_in[24];
    const float* avgproj  = (const float*)d_in[25];
    const float* w_out    = (const float*)d_in[26];
    const float* b_out    = (const float*)d_in[27];
    const float* ln_g     = (const float*)d_in[28];
    const float* ln_b     = (const float*)d_in[29];
    float* outp = (float*)d_out;

    float *xp, *pat, *query, *v, *hv, *molsumT, *emb, *match, *bip, *wm, *att;
    float *wqT, *wg0T, *wg1T, *wbipT;
    cudaGetSymbolAddress((void**)&xp,      g_xp);
    cudaGetSymbolAddress((void**)&pat,     g_pat);
    cudaGetSymbolAddress((void**)&query,   g_query);
    cudaGetSymbolAddress((void**)&v,       g_v);
    cudaGetSymbolAddress((void**)&hv,      g_hv);
    cudaGetSymbolAddress((void**)&molsumT, g_molsumT);
    cudaGetSymbolAddress((void**)&emb,     g_emb);
    cudaGetSymbolAddress((void**)&match,   g_match);
    cudaGetSymbolAddress((void**)&bip,     g_bip);
    cudaGetSymbolAddress((void**)&wm,      g_wm);
    cudaGetSymbolAddress((void**)&att,     g_att);
    cudaGetSymbolAddress((void**)&wqT,     g_wqT);
    cudaGetSymbolAddress((void**)&wg0T,    g_wg0T);
    cudaGetSymbolAddress((void**)&wg1T,    g_wg1T);
    cudaGetSymbolAddress((void**)&wbipT,   g_wbipT);

    const int GEMMF_SMEM = (2 * 128 * 32 + 2 * 64 * 32) * 4;        // 49152
    const int GRU_SMEM   = (48 * 258 + 64 * 256) * 4;               // 115072

    static cudaStream_t s2 = nullptr;
    static cudaEvent_t evFork = nullptr, evJoin = nullptr;
    if (!s2) {
        cudaStreamCreateWithFlags(&s2, cudaStreamNonBlocking);
        cudaEventCreateWithFlags(&evFork, cudaEventDisableTiming);
        cudaEventCreateWithFlags(&evJoin, cudaEventDisableTiming);
        cudaFuncSetAttribute(gemm_f, cudaFuncAttributeMaxDynamicSharedMemorySize, GEMMF_SMEM);
        cudaFuncSetAttribute(gru_persist_kernel, cudaFuncAttributeMaxDynamicSharedMemorySize, GRU_SMEM);
    }

    // ---- fork: side stream runs the whole molecular-graph branch ----
    cudaEventRecord(evFork, 0);
    cudaStreamWaitEvent(s2, evFork, 0);

    {   // s2: MPNN branch (depends only on inputs)
        dim3 blk(32, 8);
        molstart_kernel<<<32, 256, 0, s2>>>(seg);
        transpose_kernel<<<dim3(8, 16), blk, 0, s2>>>(w_query, wqT, 2 * HH, HH);
        transpose_kernel<<<dim3(8, 8),  blk, 0, s2>>>(w_g0,   wg0T, HH, HH);
        transpose_kernel<<<dim3(8, 8),  blk, 0, s2>>>(w_g1,   wg1T, HH, HH);
        transpose_kernel<<<dim3(16, 8), blk, 0, s2>>>(w_bip,  wbipT, HH, NSUB);
        wm_kernel<<<(NSUB * LBL + 255) / 256, 256, 0, s2>>>(w_mlin, ddi);
        gather_kernel<<<(NATOMS * 64 + 255) / 256, 256, 0, s2>>>(embed_fp, fp);
        dim3 grid(HH / 64, (NATOMS + 127) / 128);
        gemm_f<<<grid, 256, GEMMF_SMEM, s2>>>(v, wg0T, b_g0, nullptr, hv, NATOMS, HH, HH, 1);
        adj_kernel<<<NMOL, HH, 0, s2>>>(adj);
        gemm_f<<<grid, 256, GEMMF_SMEM, s2>>>(v, wg1T, b_g1, nullptr, hv, NATOMS, HH, HH, 1);
        adj_kernel<<<NMOL, HH, 0, s2>>>(adj);
        molsum_kernel<<<NMOL, HH, 0, s2>>>();
        // mpnn_emb = avgproj @ molsum  (M=200, N=256, K=600)
        gemm_f<<<dim3(4, 2), 256, GEMMF_SMEM, s2>>>(avgproj, molsumT, nullptr, nullptr, emb,
                                                    LBL, HH, NMOL, 0);
        cudaEventRecord(evJoin, s2);
    }

    // ---- main stream: GRU path ----
    prep_idx_kernel<<<1, 256>>>(mask);
    zero_h_kernel<<<(2 * BB * HH + 255) / 256, 256>>>();

    {   // input projections: xp = x @ w_ih^T + b_ih (M=8192, N=768, K=128)
        dim3 grid(768 / 64, 8192 / 128);
        gemm_f<<<grid, 256, GEMMF_SMEM>>>(x_c, w_ih_c, b_ih_c, nullptr, xp,
                                          BB * SS, 3 * HH, II, 0);
        gemm_f<<<grid, 256, GEMMF_SMEM>>>(x_p, w_ih_p, b_ih_p, nullptr,
                                          xp + (size_t)BB * SS * 3 * HH,
                                          BB * SS, 3 * HH, II, 0);
    }

    // persistent GRU: one launch, 32 internal steps
    gru_persist_kernel<<<dim3(16, 4, 2), 256, GRU_SMEM>>>(w_hh_c, w_hh_p, b_hh_c, b_hh_p);

    // ---- join MPNN branch, then tail ----
    cudaStreamWaitEvent(0, evJoin, 0);

    concat_relu_kernel<<<BB, 512>>>();
    // query = relu(concat) @ w_query + b_query   (M=256, N=256, K=512)
    gemm_f<<<dim3(4, 2), 256, GEMMF_SMEM>>>(pat, wqT, b_query, nullptr, query,
                                            BB, HH, 2 * HH, 0);
    // match = sigmoid(query @ emb^T)   (M=256, N=200, K=256)
    gemm_f<<<dim3(4, 2), 256, GEMMF_SMEM>>>(query, emb, nullptr, nullptr, match,
                                            BB, LBL, HH, 2);
    att_kernel<<<BB, 256>>>(w_out, b_out, ln_g, ln_b);
    // bip = query @ w_bip + b_bip   (M=256, N=491, K=256)
    gemm_f<<<dim3(8, 2), 256, GEMMF_SMEM>>>(query, wbipT, b_bip, nullptr, bip,
                                            BB, NSUB, HH, 0);
    // out = (bip @ wm) * mpnn_att   (M=256, N=200, K=491) — odd K, generic kernel
    gemm_kernel<<<dim3(4, 4), 256>>>(bip, wm, nullptr, att, outp,
                                     BB, LBL, NSUB, 0, 0);
}

// round 6
// speedup vs baseline: 2.2141x; 1.1737x over previous
#include <cuda_runtime.h>
#include <cstdint>
#include <cstddef>

// ---------------------------------------------------------------------------
// Problem constants
// ---------------------------------------------------------------------------
#define BB    256      // batch
#define SS    32       // seq len
#define II    128      // input dim
#define HH    256      // hidden
#define LBL   200      // label
#define NSUB  491
#define NSUBP 496      // NSUB padded to multiple of 16 bytes/4 floats
#define NATOMS 8000
#define NMOL  600

// ---------------------------------------------------------------------------
// Scratch (static __device__ — no allocation anywhere)
// ---------------------------------------------------------------------------
__device__ __align__(16) float g_xp[2 * BB * SS * 3 * HH];
__device__ __align__(16) float g_h[2][2 * BB * HH];
__device__ __align__(16) float g_hlast[2 * BB * HH];
__device__ int   g_idxlast[BB];
__device__ int   g_molstart[NMOL + 1];
__device__ int   g_bar[8 * 32];                        // 8 barrier groups, 128B apart
__device__ __align__(16) float g_pat[BB * 2 * HH];
__device__ __align__(16) float g_query[BB * HH];
__device__ __align__(16) float g_v[NATOMS * HH];
__device__ __align__(16) float g_hv[NATOMS * HH];
__device__ __align__(16) float g_molsumT[HH * NMOL];   // transposed [H][NMOL]
__device__ __align__(16) float g_emb[LBL * HH];
__device__ __align__(16) float g_match[BB * LBL];
__device__ __align__(16) float g_att[BB * LBL];
__device__ __align__(16) float g_bip[BB * NSUBP];      // padded stride
__device__ __align__(16) float g_wmT[LBL * NSUBP];     // masked weight, transposed+padded
__device__ __align__(16) float g_bbip[NSUBP];          // padded bias
// pre-transposed weights (so all fast GEMMs are transB with K-contiguous rows)
__device__ __align__(16) float g_wqT[HH * 2 * HH];     // [256][512]
__device__ __align__(16) float g_wg0T[HH * HH];
__device__ __align__(16) float g_wg1T[HH * HH];
__device__ __align__(16) float g_wbipT[NSUBP * HH];    // [496][256], rows 491..495 zero

// ---------------------------------------------------------------------------
// Helpers
// ---------------------------------------------------------------------------
__device__ __forceinline__ unsigned long long ffma2(unsigned long long a,
                                                    unsigned long long b,
                                                    unsigned long long c) {
#if defined(__CUDA_ARCH__) && (__CUDA_ARCH__ >= 1000)
    unsigned long long d;
    asm("fma.rn.f32x2 %0, %1, %2, %3;" : "=l"(d) : "l"(a), "l"(b), "l"(c));
    return d;
#else
    float2 af = *reinterpret_cast<float2*>(&a);
    float2 bf = *reinterpret_cast<float2*>(&b);
    float2 cf = *reinterpret_cast<float2*>(&c);
    float2 df;
    df.x = fmaf(af.x, bf.x, cf.x);
    df.y = fmaf(af.y, bf.y, cf.y);
    return *reinterpret_cast<unsigned long long*>(&df);
#endif
}

__device__ __forceinline__ unsigned long long lds64(const float* p) {
    return *reinterpret_cast<const unsigned long long*>(p);
}

__device__ __forceinline__ float unpack_sum(unsigned long long u) {
    return __uint_as_float((unsigned)u) + __uint_as_float((unsigned)(u >> 32));
}

__device__ __forceinline__ float sigmoidf_(float x) {
    return 1.f / (1.f + expf(-x));
}

__device__ __forceinline__ void cp16(float* dst, const float* src, bool p) {
    unsigned s = (unsigned)__cvta_generic_to_shared(dst);
    int n = p ? 16 : 0;
    asm volatile("cp.async.ca.shared.global [%0], [%1], 16, %2;"
                 :: "r"(s), "l"(src), "r"(n));
}
__device__ __forceinline__ void cp8(float* dst, const float* src, bool p) {
    unsigned s = (unsigned)__cvta_generic_to_shared(dst);
    int n = p ? 8 : 0;
    asm volatile("cp.async.ca.shared.global [%0], [%1], 8, %2;"
                 :: "r"(s), "l"(src), "r"(n));
}
__device__ __forceinline__ void cp_commit() { asm volatile("cp.async.commit_group;"); }
__device__ __forceinline__ void cp_wait0()  { asm volatile("cp.async.wait_group 0;"); }

// ---------------------------------------------------------------------------
// Fast GEMM (transB only): C[M,N] = act( A[M,K] * B[N,K]^T + bias ) (* mul)
// K % 4 == 0 required. 128x64 tile, double-buffered cp.async, f32x2 8x4 tile.
// mulStride: row stride of mul (it may differ from N when C is padded).
// ---------------------------------------------------------------------------
__global__ void __launch_bounds__(256, 1)
gemm_f(const float* __restrict__ A, const float* __restrict__ Bm,
       const float* __restrict__ bias, const float* __restrict__ mul,
       float* __restrict__ C, int M, int N, int K, int act)
{
    extern __shared__ float sm[];
    float* As = sm;                 // [2][128][32]
    float* Bs = sm + 2 * 128 * 32;  // [2][64][32]
    const int tid = threadIdx.x;
    const int tx = tid & 15, ty = tid >> 4;
    const int m0 = blockIdx.y * 128, n0 = blockIdx.x * 64;
    const int nchunks = (K + 31) / 32;

    unsigned long long acc[8][4];
#pragma unroll
    for (int q = 0; q < 8; q++)
#pragma unroll
        for (int p = 0; p < 4; p++) acc[q][p] = 0ull;

    auto stage = [&](int buf, int k0) {
        float* Ab = As + buf * (128 * 32);
        float* Bb = Bs + buf * (64 * 32);
#pragma unroll
        for (int j = 0; j < 4; j++) {
            int idx = tid + 256 * j;
            int r = idx >> 3, kf4 = idx & 7;
            int gm = m0 + r, gk = k0 + kf4 * 4;
            bool pr = (gm < M) && (gk < K);
            const float* src = pr ? (A + (size_t)gm * K + gk) : A;
            cp16(Ab + r * 32 + ((kf4 ^ (r & 7)) << 2), src, pr);
        }
#pragma unroll
        for (int j = 0; j < 2; j++) {
            int idx = tid + 256 * j;
            int r = idx >> 3, kf4 = idx & 7;
            int gn = n0 + r, gk = k0 + kf4 * 4;
            bool pr = (gn < N) && (gk < K);
            const float* src = pr ? (Bm + (size_t)gn * K + gk) : Bm;
            cp16(Bb + r * 32 + ((kf4 ^ (r & 7)) << 2), src, pr);
        }
        cp_commit();
    };

    stage(0, 0);
    int buf = 0;
    for (int c = 0; c < nchunks; c++) {
        cp_wait0();
        __syncthreads();
        if (c + 1 < nchunks) stage(buf ^ 1, (c + 1) * 32);
        const float* Ab = As + buf * (128 * 32);
        const float* Bb = Bs + buf * (64 * 32);
#pragma unroll
        for (int k4 = 0; k4 < 8; k4++) {
            ulonglong2 a[8], b[4];
#pragma unroll
            for (int q = 0; q < 8; q++) {
                int r = ty + 16 * q;
                a[q] = *reinterpret_cast<const ulonglong2*>(
                    Ab + r * 32 + ((k4 ^ (r & 7)) << 2));
            }
#pragma unroll
            for (int p = 0; p < 4; p++) {
                int r = tx + 16 * p;
                b[p] = *reinterpret_cast<const ulonglong2*>(
                    Bb + r * 32 + ((k4 ^ (r & 7)) << 2));
            }
#pragma unroll
            for (int q = 0; q < 8; q++)
#pragma unroll
                for (int p = 0; p < 4; p++) {
                    acc[q][p] = ffma2(a[q].x, b[p].x, acc[q][p]);
                    acc[q][p] = ffma2(a[q].y, b[p].y, acc[q][p]);
                }
        }
        buf ^= 1;
    }

#pragma unroll
    for (int q = 0; q < 8; q++) {
        int gm = m0 + ty + 16 * q;
        if (gm >= M) continue;
#pragma unroll
        for (int p = 0; p < 4; p++) {
            int gn = n0 + tx + 16 * p;
            if (gn >= N) continue;
            float v = unpack_sum(acc[q][p]);
            if (bias) v += bias[gn];
            if (act == 1) v = fmaxf(v, 0.f);
            else if (act == 2) v = sigmoidf_(v);
            if (mul) v *= mul[(size_t)gm * N + gn];
            C[(size_t)gm * N + gn] = v;
        }
    }
}

// ---------------------------------------------------------------------------
// Transpose: out[C x R] = in[R x C]^T
// ---------------------------------------------------------------------------
__global__ void transpose_kernel(const float* __restrict__ in, float* __restrict__ out,
                                 int R, int C)
{
    __shared__ float tile[32][33];
    int bx = blockIdx.x * 32, by = blockIdx.y * 32;
    int x = bx + threadIdx.x;
#pragma unroll
    for (int j = 0; j < 32; j += 8) {
        int y = by + threadIdx.y + j;
        if (x < C && y < R) tile[threadIdx.y + j][threadIdx.x] = in[(size_t)y * C + x];
    }
    __syncthreads();
    int x2 = by + threadIdx.x;
#pragma unroll
    for (int j = 0; j < 32; j += 8) {
        int y2 = bx + threadIdx.y + j;
        if (x2 < R && y2 < C) out[(size_t)y2 * R + x2] = tile[threadIdx.x][threadIdx.y + j];
    }
}

// ---------------------------------------------------------------------------
// Small prep kernels
// ---------------------------------------------------------------------------
__global__ void prep_idx_kernel(const int* __restrict__ mask) {
    int b = threadIdx.x;
    if (b < BB) {
        int s = 0;
        for (int j = 0; j < SS; j++) s += mask[b * SS + j];
        g_idxlast[b] = s - 1;
    }
}

__global__ void molstart_kernel(const int* __restrict__ seg) {
    int stride = gridDim.x * blockDim.x;
    for (int i = blockIdx.x * blockDim.x + threadIdx.x; i < NATOMS; i += stride) {
        if (i == 0) {
            g_molstart[seg[0]] = 0;
            g_molstart[NMOL] = NATOMS;
        } else if (seg[i] != seg[i - 1]) {
            g_molstart[seg[i]] = i;
        }
    }
}

__global__ void zero_h_kernel() {
    int i = blockIdx.x * blockDim.x + threadIdx.x;
    if (i < 2 * BB * HH) g_h[0][i] = 0.f;
    if (i < 8 * 32) g_bar[i] = 0;
}

// pad bias + zero the 5 pad rows of wbipT (after its transpose)
__global__ void pad_kernel(const float* __restrict__ b_bip) {
    int i = blockIdx.x * blockDim.x + threadIdx.x;
    if (i < NSUBP) g_bbip[i] = (i < NSUB) ? b_bip[i] : 0.f;
    if (i < (NSUBP - NSUB) * HH) g_wbipT[NSUB * HH + i] = 0.f;
}

// masked bipartite weight, transposed + padded:
// wmT[j][k] = w_masklin[k][j] * ddi[j][k]  (k < NSUB), 0 for pad
__global__ void wmT_kernel(const float* __restrict__ w_masklin,
                           const float* __restrict__ ddi) {
    int idx = blockIdx.x * blockDim.x + threadIdx.x;
    if (idx < LBL * NSUBP) {
        int j = idx / NSUBP, k = idx - j * NSUBP;
        g_wmT[idx] = (k < NSUB) ? w_masklin[k * LBL + j] * ddi[j * NSUB + k] : 0.f;
    }
}

// ---------------------------------------------------------------------------
// Persistent GRU: single launch, 32 steps with inter-block barriers.
// Grid (16 colgroups, 4 batchgroups, 2 grus) = 128 blocks, 256 threads.
// ---------------------------------------------------------------------------
__global__ void __launch_bounds__(256)
gru_persist_kernel(const float* __restrict__ whh_c, const float* __restrict__ whh_p,
                   const float* __restrict__ bhh_c, const float* __restrict__ bhh_p)
{
    extern __shared__ float sm[];
    float* w_s = sm;                 // [48][258]
    float* h_s = sm + 48 * 258;      // [64][256]
    const int tid = threadIdx.x;
    const int c = tid & 15;
    const int bq = tid >> 4;         // 0..15
    const int g  = blockIdx.z;
    const int c0 = blockIdx.x * 16;
    const int b0 = blockIdx.y * 64;
    const int grp = blockIdx.y + 4 * blockIdx.z;      // 8 barrier groups of 16 blocks
    const float* whh = g ? whh_p : whh_c;
    const float* bhh = g ? bhh_p : bhh_c;
    const int col = c0 + c;

    // stage weights once
#pragma unroll
    for (int j = 0; j < 24; j++) {
        int idx = tid + 256 * j;
        int r = idx >> 7, f2 = idx & 127;
        int grow = (r >> 4) * HH + c0 + (r & 15);
        cp8(w_s + r * 258 + f2 * 2, whh + (size_t)grow * HH + f2 * 2, true);
    }
    cp_commit();

    const float bh_r = bhh[col];
    const float bh_z = bhh[HH + col];
    const float bh_n = bhh[2 * HH + col];
    const int idxl[4] = {g_idxlast[b0 + bq], g_idxlast[b0 + bq + 16],
                         g_idxlast[b0 + bq + 32], g_idxlast[b0 + bq + 48]};

    for (int t = 0; t < SS; t++) {
        const float* hsrc = g_h[t & 1] + g * (BB * HH);
#pragma unroll
        for (int j = 0; j < 16; j++) {
            int idx = tid + 256 * j;
            int r = idx >> 6, f4 = idx & 63;
            cp16(h_s + r * 256 + f4 * 4, hsrc + (b0 + r) * HH + f4 * 4, true);
        }
        cp_commit();

        float xr[4][3];
#pragma unroll
        for (int i = 0; i < 4; i++) {
            int b = b0 + bq + 16 * i;
            const float* xp = g_xp + ((size_t)g * BB * SS + (size_t)b * SS + t) * (3 * HH);
            xr[i][0] = __ldg(xp + col);
            xr[i][1] = __ldg(xp + HH + col);
            xr[i][2] = __ldg(xp + 2 * HH + col);
        }

        cp_wait0();
        __syncthreads();

        unsigned long long acc[4][3];
#pragma unroll
        for (int i = 0; i < 4; i++)
#pragma unroll
            for (int gt = 0; gt < 3; gt++) acc[i][gt] = 0ull;

#pragma unroll 8
        for (int k2 = 0; k2 < 128; k2++) {
            unsigned long long h2[4], w2[3];
#pragma unroll
            for (int i = 0; i < 4; i++)
                h2[i] = lds64(h_s + (bq + 16 * i) * 256 + 2 * k2);
#pragma unroll
            for (int gt = 0; gt < 3; gt++)
                w2[gt] = lds64(w_s + (gt * 16 + c) * 258 + 2 * k2);
#pragma unroll
            for (int i = 0; i < 4; i++)
#pragma unroll
                for (int gt = 0; gt < 3; gt++)
                    acc[i][gt] = ffma2(h2[i], w2[gt], acc[i][gt]);
        }

        float* hdst = g_h[(t + 1) & 1] + g * (BB * HH);
#pragma unroll
        for (int i = 0; i < 4; i++) {
            int b = b0 + bq + 16 * i;
            float hr = unpack_sum(acc[i][0]) + bh_r;
            float hz = unpack_sum(acc[i][1]) + bh_z;
            float hn = unpack_sum(acc[i][2]) + bh_n;
            float r = sigmoidf_(xr[i][0] + hr);
            float z = sigmoidf_(xr[i][1] + hz);
            float n = tanhf(xr[i][2] + r * hn);
            float hp = h_s[(bq + 16 * i) * 256 + col];
            float hnew = (1.f - z) * n + z * hp;
            hdst[b * HH + col] = hnew;
            if (t == idxl[i]) g_hlast[g * (BB * HH) + b * HH + col] = hnew;
        }

        if (t + 1 < SS) {
            __threadfence();
            __syncthreads();
            if (tid == 0) {
                atomicAdd(&g_bar[grp * 32], 1);
                int tgt = 16 * (t + 1);
                while (*(volatile int*)&g_bar[grp * 32] < tgt) { }
            }
            __syncthreads();
            __threadfence();
        }
    }
}

// ---------------------------------------------------------------------------
// relu(concat(h_c_last, h_p_last)) -> g_pat[B, 2H]
// ---------------------------------------------------------------------------
__global__ void concat_relu_kernel() {
    int b = blockIdx.x, tid = threadIdx.x;
    int g = tid >> 8, cc = tid & 255;
    float v = g_hlast[g * (BB * HH) + b * HH + cc];
    g_pat[b * (2 * HH) + tid] = fmaxf(v, 0.f);
}

// ---------------------------------------------------------------------------
// Fingerprint gather (flat, float4)
// ---------------------------------------------------------------------------
__global__ void gather_kernel(const float* __restrict__ embed_fp,
                              const int* __restrict__ fp) {
    int idx = blockIdx.x * blockDim.x + threadIdx.x;
    if (idx < NATOMS * (HH / 4)) {
        int a = idx >> 6, f4 = idx & 63;
        reinterpret_cast<float4*>(g_v)[(size_t)a * 64 + f4] =
            reinterpret_cast<const float4*>(embed_fp)[(size_t)fp[a] * 64 + f4];
    }
}

// ---------------------------------------------------------------------------
// Block-diagonal adjacency: v_out = hv + adj_block @ hv (per molecule)
// ---------------------------------------------------------------------------
__global__ void adj_kernel(const float* __restrict__ adj) {
    int m = blockIdx.x, tid = threadIdx.x;
    int s = g_molstart[m], e = g_molstart[m + 1];
    int na = e - s;
    __shared__ float hs[14][HH];
    __shared__ float as[14][14];
    for (int a = 0; a < na; a++) hs[a][tid] = g_hv[(s + a) * HH + tid];
    for (int idx = tid; idx < na * na; idx += 256) {
        int i = idx / na, j = idx - i * na;
        as[i][j] = adj[(size_t)(s + i) * NATOMS + (s + j)];
    }
    __syncthreads();
    for (int i = 0; i < na; i++) {
        float acc = hs[i][tid];
        for (int j = 0; j < na; j++) acc = fmaf(as[i][j], hs[j][tid], acc);
        g_v[(s + i) * HH + tid] = acc;
    }
}

// ---------------------------------------------------------------------------
// Per-molecule segment sum -> transposed [H][NMOL]
// ---------------------------------------------------------------------------
__global__ void molsum_kernel() {
    int m = blockIdx.x, c = threadIdx.x;
    int s = g_molstart[m], e = g_molstart[m + 1];
    float acc = 0.f;
    for (int i = s; i < e; i++) acc += g_v[i * HH + c];
    g_molsumT[c * NMOL + m] = acc;
}

// ---------------------------------------------------------------------------
// x2 = match + match @ w_out + b_out; layernorm -> g_att
// ---------------------------------------------------------------------------
__global__ void att_kernel(const float* __restrict__ w_out, const float* __restrict__ b_out,
                           const float* __restrict__ gamma, const float* __restrict__ beta)
{
    int b = blockIdx.x, tid = threadIdx.x;
    __shared__ float mrow[LBL];
    __shared__ float red[256];
    if (tid < LBL) mrow[tid] = g_match[b * LBL + tid];
    __syncthreads();
    float x2 = 0.f;
    if (tid < LBL) {
        float acc = 0.f;
        for (int k = 0; k < LBL; k++) acc = fmaf(mrow[k], w_out[k * LBL + tid], acc);
        x2 = mrow[tid] + acc + b_out[tid];
    }
    red[tid] = (tid < LBL) ? x2 : 0.f;
    __syncthreads();
    for (int s2 = 128; s2 > 0; s2 >>= 1) {
        if (tid < s2) red[tid] += red[tid + s2];
        __syncthreads();
    }
    float mean = red[0] * (1.f / LBL);
    __syncthreads();
    float d = x2 - mean;
    red[tid] = (tid < LBL) ? d * d : 0.f;
    __syncthreads();
    for (int s2 = 128; s2 > 0; s2 >>= 1) {
        if (tid < s2) red[tid] += red[tid + s2];
        __syncthreads();
    }
    float var = red[0] * (1.f / LBL);
    if (tid < LBL)
        g_att[b * LBL + tid] = d * rsqrtf(var + 1e-5f) * gamma[tid] + beta[tid];
}

// ---------------------------------------------------------------------------
// Launch orchestration
//   s2: MPNN branch (joined BEFORE the persistent GRU so GRU owns the chip)
//   s3: tail-only weight prep (joined before the tail)
// ---------------------------------------------------------------------------
extern "C" void kernel_launch(void* const* d_in, const int* in_sizes, int n_in,
                              void* d_out, int out_size) {
    const float* x_c      = (const float*)d_in[0];
    const float* x_p      = (const float*)d_in[1];
    const int*   mask     = (const int*)  d_in[2];
    const float* w_ih_c   = (const float*)d_in[3];
    const float* w_hh_c   = (const float*)d_in[4];
    const float* b_ih_c   = (const float*)d_in[5];
    const float* b_hh_c   = (const float*)d_in[6];
    const float* w_ih_p   = (const float*)d_in[7];
    const float* w_hh_p   = (const float*)d_in[8];
    const float* b_ih_p   = (const float*)d_in[9];
    const float* b_hh_p   = (const float*)d_in[10];
    const float* w_query  = (const float*)d_in[11];
    const float* b_query  = (const float*)d_in[12];
    const float* w_bip    = (const float*)d_in[13];
    const float* b_bip    = (const float*)d_in[14];
    const float* w_mlin   = (const float*)d_in[15];
    const float* ddi      = (const float*)d_in[16];
    const float* embed_fp = (const float*)d_in[17];
    const int*   fp       = (const int*)  d_in[18];
    const float* adj      = (const float*)d_in[19];
    const int*   seg      = (const int*)  d_in[20];
    const float* w_g0     = (const float*)d_in[21];
    const float* b_g0     = (const float*)d_in[22];
    const float* w_g1     = (const float*)d_in[23];
    const float* b_g1     = (const float*)d_in[24];
    const float* avgproj  = (const float*)d_in[25];
    const float* w_out    = (const float*)d_in[26];
    const float* b_out    = (const float*)d_in[27];
    const float* ln_g     = (const float*)d_in[28];
    const float* ln_b     = (const float*)d_in[29];
    float* outp = (float*)d_out;

    float *xp, *pat, *query, *v, *hv, *molsumT, *emb, *match, *bip, *wmT, *att, *bbip;
    float *wqT, *wg0T, *wg1T, *wbipT;
    cudaGetSymbolAddress((void**)&xp,      g_xp);
    cudaGetSymbolAddress((void**)&pat,     g_pat);
    cudaGetSymbolAddress((void**)&query,   g_query);
    cudaGetSymbolAddress((void**)&v,       g_v);
    cudaGetSymbolAddress((void**)&hv,      g_hv);
    cudaGetSymbolAddress((void**)&molsumT, g_molsumT);
    cudaGetSymbolAddress((void**)&emb,     g_emb);
    cudaGetSymbolAddress((void**)&match,   g_match);
    cudaGetSymbolAddress((void**)&bip,     g_bip);
    cudaGetSymbolAddress((void**)&wmT,     g_wmT);
    cudaGetSymbolAddress((void**)&att,     g_att);
    cudaGetSymbolAddress((void**)&bbip,    g_bbip);
    cudaGetSymbolAddress((void**)&wqT,     g_wqT);
    cudaGetSymbolAddress((void**)&wg0T,    g_wg0T);
    cudaGetSymbolAddress((void**)&wg1T,    g_wg1T);
    cudaGetSymbolAddress((void**)&wbipT,   g_wbipT);

    const int GEMMF_SMEM = (2 * 128 * 32 + 2 * 64 * 32) * 4;        // 49152
    const int GRU_SMEM   = (48 * 258 + 64 * 256) * 4;               // 115072

    static cudaStream_t s2 = nullptr, s3 = nullptr;
    static cudaEvent_t evFork = nullptr, evJoin2 = nullptr, evJoin3 = nullptr;
    if (!s2) {
        cudaStreamCreateWithFlags(&s2, cudaStreamNonBlocking);
        cudaStreamCreateWithFlags(&s3, cudaStreamNonBlocking);
        cudaEventCreateWithFlags(&evFork, cudaEventDisableTiming);
        cudaEventCreateWithFlags(&evJoin2, cudaEventDisableTiming);
        cudaEventCreateWithFlags(&evJoin3, cudaEventDisableTiming);
        cudaFuncSetAttribute(gemm_f, cudaFuncAttributeMaxDynamicSharedMemorySize, GEMMF_SMEM);
        cudaFuncSetAttribute(gru_persist_kernel, cudaFuncAttributeMaxDynamicSharedMemorySize, GRU_SMEM);
    }

    cudaEventRecord(evFork, 0);
    cudaStreamWaitEvent(s2, evFork, 0);
    cudaStreamWaitEvent(s3, evFork, 0);

    {   // s3: tail-only weight prep
        dim3 blk(32, 8);
        transpose_kernel<<<dim3(8, 16), blk, 0, s3>>>(w_query, wqT, 2 * HH, HH);
        transpose_kernel<<<dim3(16, 8), blk, 0, s3>>>(w_bip,  wbipT, HH, NSUB);
        pad_kernel<<<((NSUBP - NSUB) * HH + 255) / 256, 256, 0, s3>>>(b_bip);
        wmT_kernel<<<(LBL * NSUBP + 255) / 256, 256, 0, s3>>>(w_mlin, ddi);
        cudaEventRecord(evJoin3, s3);
    }

    {   // s2: MPNN branch
        dim3 blk(32, 8);
        molstart_kernel<<<32, 256, 0, s2>>>(seg);
        transpose_kernel<<<dim3(8, 8), blk, 0, s2>>>(w_g0, wg0T, HH, HH);
        transpose_kernel<<<dim3(8, 8), blk, 0, s2>>>(w_g1, wg1T, HH, HH);
        gather_kernel<<<(NATOMS * 64 + 255) / 256, 256, 0, s2>>>(embed_fp, fp);
        dim3 grid(HH / 64, (NATOMS + 127) / 128);
        gemm_f<<<grid, 256, GEMMF_SMEM, s2>>>(v, wg0T, b_g0, nullptr, hv, NATOMS, HH, HH, 1);
        adj_kernel<<<NMOL, HH, 0, s2>>>(adj);
        gemm_f<<<grid, 256, GEMMF_SMEM, s2>>>(v, wg1T, b_g1, nullptr, hv, NATOMS, HH, HH, 1);
        adj_kernel<<<NMOL, HH, 0, s2>>>(adj);
        molsum_kernel<<<NMOL, HH, 0, s2>>>();
        gemm_f<<<dim3(4, 2), 256, GEMMF_SMEM, s2>>>(avgproj, molsumT, nullptr, nullptr, emb,
                                                    LBL, HH, NMOL, 0);
        cudaEventRecord(evJoin2, s2);
    }

    // ---- main stream: prep + input projections (overlap the MPNN branch) ----
    prep_idx_kernel<<<1, 256>>>(mask);
    zero_h_kernel<<<(2 * BB * HH + 255) / 256, 256>>>();
    {
        dim3 grid(768 / 64, 8192 / 128);
        gemm_f<<<grid, 256, GEMMF_SMEM>>>(x_c, w_ih_c, b_ih_c, nullptr, xp,
                                          BB * SS, 3 * HH, II, 0);
        gemm_f<<<grid, 256, GEMMF_SMEM>>>(x_p, w_ih_p, b_ih_p, nullptr,
                                          xp + (size_t)BB * SS * 3 * HH,
                                          BB * SS, 3 * HH, II, 0);
    }

    // ---- join MPNN FIRST so the persistent GRU owns the whole chip ----
    cudaStreamWaitEvent(0, evJoin2, 0);
    gru_persist_kernel<<<dim3(16, 4, 2), 256, GRU_SMEM>>>(w_hh_c, w_hh_p, b_hh_c, b_hh_p);

    // ---- tail ----
    cudaStreamWaitEvent(0, evJoin3, 0);
    concat_relu_kernel<<<BB, 512>>>();
    gemm_f<<<dim3(4, 2), 256, GEMMF_SMEM>>>(pat, wqT, b_query, nullptr, query,
                                            BB, HH, 2 * HH, 0);
    gemm_f<<<dim3(4, 2), 256, GEMMF_SMEM>>>(query, emb, nullptr, nullptr, match,
                                            BB, LBL, HH, 2);
    att_kernel<<<BB, 256>>>(w_out, b_out, ln_g, ln_b);
    // bip = query @ w_bip + b_bip  (N padded to 496; pad rows of wbipT are zero)
    gemm_f<<<dim3(NSUBP / 64 + 1, 2), 256, GEMMF_SMEM>>>(query, wbipT, bbip, nullptr, bip,
                                                         BB, NSUBP, HH, 0);
    // out = (bip @ wmT^T) * mpnn_att  (K padded to 496, pad contributes zero)
    gemm_f<<<dim3(4, 2), 256, GEMMF_SMEM>>>(bip, wmT, nullptr, att, outp,
                                            BB, LBL, NSUBP, 0);
}

// round 12
// speedup vs baseline: 2.4624x; 1.1121x over previous
#include <cuda_runtime.h>
#include <cstdint>
#include <cstddef>

// ---------------------------------------------------------------------------
// Problem constants
// ---------------------------------------------------------------------------
#define BB    256      // batch
#define SS    32       // seq len
#define II    128      // input dim
#define HH    256      // hidden
#define LBL   200      // label
#define NSUB  491
#define NSUBP 496      // NSUB padded to multiple of 4 floats
#define NATOMS 8000
#define NMOL  600

// ---------------------------------------------------------------------------
// Scratch (static __device__ — no allocation anywhere)
// ---------------------------------------------------------------------------
__device__ __align__(16) float g_xp[2 * BB * SS * 3 * HH];
__device__ __align__(16) float g_h[2][2 * BB * HH];
__device__ int   g_idxlast[BB];
__device__ int   g_molstart[NMOL + 1];
__device__ int   g_bar[8 * 32];                        // 8 barrier groups, 128B apart
__device__ __align__(16) float g_pat[BB * 2 * HH];     // relu(h_last) written by GRU
__device__ __align__(16) float g_query[BB * HH];
__device__ __align__(16) float g_v[NATOMS * HH];
__device__ __align__(16) float g_hv[NATOMS * HH];
__device__ __align__(16) float g_molsumT[HH * NMOL];   // transposed [H][NMOL]
__device__ __align__(16) float g_emb[LBL * HH];
__device__ __align__(16) float g_match[BB * LBL];
__device__ __align__(16) float g_att[BB * LBL];
__device__ __align__(16) float g_bip[BB * NSUBP];      // padded stride
__device__ __align__(16) float g_wmT[LBL * NSUBP];     // masked weight, transposed+padded
__device__ __align__(16) float g_bbip[NSUBP];          // padded bias
// pre-transposed weights (all fast GEMMs are transB with K-contiguous rows)
__device__ __align__(16) float g_wqT[HH * 2 * HH];     // [256][512]
__device__ __align__(16) float g_wg0T[HH * HH];
__device__ __align__(16) float g_wg1T[HH * HH];
__device__ __align__(16) float g_wbipT[NSUBP * HH];    // [496][256], rows 491..495 zero

// ---------------------------------------------------------------------------
// Helpers
// ---------------------------------------------------------------------------
__device__ __forceinline__ unsigned long long ffma2(unsigned long long a,
                                                    unsigned long long b,
                                                    unsigned long long c) {
#if defined(__CUDA_ARCH__) && (__CUDA_ARCH__ >= 1000)
    unsigned long long d;
    asm("fma.rn.f32x2 %0, %1, %2, %3;" : "=l"(d) : "l"(a), "l"(b), "l"(c));
    return d;
#else
    float2 af = *reinterpret_cast<float2*>(&a);
    float2 bf = *reinterpret_cast<float2*>(&b);
    float2 cf = *reinterpret_cast<float2*>(&c);
    float2 df;
    df.x = fmaf(af.x, bf.x, cf.x);
    df.y = fmaf(af.y, bf.y, cf.y);
    return *reinterpret_cast<unsigned long long*>(&df);
#endif
}

__device__ __forceinline__ unsigned long long lds64(const float* p) {
    return *reinterpret_cast<const unsigned long long*>(p);
}

__device__ __forceinline__ float unpack_sum(unsigned long long u) {
    return __uint_as_float((unsigned)u) + __uint_as_float((unsigned)(u >> 32));
}

__device__ __forceinline__ float sigmoidf_(float x) {
    return 1.f / (1.f + expf(-x));
}

__device__ __forceinline__ void cp16(float* dst, const float* src, bool p) {
    unsigned s = (unsigned)__cvta_generic_to_shared(dst);
    int n = p ? 16 : 0;
    asm volatile("cp.async.ca.shared.global [%0], [%1], 16, %2;"
                 :: "r"(s), "l"(src), "r"(n));
}
__device__ __forceinline__ void cp8(float* dst, const float* src, bool p) {
    unsigned s = (unsigned)__cvta_generic_to_shared(dst);
    int n = p ? 8 : 0;
    asm volatile("cp.async.ca.shared.global [%0], [%1], 8, %2;"
                 :: "r"(s), "l"(src), "r"(n));
}
__device__ __forceinline__ void cp_commit() { asm volatile("cp.async.commit_group;"); }
__device__ __forceinline__ void cp_wait0()  { asm volatile("cp.async.wait_group 0;"); }

// ---------------------------------------------------------------------------
// Fast GEMM (transB): C[M,N] = act( A[M,K] * B[N,K]^T + bias ) (* mul)
// 128x64 block tile, 256 threads, double-buffered cp.async, f32x2 8x4 tile.
// Optional rowidx: A row gm is read from A[rowidx[gm]] (fused gather).
// ---------------------------------------------------------------------------
__global__ void __launch_bounds__(256, 1)
gemm_f(const float* __restrict__ A, const float* __restrict__ Bm,
       const float* __restrict__ bias, const float* __restrict__ mul,
       float* __restrict__ C, int M, int N, int K, int act,
       const int* __restrict__ rowidx)
{
    extern __shared__ float sm[];
    float* As = sm;                 // [2][128][32]
    float* Bs = sm + 2 * 128 * 32;  // [2][64][32]
    const int tid = threadIdx.x;
    const int tx = tid & 15, ty = tid >> 4;
    const int m0 = blockIdx.y * 128, n0 = blockIdx.x * 64;
    const int nchunks = (K + 31) / 32;

    unsigned long long acc[8][4];
#pragma unroll
    for (int q = 0; q < 8; q++)
#pragma unroll
        for (int p = 0; p < 4; p++) acc[q][p] = 0ull;

    auto stage = [&](int buf, int k0) {
        float* Ab = As + buf * (128 * 32);
        float* Bb = Bs + buf * (64 * 32);
#pragma unroll
        for (int j = 0; j < 4; j++) {
            int idx = tid + 256 * j;
            int r = idx >> 3, kf4 = idx & 7;
            int gm = m0 + r, gk = k0 + kf4 * 4;
            bool pr = (gm < M) && (gk < K);
            int grow = pr ? (rowidx ? rowidx[gm] : gm) : 0;
            const float* src = pr ? (A + (size_t)grow * K + gk) : A;
            cp16(Ab + r * 32 + ((kf4 ^ (r & 7)) << 2), src, pr);
        }
#pragma unroll
        for (int j = 0; j < 2; j++) {
            int idx = tid + 256 * j;
            int r = idx >> 3, kf4 = idx & 7;
            int gn = n0 + r, gk = k0 + kf4 * 4;
            bool pr = (gn < N) && (gk < K);
            const float* src = pr ? (Bm + (size_t)gn * K + gk) : Bm;
            cp16(Bb + r * 32 + ((kf4 ^ (r & 7)) << 2), src, pr);
        }
        cp_commit();
    };

    stage(0, 0);
    int buf = 0;
    for (int c = 0; c < nchunks; c++) {
        cp_wait0();
        __syncthreads();
        if (c + 1 < nchunks) stage(buf ^ 1, (c + 1) * 32);
        const float* Ab = As + buf * (128 * 32);
        const float* Bb = Bs + buf * (64 * 32);
#pragma unroll
        for (int k4 = 0; k4 < 8; k4++) {
            ulonglong2 a[8], b[4];
#pragma unroll
            for (int q = 0; q < 8; q++) {
                int r = ty + 16 * q;
                a[q] = *reinterpret_cast<const ulonglong2*>(
                    Ab + r * 32 + ((k4 ^ (r & 7)) << 2));
            }
#pragma unroll
            for (int p = 0; p < 4; p++) {
                int r = tx + 16 * p;
                b[p] = *reinterpret_cast<const ulonglong2*>(
                    Bb + r * 32 + ((k4 ^ (r & 7)) << 2));
            }
#pragma unroll
            for (int q = 0; q < 8; q++)
#pragma unroll
                for (int p = 0; p < 4; p++) {
                    acc[q][p] = ffma2(a[q].x, b[p].x, acc[q][p]);
                    acc[q][p] = ffma2(a[q].y, b[p].y, acc[q][p]);
                }
        }
        buf ^= 1;
    }

#pragma unroll
    for (int q = 0; q < 8; q++) {
        int gm = m0 + ty + 16 * q;
        if (gm >= M) continue;
#pragma unroll
        for (int p = 0; p < 4; p++) {
            int gn = n0 + tx + 16 * p;
            if (gn >= N) continue;
            float v = unpack_sum(acc[q][p]);
            if (bias) v += bias[gn];
            if (act == 1) v = fmaxf(v, 0.f);
            else if (act == 2) v = sigmoidf_(v);
            if (mul) v *= mul[(size_t)gm * N + gn];
            C[(size_t)gm * N + gn] = v;
        }
    }
}

// ---------------------------------------------------------------------------
// Small-M GEMM (transB): 64x32 block tile, 128 threads. Same contract.
// ---------------------------------------------------------------------------
__global__ void __launch_bounds__(128)
gemm_s(const float* __restrict__ A, const float* __restrict__ Bm,
       const float* __restrict__ bias, const float* __restrict__ mul,
       float* __restrict__ C, int M, int N, int K, int act)
{
    __shared__ float As[2][64 * 32];
    __shared__ float Bs[2][32 * 32];
    const int tid = threadIdx.x;
    const int tx = tid & 7, ty = tid >> 3;          // 8 x 16
    const int m0 = blockIdx.y * 64, n0 = blockIdx.x * 32;
    const int nchunks = (K + 31) / 32;

    unsigned long long acc[4][4];
#pragma unroll
    for (int q = 0; q < 4; q++)
#pragma unroll
        for (int p = 0; p < 4; p++) acc[q][p] = 0ull;

    auto stage = [&](int buf, int k0) {
#pragma unroll
        for (int j = 0; j < 4; j++) {               // A: 512 float4
            int idx = tid + 128 * j;
            int r = idx >> 3, kf4 = idx & 7;
            int gm = m0 + r, gk = k0 + kf4 * 4;
            bool pr = (gm < M) && (gk < K);
            const float* src = pr ? (A + (size_t)gm * K + gk) : A;
            cp16(&As[buf][r * 32 + ((kf4 ^ (r & 7)) << 2)], src, pr);
        }
#pragma unroll
        for (int j = 0; j < 2; j++) {               // B: 256 float4
            int idx = tid + 128 * j;
            int r = idx >> 3, kf4 = idx & 7;
            int gn = n0 + r, gk = k0 + kf4 * 4;
            bool pr = (gn < N) && (gk < K);
            const float* src = pr ? (Bm + (size_t)gn * K + gk) : Bm;
            cp16(&Bs[buf][r * 32 + ((kf4 ^ (r & 7)) << 2)], src, pr);
        }
        cp_commit();
    };

    stage(0, 0);
    int buf = 0;
    for (int c = 0; c < nchunks; c++) {
        cp_wait0();
        __syncthreads();
        if (c + 1 < nchunks) stage(buf ^ 1, (c + 1) * 32);
#pragma unroll
        for (int k4 = 0; k4 < 8; k4++) {
            ulonglong2 a[4], b[4];
#pragma unroll
            for (int q = 0; q < 4; q++) {
                int r = ty + 16 * q;
                a[q] = *reinterpret_cast<const ulonglong2*>(
                    &As[buf][r * 32 + ((k4 ^ (r & 7)) << 2)]);
            }
#pragma unroll
            for (int p = 0; p < 4; p++) {
                int r = tx + 8 * p;
                b[p] = *reinterpret_cast<const ulonglong2*>(
                    &Bs[buf][r * 32 + ((k4 ^ (r & 7)) << 2)]);
            }
#pragma unroll
            for (int q = 0; q < 4; q++)
#pragma unroll
                for (int p = 0; p < 4; p++) {
                    acc[q][p] = ffma2(a[q].x, b[p].x, acc[q][p]);
                    acc[q][p] = ffma2(a[q].y, b[p].y, acc[q][p]);
                }
        }
        buf ^= 1;
    }

#pragma unroll
    for (int q = 0; q < 4; q++) {
        int gm = m0 + ty + 16 * q;
        if (gm >= M) continue;
#pragma unroll
        for (int p = 0; p < 4; p++) {
            int gn = n0 + tx + 8 * p;
            if (gn >= N) continue;
            float v = unpack_sum(acc[q][p]);
            if (bias) v += bias[gn];
            if (act == 1) v = fmaxf(v, 0.f);
            else if (act == 2) v = sigmoidf_(v);
            if (mul) v *= mul[(size_t)gm * N + gn];
            C[(size_t)gm * N + gn] = v;
        }
    }
}

// ---------------------------------------------------------------------------
// Transpose: out[C x R] = in[R x C]^T
// ---------------------------------------------------------------------------
__global__ void transpose_kernel(const float* __restrict__ in, float* __restrict__ out,
                                 int R, int C)
{
    __shared__ float tile[32][33];
    int bx = blockIdx.x * 32, by = blockIdx.y * 32;
    int x = bx + threadIdx.x;
#pragma unroll
    for (int j = 0; j < 32; j += 8) {
        int y = by + threadIdx.y + j;
        if (x < C && y < R) tile[threadIdx.y + j][threadIdx.x] = in[(size_t)y * C + x];
    }
    __syncthreads();
    int x2 = by + threadIdx.x;
#pragma unroll
    for (int j = 0; j < 32; j += 8) {
        int y2 = bx + threadIdx.y + j;
        if (x2 < R && y2 < C) out[(size_t)y2 * R + x2] = tile[threadIdx.x][threadIdx.y + j];
    }
}

// ---------------------------------------------------------------------------
// Main-stream prep: last-visit idx, zero h + barriers
// ---------------------------------------------------------------------------
__global__ void prep_kernel(const int* __restrict__ mask) {
    int i = blockIdx.x * blockDim.x + threadIdx.x;
    if (i < 2 * BB * HH) g_h[0][i] = 0.f;
    if (i < 8 * 32) g_bar[i] = 0;
    if (i < BB) {
        int s = 0;
        for (int j = 0; j < SS; j++) s += mask[i * SS + j];
        g_idxlast[i] = s - 1;
    }
}

// ---------------------------------------------------------------------------
// molstart (runs on s2, stream-ordered before adj kernels)
// ---------------------------------------------------------------------------
__global__ void molstart_kernel(const int* __restrict__ seg) {
    int stride = gridDim.x * blockDim.x;
    for (int i = blockIdx.x * blockDim.x + threadIdx.x; i < NATOMS; i += stride) {
        if (i == 0) {
            g_molstart[seg[0]] = 0;
            g_molstart[NMOL] = NATOMS;
        } else if (seg[i] != seg[i - 1]) {
            g_molstart[seg[i]] = i;
        }
    }
}

// ---------------------------------------------------------------------------
// Merged tail-weight prep: wmT (transposed+padded) + padded bias + wbipT pad rows
// ---------------------------------------------------------------------------
__global__ void wprep_kernel(const float* __restrict__ w_masklin,
                             const float* __restrict__ ddi,
                             const float* __restrict__ b_bip) {
    int idx = blockIdx.x * blockDim.x + threadIdx.x;
    if (idx < LBL * NSUBP) {
        int j = idx / NSUBP, k = idx - j * NSUBP;
        g_wmT[idx] = (k < NSUB) ? w_masklin[k * LBL + j] * ddi[j * NSUB + k] : 0.f;
    }
    if (idx < NSUBP) g_bbip[idx] = (idx < NSUB) ? b_bip[idx] : 0.f;
    if (idx < (NSUBP - NSUB) * HH) g_wbipT[NSUB * HH + idx] = 0.f;
}

// ---------------------------------------------------------------------------
// Persistent GRU: single launch, 32 steps with inter-block barriers.
// Grid (16 colgroups, 4 batchgroups, 2 grus) = 128 blocks, 256 threads.
// Writes relu(h_last) straight into g_pat (concat layout).
// ---------------------------------------------------------------------------
__global__ void __launch_bounds__(256)
gru_persist_kernel(const float* __restrict__ whh_c, const float* __restrict__ whh_p,
                   const float* __restrict__ bhh_c, const float* __restrict__ bhh_p)
{
    extern __shared__ float sm[];
    float* w_s = sm;                 // [48][258]
    float* h_s = sm + 48 * 258;      // [64][256]
    const int tid = threadIdx.x;
    const int c = tid & 15;
    const int bq = tid >> 4;         // 0..15
    const int g  = blockIdx.z;
    const int c0 = blockIdx.x * 16;
    const int b0 = blockIdx.y * 64;
    const int grp = blockIdx.y + 4 * blockIdx.z;      // 8 barrier groups of 16 blocks
    const float* whh = g ? whh_p : whh_c;
    const float* bhh = g ? bhh_p : bhh_c;
    const int col = c0 + c;

    // stage weights once
#pragma unroll
    for (int j = 0; j < 24; j++) {
        int idx = tid + 256 * j;
        int r = idx >> 7, f2 = idx & 127;
        int grow = (r >> 4) * HH + c0 + (r & 15);
        cp8(w_s + r * 258 + f2 * 2, whh + (size_t)grow * HH + f2 * 2, true);
    }
    cp_commit();

    const float bh_r = bhh[col];
    const float bh_z = bhh[HH + col];
    const float bh_n = bhh[2 * HH + col];
    const int idxl[4] = {g_idxlast[b0 + bq], g_idxlast[b0 + bq + 16],
                         g_idxlast[b0 + bq + 32], g_idxlast[b0 + bq + 48]};

    for (int t = 0; t < SS; t++) {
        const float* hsrc = g_h[t & 1] + g * (BB * HH);
#pragma unroll
        for (int j = 0; j < 16; j++) {
            int idx = tid + 256 * j;
            int r = idx >> 6, f4 = idx & 63;
            cp16(h_s + r * 256 + f4 * 4, hsrc + (b0 + r) * HH + f4 * 4, true);
        }
        cp_commit();

        float xr[4][3];
#pragma unroll
        for (int i = 0; i < 4; i++) {
            int b = b0 + bq + 16 * i;
            const float* xp = g_xp + ((size_t)g * BB * SS + (size_t)b * SS + t) * (3 * HH);
            xr[i][0] = __ldg(xp + col);
            xr[i][1] = __ldg(xp + HH + col);
            xr[i][2] = __ldg(xp + 2 * HH + col);
        }

        cp_wait0();
        __syncthreads();

        unsigned long long acc[4][3];
#pragma unroll
        for (int i = 0; i < 4; i++)
#pragma unroll
            for (int gt = 0; gt < 3; gt++) acc[i][gt] = 0ull;

#pragma unroll 8
        for (int k2 = 0; k2 < 128; k2++) {
            unsigned long long h2[4], w2[3];
#pragma unroll
            for (int i = 0; i < 4; i++)
                h2[i] = lds64(h_s + (bq + 16 * i) * 256 + 2 * k2);
#pragma unroll
            for (int gt = 0; gt < 3; gt++)
                w2[gt] = lds64(w_s + (gt * 16 + c) * 258 + 2 * k2);
#pragma unroll
            for (int i = 0; i < 4; i++)
#pragma unroll
                for (int gt = 0; gt < 3; gt++)
                    acc[i][gt] = ffma2(h2[i], w2[gt], acc[i][gt]);
        }

        float* hdst = g_h[(t + 1) & 1] + g * (BB * HH);
#pragma unroll
        for (int i = 0; i < 4; i++) {
            int b = b0 + bq + 16 * i;
            float hr = unpack_sum(acc[i][0]) + bh_r;
            float hz = unpack_sum(acc[i][1]) + bh_z;
            float hn = unpack_sum(acc[i][2]) + bh_n;
            float r = sigmoidf_(xr[i][0] + hr);
            float z = sigmoidf_(xr[i][1] + hz);
            float n = tanhf(xr[i][2] + r * hn);
            float hp = h_s[(bq + 16 * i) * 256 + col];
            float hnew = (1.f - z) * n + z * hp;
            hdst[b * HH + col] = hnew;
            if (t == idxl[i])
                g_pat[b * (2 * HH) + g * HH + col] = fmaxf(hnew, 0.f);
        }

        if (t + 1 < SS) {
            __threadfence();
            __syncthreads();
            if (tid == 0) {
                atomicAdd(&g_bar[grp * 32], 1);
                int tgt = 16 * (t + 1);
                while (*(volatile int*)&g_bar[grp * 32] < tgt) {
                    __nanosleep(64);
                }
            }
            __syncthreads();
            __threadfence();
        }
    }
}

// ---------------------------------------------------------------------------
// Block-diagonal adjacency pass 1: v = hv + adj_block @ hv (per molecule)
// ---------------------------------------------------------------------------
__global__ void adj_kernel(const float* __restrict__ adj) {
    int m = blockIdx.x, tid = threadIdx.x;
    int s = g_molstart[m], e = g_molstart[m + 1];
    int na = e - s;
    __shared__ float hs[14][HH];
    __shared__ float as[14][14];
    for (int a = 0; a < na; a++) hs[a][tid] = g_hv[(s + a) * HH + tid];
    for (int idx = tid; idx < na * na; idx += 256) {
        int i = idx / na, j = idx - i * na;
        as[i][j] = adj[(size_t)(s + i) * NATOMS + (s + j)];
    }
    __syncthreads();
    for (int i = 0; i < na; i++) {
        float acc = hs[i][tid];
        for (int j = 0; j < na; j++) acc = fmaf(as[i][j], hs[j][tid], acc);
        g_v[(s + i) * HH + tid] = acc;
    }
}

// ---------------------------------------------------------------------------
// Fused adjacency pass 2 + segment sum -> molsumT [H][NMOL]
// ---------------------------------------------------------------------------
__global__ void adj_molsum_kernel(const float* __restrict__ adj) {
    int m = blockIdx.x, tid = threadIdx.x;
    int s = g_molstart[m], e = g_molstart[m + 1];
    int na = e - s;
    __shared__ float hs[14][HH];
    __shared__ float as[14][14];
    for (int a = 0; a < na; a++) hs[a][tid] = g_hv[(s + a) * HH + tid];
    for (int idx = tid; idx < na * na; idx += 256) {
        int i = idx / na, j = idx - i * na;
        as[i][j] = adj[(size_t)(s + i) * NATOMS + (s + j)];
    }
    __syncthreads();
    float sum = 0.f;
    for (int i = 0; i < na; i++) {
        float acc = hs[i][tid];
        for (int j = 0; j < na; j++) acc = fmaf(as[i][j], hs[j][tid], acc);
        sum += acc;
    }
    g_molsumT[tid * NMOL + m] = sum;
}

// ---------------------------------------------------------------------------
// x2 = match + match @ w_out + b_out; layernorm -> g_att
// ---------------------------------------------------------------------------
__global__ void att_kernel(const float* __restrict__ w_out, const float* __restrict__ b_out,
                           const float* __restrict__ gamma, const float* __restrict__ beta)
{
    int b = blockIdx.x, tid = threadIdx.x;
    __shared__ float mrow[LBL];
    __shared__ float red[256];
    if (tid < LBL) mrow[tid] = g_match[b * LBL + tid];
    __syncthreads();
    float x2 = 0.f;
    if (tid < LBL) {
        float acc = 0.f;
        for (int k = 0; k < LBL; k++) acc = fmaf(mrow[k], w_out[k * LBL + tid], acc);
        x2 = mrow[tid] + acc + b_out[tid];
    }
    red[tid] = (tid < LBL) ? x2 : 0.f;
    __syncthreads();
    for (int s2 = 128; s2 > 0; s2 >>= 1) {
        if (tid < s2) red[tid] += red[tid + s2];
        __syncthreads();
    }
    float mean = red[0] * (1.f / LBL);
    __syncthreads();
    float d = x2 - mean;
    red[tid] = (tid < LBL) ? d * d : 0.f;
    __syncthreads();
    for (int s2 = 128; s2 > 0; s2 >>= 1) {
        if (tid < s2) red[tid] += red[tid + s2];
        __syncthreads();
    }
    float var = red[0] * (1.f / LBL);
    if (tid < LBL)
        g_att[b * LBL + tid] = d * rsqrtf(var + 1e-5f) * gamma[tid] + beta[tid];
}

// ---------------------------------------------------------------------------
// Launch orchestration
// ---------------------------------------------------------------------------
extern "C" void kernel_launch(void* const* d_in, const int* in_sizes, int n_in,
                              void* d_out, int out_size) {
    const float* x_c      = (const float*)d_in[0];
    const float* x_p      = (const float*)d_in[1];
    const int*   mask     = (const int*)  d_in[2];
    const float* w_ih_c   = (const float*)d_in[3];
    const float* w_hh_c   = (const float*)d_in[4];
    const float* b_ih_c   = (const float*)d_in[5];
    const float* b_hh_c   = (const float*)d_in[6];
    const float* w_ih_p   = (const float*)d_in[7];
    const float* w_hh_p   = (const float*)d_in[8];
    const float* b_ih_p   = (const float*)d_in[9];
    const float* b_hh_p   = (const float*)d_in[10];
    const float* w_query  = (const float*)d_in[11];
    const float* b_query  = (const float*)d_in[12];
    const float* w_bip    = (const float*)d_in[13];
    const float* b_bip    = (const float*)d_in[14];
    const float* w_mlin   = (const float*)d_in[15];
    const float* ddi      = (const float*)d_in[16];
    const float* embed_fp = (const float*)d_in[17];
    const int*   fp       = (const int*)  d_in[18];
    const float* adj      = (const float*)d_in[19];
    const int*   seg      = (const int*)  d_in[20];
    const float* w_g0     = (const float*)d_in[21];
    const float* b_g0     = (const float*)d_in[22];
    const float* w_g1     = (const float*)d_in[23];
    const float* b_g1     = (const float*)d_in[24];
    const float* avgproj  = (const float*)d_in[25];
    const float* w_out    = (const float*)d_in[26];
    const float* b_out    = (const float*)d_in[27];
    const float* ln_g     = (const float*)d_in[28];
    const float* ln_b     = (const float*)d_in[29];
    float* outp = (float*)d_out;

    float *xp, *pat, *query, *v, *hv, *molsumT, *emb, *match, *bip, *wmT, *att, *bbip;
    float *wqT, *wg0T, *wg1T, *wbipT;
    cudaGetSymbolAddress((void**)&xp,      g_xp);
    cudaGetSymbolAddress((void**)&pat,     g_pat);
    cudaGetSymbolAddress((void**)&query,   g_query);
    cudaGetSymbolAddress((void**)&v,       g_v);
    cudaGetSymbolAddress((void**)&hv,      g_hv);
    cudaGetSymbolAddress((void**)&molsumT, g_molsumT);
    cudaGetSymbolAddress((void**)&emb,     g_emb);
    cudaGetSymbolAddress((void**)&match,   g_match);
    cudaGetSymbolAddress((void**)&bip,     g_bip);
    cudaGetSymbolAddress((void**)&wmT,     g_wmT);
    cudaGetSymbolAddress((void**)&att,     g_att);
    cudaGetSymbolAddress((void**)&bbip,    g_bbip);
    cudaGetSymbolAddress((void**)&wqT,     g_wqT);
    cudaGetSymbolAddress((void**)&wg0T,    g_wg0T);
    cudaGetSymbolAddress((void**)&wg1T,    g_wg1T);
    cudaGetSymbolAddress((void**)&wbipT,   g_wbipT);

    const int GEMMF_SMEM = (2 * 128 * 32 + 2 * 64 * 32) * 4;        // 49152
    const int GRU_SMEM   = (48 * 258 + 64 * 256) * 4;               // 115072

    static cudaStream_t s2 = nullptr, s3 = nullptr;
    static cudaEvent_t evFork = nullptr, evJoin2 = nullptr, evJoin3 = nullptr;
    if (!s2) {
        cudaStreamCreateWithFlags(&s2, cudaStreamNonBlocking);
        cudaStreamCreateWithFlags(&s3, cudaStreamNonBlocking);
        cudaEventCreateWithFlags(&evFork, cudaEventDisableTiming);
        cudaEventCreateWithFlags(&evJoin2, cudaEventDisableTiming);
        cudaEventCreateWithFlags(&evJoin3, cudaEventDisableTiming);
        cudaFuncSetAttribute(gemm_f, cudaFuncAttributeMaxDynamicSharedMemorySize, GEMMF_SMEM);
        cudaFuncSetAttribute(gru_persist_kernel, cudaFuncAttributeMaxDynamicSharedMemorySize, GRU_SMEM);
    }

    cudaEventRecord(evFork, 0);
    cudaStreamWaitEvent(s2, evFork, 0);
    cudaStreamWaitEvent(s3, evFork, 0);

    {   // s3: tail-only weight prep
        dim3 blk(32, 8);
        transpose_kernel<<<dim3(8, 16), blk, 0, s3>>>(w_query, wqT, 2 * HH, HH);
        transpose_kernel<<<dim3(16, 8), blk, 0, s3>>>(w_bip,  wbipT, HH, NSUB);
        wprep_kernel<<<(LBL * NSUBP + 255) / 256, 256, 0, s3>>>(w_mlin, ddi, b_bip);
        cudaEventRecord(evJoin3, s3);
    }

    {   // s2: MPNN branch (molstart FIRST — stream-ordered before adj kernels)
        dim3 blk(32, 8);
        molstart_kernel<<<32, 256, 0, s2>>>(seg);
        transpose_kernel<<<dim3(8, 8), blk, 0, s2>>>(w_g0, wg0T, HH, HH);
        transpose_kernel<<<dim3(8, 8), blk, 0, s2>>>(w_g1, wg1T, HH, HH);
        dim3 grid(HH / 64, (NATOMS + 127) / 128);
        // layer 0: hv = relu(embed_fp[fp] @ w_g0 + b_g0)  — gather fused into A
        gemm_f<<<grid, 256, GEMMF_SMEM, s2>>>(embed_fp, wg0T, b_g0, nullptr, hv,
                                              NATOMS, HH, HH, 1, fp);
        adj_kernel<<<NMOL, HH, 0, s2>>>(adj);
        // layer 1: hv = relu(v @ w_g1 + b_g1)
        gemm_f<<<grid, 256, GEMMF_SMEM, s2>>>(v, wg1T, b_g1, nullptr, hv,
                                              NATOMS, HH, HH, 1, nullptr);
        adj_molsum_kernel<<<NMOL, HH, 0, s2>>>(adj);
        // mpnn_emb = avgproj @ molsum  (M=200, N=256, K=600)
        gemm_s<<<dim3(8, 4), 128, 0, s2>>>(avgproj, molsumT, nullptr, nullptr, emb,
                                           LBL, HH, NMOL, 0);
        cudaEventRecord(evJoin2, s2);
    }

    // ---- main stream: prep + input projections (overlap the MPNN branch) ----
    prep_kernel<<<(2 * BB * HH + 255) / 256, 256>>>(mask);
    {
        dim3 grid(768 / 64, 8192 / 128);
        gemm_f<<<grid, 256, GEMMF_SMEM>>>(x_c, w_ih_c, b_ih_c, nullptr, xp,
                                          BB * SS, 3 * HH, II, 0, nullptr);
        gemm_f<<<grid, 256, GEMMF_SMEM>>>(x_p, w_ih_p, b_ih_p, nullptr,
                                          xp + (size_t)BB * SS * 3 * HH,
                                          BB * SS, 3 * HH, II, 0, nullptr);
    }

    // ---- join both side streams BEFORE the persistent GRU (GRU owns the chip) ----
    cudaStreamWaitEvent(0, evJoin2, 0);
    cudaStreamWaitEvent(0, evJoin3, 0);
    gru_persist_kernel<<<dim3(16, 4, 2), 256, GRU_SMEM>>>(w_hh_c, w_hh_p, b_hh_c, b_hh_p);

    // ---- tail (all on main stream — simple chain) ----
    // query = relu(concat) @ w_query + b_query   (M=256, N=256, K=512)
    gemm_s<<<dim3(8, 4), 128>>>(pat, wqT, b_query, nullptr, query, BB, HH, 2 * HH, 0);
    // match = sigmoid(query @ emb^T)   (M=256, N=200, K=256)
    gemm_s<<<dim3(7, 4), 128>>>(query, emb, nullptr, nullptr, match, BB, LBL, HH, 2);
    // x2 + layernorm -> att
    att_kernel<<<BB, 256>>>(w_out, b_out, ln_g, ln_b);
    // bip = query @ w_bip + b_bip  (N padded to 496)
    gemm_s<<<dim3(NSUBP / 32 + 1, 4), 128>>>(query, wbipT, bbip, nullptr, bip,
                                             BB, NSUBP, HH, 0);
    // out = (bip @ wmT^T) * mpnn_att  (K padded to 496)
    gemm_s<<<dim3(7, 4), 128>>>(bip, wmT, nullptr, att, outp, BB, LBL, NSUBP, 0);
}

// round 13
// speedup vs baseline: 2.5080x; 1.0185x over previous
#include <cuda_runtime.h>
#include <cstdint>
#include <cstddef>

// ---------------------------------------------------------------------------
// Problem constants
// ---------------------------------------------------------------------------
#define BB    256      // batch
#define SS    32       // seq len
#define II    128      // input dim
#define HH    256      // hidden
#define LBL   200      // label
#define NSUB  491
#define NSUBP 496      // NSUB padded to multiple of 4 floats
#define NATOMS 8000
#define NMOL  600

// ---------------------------------------------------------------------------
// Scratch (static __device__ — no allocation anywhere)
// ---------------------------------------------------------------------------
__device__ __align__(16) float g_xp[2 * BB * SS * 3 * HH];
__device__ __align__(16) float g_h[2][2 * BB * HH];
__device__ int   g_idxlast[BB];
__device__ int   g_molstart[NMOL + 1];
__device__ int   g_bar[8 * 32];                        // 8 barrier groups, 128B apart
__device__ __align__(16) float g_pat[BB * 2 * HH];     // relu(h_last) written by GRU
__device__ __align__(16) float g_query[BB * HH];
__device__ __align__(16) float g_v[NATOMS * HH];
__device__ __align__(16) float g_hv[NATOMS * HH];
__device__ __align__(16) float g_molsumT[HH * NMOL];   // transposed [H][NMOL]
__device__ __align__(16) float g_emb[LBL * HH];
__device__ __align__(16) float g_match[BB * LBL];
__device__ __align__(16) float g_att[BB * LBL];
__device__ __align__(16) float g_bip[BB * NSUBP];      // padded stride
__device__ __align__(16) float g_wmT[LBL * NSUBP];     // masked weight, transposed+padded
__device__ __align__(16) float g_bbip[NSUBP];          // padded bias
// pre-transposed weights (all fast GEMMs are transB with K-contiguous rows)
__device__ __align__(16) float g_wqT[HH * 2 * HH];     // [256][512]
__device__ __align__(16) float g_wg0T[HH * HH];
__device__ __align__(16) float g_wg1T[HH * HH];
__device__ __align__(16) float g_wbipT[NSUBP * HH];    // [496][256], rows 491..495 zero

// ---------------------------------------------------------------------------
// Helpers
// ---------------------------------------------------------------------------
__device__ __forceinline__ unsigned long long ffma2(unsigned long long a,
                                                    unsigned long long b,
                                                    unsigned long long c) {
#if defined(__CUDA_ARCH__) && (__CUDA_ARCH__ >= 1000)
    unsigned long long d;
    asm("fma.rn.f32x2 %0, %1, %2, %3;" : "=l"(d) : "l"(a), "l"(b), "l"(c));
    return d;
#else
    float2 af = *reinterpret_cast<float2*>(&a);
    float2 bf = *reinterpret_cast<float2*>(&b);
    float2 cf = *reinterpret_cast<float2*>(&c);
    float2 df;
    df.x = fmaf(af.x, bf.x, cf.x);
    df.y = fmaf(af.y, bf.y, cf.y);
    return *reinterpret_cast<unsigned long long*>(&df);
#endif
}

__device__ __forceinline__ unsigned long long lds64(const float* p) {
    return *reinterpret_cast<const unsigned long long*>(p);
}

__device__ __forceinline__ float unpack_sum(unsigned long long u) {
    return __uint_as_float((unsigned)u) + __uint_as_float((unsigned)(u >> 32));
}

__device__ __forceinline__ float sigmoidf_(float x) {
    return 1.f / (1.f + expf(-x));
}

__device__ __forceinline__ void cp16(float* dst, const float* src, bool p) {
    unsigned s = (unsigned)__cvta_generic_to_shared(dst);
    int n = p ? 16 : 0;
    asm volatile("cp.async.ca.shared.global [%0], [%1], 16, %2;"
                 :: "r"(s), "l"(src), "r"(n));
}
__device__ __forceinline__ void cp8(float* dst, const float* src, bool p) {
    unsigned s = (unsigned)__cvta_generic_to_shared(dst);
    int n = p ? 8 : 0;
    asm volatile("cp.async.ca.shared.global [%0], [%1], 8, %2;"
                 :: "r"(s), "l"(src), "r"(n));
}
__device__ __forceinline__ void cp_commit() { asm volatile("cp.async.commit_group;"); }
__device__ __forceinline__ void cp_wait0()  { asm volatile("cp.async.wait_group 0;"); }
__device__ __forceinline__ void cp_wait1()  { asm volatile("cp.async.wait_group 1;"); }

// ---------------------------------------------------------------------------
// Fast GEMM (transB): C[M,N] = act( A[M,K] * B[N,K]^T + bias ) (* mul)
// 128x64 block tile, 256 threads, double-buffered cp.async, f32x2 8x4 tile.
// Optional rowidx: A row gm is read from A[rowidx[gm]] (fused gather).
// ---------------------------------------------------------------------------
__global__ void __launch_bounds__(256, 1)
gemm_f(const float* __restrict__ A, const float* __restrict__ Bm,
       const float* __restrict__ bias, const float* __restrict__ mul,
       float* __restrict__ C, int M, int N, int K, int act,
       const int* __restrict__ rowidx)
{
    extern __shared__ float sm[];
    float* As = sm;                 // [2][128][32]
    float* Bs = sm + 2 * 128 * 32;  // [2][64][32]
    const int tid = threadIdx.x;
    const int tx = tid & 15, ty = tid >> 4;
    const int m0 = blockIdx.y * 128, n0 = blockIdx.x * 64;
    const int nchunks = (K + 31) / 32;

    unsigned long long acc[8][4];
#pragma unroll
    for (int q = 0; q < 8; q++)
#pragma unroll
        for (int p = 0; p < 4; p++) acc[q][p] = 0ull;

    auto stage = [&](int buf, int k0) {
        float* Ab = As + buf * (128 * 32);
        float* Bb = Bs + buf * (64 * 32);
#pragma unroll
        for (int j = 0; j < 4; j++) {
            int idx = tid + 256 * j;
            int r = idx >> 3, kf4 = idx & 7;
            int gm = m0 + r, gk = k0 + kf4 * 4;
            bool pr = (gm < M) && (gk < K);
            int grow = pr ? (rowidx ? rowidx[gm] : gm) : 0;
            const float* src = pr ? (A + (size_t)grow * K + gk) : A;
            cp16(Ab + r * 32 + ((kf4 ^ (r & 7)) << 2), src, pr);
        }
#pragma unroll
        for (int j = 0; j < 2; j++) {
            int idx = tid + 256 * j;
            int r = idx >> 3, kf4 = idx & 7;
            int gn = n0 + r, gk = k0 + kf4 * 4;
            bool pr = (gn < N) && (gk < K);
            const float* src = pr ? (Bm + (size_t)gn * K + gk) : Bm;
            cp16(Bb + r * 32 + ((kf4 ^ (r & 7)) << 2), src, pr);
        }
        cp_commit();
    };

    stage(0, 0);
    int buf = 0;
    for (int c = 0; c < nchunks; c++) {
        cp_wait0();
        __syncthreads();
        if (c + 1 < nchunks) stage(buf ^ 1, (c + 1) * 32);
        const float* Ab = As + buf * (128 * 32);
        const float* Bb = Bs + buf * (64 * 32);
#pragma unroll
        for (int k4 = 0; k4 < 8; k4++) {
            ulonglong2 a[8], b[4];
#pragma unroll
            for (int q = 0; q < 8; q++) {
                int r = ty + 16 * q;
                a[q] = *reinterpret_cast<const ulonglong2*>(
                    Ab + r * 32 + ((k4 ^ (r & 7)) << 2));
            }
#pragma unroll
            for (int p = 0; p < 4; p++) {
                int r = tx + 16 * p;
                b[p] = *reinterpret_cast<const ulonglong2*>(
                    Bb + r * 32 + ((k4 ^ (r & 7)) << 2));
            }
#pragma unroll
            for (int q = 0; q < 8; q++)
#pragma unroll
                for (int p = 0; p < 4; p++) {
                    acc[q][p] = ffma2(a[q].x, b[p].x, acc[q][p]);
                    acc[q][p] = ffma2(a[q].y, b[p].y, acc[q][p]);
                }
        }
        buf ^= 1;
    }

#pragma unroll
    for (int q = 0; q < 8; q++) {
        int gm = m0 + ty + 16 * q;
        if (gm >= M) continue;
#pragma unroll
        for (int p = 0; p < 4; p++) {
            int gn = n0 + tx + 16 * p;
            if (gn >= N) continue;
            float v = unpack_sum(acc[q][p]);
            if (bias) v += bias[gn];
            if (act == 1) v = fmaxf(v, 0.f);
            else if (act == 2) v = sigmoidf_(v);
            if (mul) v *= mul[(size_t)gm * N + gn];
            C[(size_t)gm * N + gn] = v;
        }
    }
}

// ---------------------------------------------------------------------------
// Small-M GEMM (transB): 64x32 block tile, 128 threads. Same contract.
// ---------------------------------------------------------------------------
__global__ void __launch_bounds__(128)
gemm_s(const float* __restrict__ A, const float* __restrict__ Bm,
       const float* __restrict__ bias, const float* __restrict__ mul,
       float* __restrict__ C, int M, int N, int K, int act)
{
    __shared__ float As[2][64 * 32];
    __shared__ float Bs[2][32 * 32];
    const int tid = threadIdx.x;
    const int tx = tid & 7, ty = tid >> 3;          // 8 x 16
    const int m0 = blockIdx.y * 64, n0 = blockIdx.x * 32;
    const int nchunks = (K + 31) / 32;

    unsigned long long acc[4][4];
#pragma unroll
    for (int q = 0; q < 4; q++)
#pragma unroll
        for (int p = 0; p < 4; p++) acc[q][p] = 0ull;

    auto stage = [&](int buf, int k0) {
#pragma unroll
        for (int j = 0; j < 4; j++) {               // A: 512 float4
            int idx = tid + 128 * j;
            int r = idx >> 3, kf4 = idx & 7;
            int gm = m0 + r, gk = k0 + kf4 * 4;
            bool pr = (gm < M) && (gk < K);
            const float* src = pr ? (A + (size_t)gm * K + gk) : A;
            cp16(&As[buf][r * 32 + ((kf4 ^ (r & 7)) << 2)], src, pr);
        }
#pragma unroll
        for (int j = 0; j < 2; j++) {               // B: 256 float4
            int idx = tid + 128 * j;
            int r = idx >> 3, kf4 = idx & 7;
            int gn = n0 + r, gk = k0 + kf4 * 4;
            bool pr = (gn < N) && (gk < K);
            const float* src = pr ? (Bm + (size_t)gn * K + gk) : Bm;
            cp16(&Bs[buf][r * 32 + ((kf4 ^ (r & 7)) << 2)], src, pr);
        }
        cp_commit();
    };

    stage(0, 0);
    int buf = 0;
    for (int c = 0; c < nchunks; c++) {
        cp_wait0();
        __syncthreads();
        if (c + 1 < nchunks) stage(buf ^ 1, (c + 1) * 32);
#pragma unroll
        for (int k4 = 0; k4 < 8; k4++) {
            ulonglong2 a[4], b[4];
#pragma unroll
            for (int q = 0; q < 4; q++) {
                int r = ty + 16 * q;
                a[q] = *reinterpret_cast<const ulonglong2*>(
                    &As[buf][r * 32 + ((k4 ^ (r & 7)) << 2)]);
            }
#pragma unroll
            for (int p = 0; p < 4; p++) {
                int r = tx + 8 * p;
                b[p] = *reinterpret_cast<const ulonglong2*>(
                    &Bs[buf][r * 32 + ((k4 ^ (r & 7)) << 2)]);
            }
#pragma unroll
            for (int q = 0; q < 4; q++)
#pragma unroll
                for (int p = 0; p < 4; p++) {
                    acc[q][p] = ffma2(a[q].x, b[p].x, acc[q][p]);
                    acc[q][p] = ffma2(a[q].y, b[p].y, acc[q][p]);
                }
        }
        buf ^= 1;
    }

#pragma unroll
    for (int q = 0; q < 4; q++) {
        int gm = m0 + ty + 16 * q;
        if (gm >= M) continue;
#pragma unroll
        for (int p = 0; p < 4; p++) {
            int gn = n0 + tx + 8 * p;
            if (gn >= N) continue;
            float v = unpack_sum(acc[q][p]);
            if (bias) v += bias[gn];
            if (act == 1) v = fmaxf(v, 0.f);
            else if (act == 2) v = sigmoidf_(v);
            if (mul) v *= mul[(size_t)gm * N + gn];
            C[(size_t)gm * N + gn] = v;
        }
    }
}

// ---------------------------------------------------------------------------
// Transpose: out[C x R] = in[R x C]^T
// ---------------------------------------------------------------------------
__global__ void transpose_kernel(const float* __restrict__ in, float* __restrict__ out,
                                 int R, int C)
{
    __shared__ float tile[32][33];
    int bx = blockIdx.x * 32, by = blockIdx.y * 32;
    int x = bx + threadIdx.x;
#pragma unroll
    for (int j = 0; j < 32; j += 8) {
        int y = by + threadIdx.y + j;
        if (x < C && y < R) tile[threadIdx.y + j][threadIdx.x] = in[(size_t)y * C + x];
    }
    __syncthreads();
    int x2 = by + threadIdx.x;
#pragma unroll
    for (int j = 0; j < 32; j += 8) {
        int y2 = bx + threadIdx.y + j;
        if (x2 < R && y2 < C) out[(size_t)y2 * R + x2] = tile[threadIdx.x][threadIdx.y + j];
    }
}

// ---------------------------------------------------------------------------
// Main-stream prep: last-visit idx, zero h + barriers
// ---------------------------------------------------------------------------
__global__ void prep_kernel(const int* __restrict__ mask) {
    int i = blockIdx.x * blockDim.x + threadIdx.x;
    if (i < 2 * BB * HH) g_h[0][i] = 0.f;
    if (i < 8 * 32) g_bar[i] = 0;
    if (i < BB) {
        int s = 0;
        for (int j = 0; j < SS; j++) s += mask[i * SS + j];
        g_idxlast[i] = s - 1;
    }
}

// ---------------------------------------------------------------------------
// molstart (runs on s2, stream-ordered before adj kernels)
// ---------------------------------------------------------------------------
__global__ void molstart_kernel(const int* __restrict__ seg) {
    int stride = gridDim.x * blockDim.x;
    for (int i = blockIdx.x * blockDim.x + threadIdx.x; i < NATOMS; i += stride) {
        if (i == 0) {
            g_molstart[seg[0]] = 0;
            g_molstart[NMOL] = NATOMS;
        } else if (seg[i] != seg[i - 1]) {
            g_molstart[seg[i]] = i;
        }
    }
}

// ---------------------------------------------------------------------------
// Merged tail-weight prep: wmT (transposed+padded) + padded bias + wbipT pad rows
// ---------------------------------------------------------------------------
__global__ void wprep_kernel(const float* __restrict__ w_masklin,
                             const float* __restrict__ ddi,
                             const float* __restrict__ b_bip) {
    int idx = blockIdx.x * blockDim.x + threadIdx.x;
    if (idx < LBL * NSUBP) {
        int j = idx / NSUBP, k = idx - j * NSUBP;
        g_wmT[idx] = (k < NSUB) ? w_masklin[k * LBL + j] * ddi[j * NSUB + k] : 0.f;
    }
    if (idx < NSUBP) g_bbip[idx] = (idx < NSUB) ? b_bip[idx] : 0.f;
    if (idx < (NSUBP - NSUB) * HH) g_wbipT[NSUB * HH + idx] = 0.f;
}

// ---------------------------------------------------------------------------
// Persistent GRU: single launch, 32 steps with inter-block barriers.
// Grid (16 colgroups, 4 batchgroups, 2 grus) = 128 blocks, 256 threads.
// h staged in two cp.async groups (K halves) -> first half computes while the
// second half lands. Barrier uses tid0-only release/acquire fences
// (cumulativity via __syncthreads, same pattern as cooperative-groups grid.sync).
// Writes relu(h_last) straight into g_pat (concat layout).
// ---------------------------------------------------------------------------
__global__ void __launch_bounds__(256)
gru_persist_kernel(const float* __restrict__ whh_c, const float* __restrict__ whh_p,
                   const float* __restrict__ bhh_c, const float* __restrict__ bhh_p)
{
    extern __shared__ float sm[];
    float* w_s = sm;                 // [48][258]
    float* h_s = sm + 48 * 258;      // [64][256]
    const int tid = threadIdx.x;
    const int c = tid & 15;
    const int bq = tid >> 4;         // 0..15
    const int g  = blockIdx.z;
    const int c0 = blockIdx.x * 16;
    const int b0 = blockIdx.y * 64;
    const int grp = blockIdx.y + 4 * blockIdx.z;      // 8 barrier groups of 16 blocks
    const float* whh = g ? whh_p : whh_c;
    const float* bhh = g ? bhh_p : bhh_c;
    const int col = c0 + c;

    // stage weights once (its own commit group; absorbed by first wait at t=0)
#pragma unroll
    for (int j = 0; j < 24; j++) {
        int idx = tid + 256 * j;
        int r = idx >> 7, f2 = idx & 127;
        int grow = (r >> 4) * HH + c0 + (r & 15);
        cp8(w_s + r * 258 + f2 * 2, whh + (size_t)grow * HH + f2 * 2, true);
    }
    cp_commit();

    const float bh_r = bhh[col];
    const float bh_z = bhh[HH + col];
    const float bh_n = bhh[2 * HH + col];
    const int idxl[4] = {g_idxlast[b0 + bq], g_idxlast[b0 + bq + 16],
                         g_idxlast[b0 + bq + 32], g_idxlast[b0 + bq + 48]};

    for (int t = 0; t < SS; t++) {
        const float* hsrc = g_h[t & 1] + g * (BB * HH);
        // stage h in two halves: K[0:128) group A, K[128:256) group B
#pragma unroll
        for (int j = 0; j < 8; j++) {
            int idx = tid + 256 * j;
            int r = idx >> 5, f4 = idx & 31;
            cp16(h_s + r * 256 + f4 * 4, hsrc + (b0 + r) * HH + f4 * 4, true);
        }
        cp_commit();                                   // group A
#pragma unroll
        for (int j = 0; j < 8; j++) {
            int idx = tid + 256 * j;
            int r = idx >> 5, f4 = idx & 31;
            cp16(h_s + r * 256 + 128 + f4 * 4,
                 hsrc + (b0 + r) * HH + 128 + f4 * 4, true);
        }
        cp_commit();                                   // group B

        // prefetch xp into regs while copies fly
        float xr[4][3];
#pragma unroll
        for (int i = 0; i < 4; i++) {
            int b = b0 + bq + 16 * i;
            const float* xp = g_xp + ((size_t)g * BB * SS + (size_t)b * SS + t) * (3 * HH);
            xr[i][0] = __ldg(xp + col);
            xr[i][1] = __ldg(xp + HH + col);
            xr[i][2] = __ldg(xp + 2 * HH + col);
        }

        unsigned long long acc[4][3];
#pragma unroll
        for (int i = 0; i < 4; i++)
#pragma unroll
            for (int gt = 0; gt < 3; gt++) acc[i][gt] = 0ull;

        cp_wait1();                                    // group A (and weights at t=0)
        __syncthreads();

        // first K half: k2 0..63
#pragma unroll 8
        for (int k2 = 0; k2 < 64; k2++) {
            unsigned long long h2[4], w2[3];
#pragma unroll
            for (int i = 0; i < 4; i++)
                h2[i] = lds64(h_s + (bq + 16 * i) * 256 + 2 * k2);
#pragma unroll
            for (int gt = 0; gt < 3; gt++)
                w2[gt] = lds64(w_s + (gt * 16 + c) * 258 + 2 * k2);
#pragma unroll
            for (int i = 0; i < 4; i++)
#pragma unroll
                for (int gt = 0; gt < 3; gt++)
                    acc[i][gt] = ffma2(h2[i], w2[gt], acc[i][gt]);
        }

        cp_wait0();                                    // group B
        __syncthreads();

        // second K half: k2 64..127
#pragma unroll 8
        for (int k2 = 64; k2 < 128; k2++) {
            unsigned long long h2[4], w2[3];
#pragma unroll
            for (int i = 0; i < 4; i++)
                h2[i] = lds64(h_s + (bq + 16 * i) * 256 + 2 * k2);
#pragma unroll
            for (int gt = 0; gt < 3; gt++)
                w2[gt] = lds64(w_s + (gt * 16 + c) * 258 + 2 * k2);
#pragma unroll
            for (int i = 0; i < 4; i++)
#pragma unroll
                for (int gt = 0; gt < 3; gt++)
                    acc[i][gt] = ffma2(h2[i], w2[gt], acc[i][gt]);
        }

        float* hdst = g_h[(t + 1) & 1] + g * (BB * HH);
#pragma unroll
        for (int i = 0; i < 4; i++) {
            int b = b0 + bq + 16 * i;
            float hr = unpack_sum(acc[i][0]) + bh_r;
            float hz = unpack_sum(acc[i][1]) + bh_z;
            float hn = unpack_sum(acc[i][2]) + bh_n;
            float r = sigmoidf_(xr[i][0] + hr);
            float z = sigmoidf_(xr[i][1] + hz);
            float n = tanhf(xr[i][2] + r * hn);
            float hp = h_s[(bq + 16 * i) * 256 + col];
            float hnew = (1.f - z) * n + z * hp;
            hdst[b * HH + col] = hnew;
            if (t == idxl[i])
                g_pat[b * (2 * HH) + g * HH + col] = fmaxf(hnew, 0.f);
        }

        if (t + 1 < SS) {
            __syncthreads();                       // block stores happen-before tid0
            if (tid == 0) {
                __threadfence();                   // release (cumulative)
                atomicAdd(&g_bar[grp * 32], 1);
                int tgt = 16 * (t + 1);
                while (*(volatile int*)&g_bar[grp * 32] < tgt) {
                    __nanosleep(64);
                }
                __threadfence();                   // acquire
            }
            __syncthreads();                       // tid0 observation extends to block
        }
    }
}

// ---------------------------------------------------------------------------
// Block-diagonal adjacency pass 1: v = hv + adj_block @ hv (per molecule)
// ---------------------------------------------------------------------------
__global__ void adj_kernel(const float* __restrict__ adj) {
    int m = blockIdx.x, tid = threadIdx.x;
    int s = g_molstart[m], e = g_molstart[m + 1];
    int na = e - s;
    __shared__ float hs[14][HH];
    __shared__ float as[14][14];
    for (int a = 0; a < na; a++) hs[a][tid] = g_hv[(s + a) * HH + tid];
    for (int idx = tid; idx < na * na; idx += 256) {
        int i = idx / na, j = idx - i * na;
        as[i][j] = adj[(size_t)(s + i) * NATOMS + (s + j)];
    }
    __syncthreads();
    for (int i = 0; i < na; i++) {
        float acc = hs[i][tid];
        for (int j = 0; j < na; j++) acc = fmaf(as[i][j], hs[j][tid], acc);
        g_v[(s + i) * HH + tid] = acc;
    }
}

// ---------------------------------------------------------------------------
// Fused adjacency pass 2 + segment sum -> molsumT [H][NMOL]
// ---------------------------------------------------------------------------
__global__ void adj_molsum_kernel(const float* __restrict__ adj) {
    int m = blockIdx.x, tid = threadIdx.x;
    int s = g_molstart[m], e = g_molstart[m + 1];
    int na = e - s;
    __shared__ float hs[14][HH];
    __shared__ float as[14][14];
    for (int a = 0; a < na; a++) hs[a][tid] = g_hv[(s + a) * HH + tid];
    for (int idx = tid; idx < na * na; idx += 256) {
        int i = idx / na, j = idx - i * na;
        as[i][j] = adj[(size_t)(s + i) * NATOMS + (s + j)];
    }
    __syncthreads();
    float sum = 0.f;
    for (int i = 0; i < na; i++) {
        float acc = hs[i][tid];
        for (int j = 0; j < na; j++) acc = fmaf(as[i][j], hs[j][tid], acc);
        sum += acc;
    }
    g_molsumT[tid * NMOL + m] = sum;
}

// ---------------------------------------------------------------------------
// x2 = match + match @ w_out + b_out; layernorm -> g_att
// ---------------------------------------------------------------------------
__global__ void att_kernel(const float* __restrict__ w_out, const float* __restrict__ b_out,
                           const float* __restrict__ gamma, const float* __restrict__ beta)
{
    int b = blockIdx.x, tid = threadIdx.x;
    __shared__ float mrow[LBL];
    __shared__ float red[256];
    if (tid < LBL) mrow[tid] = g_match[b * LBL + tid];
    __syncthreads();
    float x2 = 0.f;
    if (tid < LBL) {
        float acc = 0.f;
        for (int k = 0; k < LBL; k++) acc = fmaf(mrow[k], w_out[k * LBL + tid], acc);
        x2 = mrow[tid] + acc + b_out[tid];
    }
    red[tid] = (tid < LBL) ? x2 : 0.f;
    __syncthreads();
    for (int s2 = 128; s2 > 0; s2 >>= 1) {
        if (tid < s2) red[tid] += red[tid + s2];
        __syncthreads();
    }
    float mean = red[0] * (1.f / LBL);
    __syncthreads();
    float d = x2 - mean;
    red[tid] = (tid < LBL) ? d * d : 0.f;
    __syncthreads();
    for (int s2 = 128; s2 > 0; s2 >>= 1) {
        if (tid < s2) red[tid] += red[tid + s2];
        __syncthreads();
    }
    float var = red[0] * (1.f / LBL);
    if (tid < LBL)
        g_att[b * LBL + tid] = d * rsqrtf(var + 1e-5f) * gamma[tid] + beta[tid];
}

// ---------------------------------------------------------------------------
// Launch orchestration
// ---------------------------------------------------------------------------
extern "C" void kernel_launch(void* const* d_in, const int* in_sizes, int n_in,
                              void* d_out, int out_size) {
    const float* x_c      = (const float*)d_in[0];
    const float* x_p      = (const float*)d_in[1];
    const int*   mask     = (const int*)  d_in[2];
    const float* w_ih_c   = (const float*)d_in[3];
    const float* w_hh_c   = (const float*)d_in[4];
    const float* b_ih_c   = (const float*)d_in[5];
    const float* b_hh_c   = (const float*)d_in[6];
    const float* w_ih_p   = (const float*)d_in[7];
    const float* w_hh_p   = (const float*)d_in[8];
    const float* b_ih_p   = (const float*)d_in[9];
    const float* b_hh_p   = (const float*)d_in[10];
    const float* w_query  = (const float*)d_in[11];
    const float* b_query  = (const float*)d_in[12];
    const float* w_bip    = (const float*)d_in[13];
    const float* b_bip    = (const float*)d_in[14];
    const float* w_mlin   = (const float*)d_in[15];
    const float* ddi      = (const float*)d_in[16];
    const float* embed_fp = (const float*)d_in[17];
    const int*   fp       = (const int*)  d_in[18];
    const float* adj      = (const float*)d_in[19];
    const int*   seg      = (const int*)  d_in[20];
    const float* w_g0     = (const float*)d_in[21];
    const float* b_g0     = (const float*)d_in[22];
    const float* w_g1     = (const float*)d_in[23];
    const float* b_g1     = (const float*)d_in[24];
    const float* avgproj  = (const float*)d_in[25];
    const float* w_out    = (const float*)d_in[26];
    const float* b_out    = (const float*)d_in[27];
    const float* ln_g     = (const float*)d_in[28];
    const float* ln_b     = (const float*)d_in[29];
    float* outp = (float*)d_out;

    float *xp, *pat, *query, *v, *hv, *molsumT, *emb, *match, *bip, *wmT, *att, *bbip;
    float *wqT, *wg0T, *wg1T, *wbipT;
    cudaGetSymbolAddress((void**)&xp,      g_xp);
    cudaGetSymbolAddress((void**)&pat,     g_pat);
    cudaGetSymbolAddress((void**)&query,   g_query);
    cudaGetSymbolAddress((void**)&v,       g_v);
    cudaGetSymbolAddress((void**)&hv,      g_hv);
    cudaGetSymbolAddress((void**)&molsumT, g_molsumT);
    cudaGetSymbolAddress((void**)&emb,     g_emb);
    cudaGetSymbolAddress((void**)&match,   g_match);
    cudaGetSymbolAddress((void**)&bip,     g_bip);
    cudaGetSymbolAddress((void**)&wmT,     g_wmT);
    cudaGetSymbolAddress((void**)&att,     g_att);
    cudaGetSymbolAddress((void**)&bbip,    g_bbip);
    cudaGetSymbolAddress((void**)&wqT,     g_wqT);
    cudaGetSymbolAddress((void**)&wg0T,    g_wg0T);
    cudaGetSymbolAddress((void**)&wg1T,    g_wg1T);
    cudaGetSymbolAddress((void**)&wbipT,   g_wbipT);

    const int GEMMF_SMEM = (2 * 128 * 32 + 2 * 64 * 32) * 4;        // 49152
    const int GRU_SMEM   = (48 * 258 + 64 * 256) * 4;               // 115072

    static cudaStream_t s2 = nullptr, s3 = nullptr;
    static cudaEvent_t evFork = nullptr, evJoin2 = nullptr, evJoin3 = nullptr;
    if (!s2) {
        cudaStreamCreateWithFlags(&s2, cudaStreamNonBlocking);
        cudaStreamCreateWithFlags(&s3, cudaStreamNonBlocking);
        cudaEventCreateWithFlags(&evFork, cudaEventDisableTiming);
        cudaEventCreateWithFlags(&evJoin2, cudaEventDisableTiming);
        cudaEventCreateWithFlags(&evJoin3, cudaEventDisableTiming);
        cudaFuncSetAttribute(gemm_f, cudaFuncAttributeMaxDynamicSharedMemorySize, GEMMF_SMEM);
        cudaFuncSetAttribute(gru_persist_kernel, cudaFuncAttributeMaxDynamicSharedMemorySize, GRU_SMEM);
    }

    cudaEventRecord(evFork, 0);
    cudaStreamWaitEvent(s2, evFork, 0);
    cudaStreamWaitEvent(s3, evFork, 0);

    {   // s3: tail-only weight prep
        dim3 blk(32, 8);
        transpose_kernel<<<dim3(8, 16), blk, 0, s3>>>(w_query, wqT, 2 * HH, HH);
        transpose_kernel<<<dim3(16, 8), blk, 0, s3>>>(w_bip,  wbipT, HH, NSUB);
        wprep_kernel<<<(LBL * NSUBP + 255) / 256, 256, 0, s3>>>(w_mlin, ddi, b_bip);
        cudaEventRecord(evJoin3, s3);
    }

    {   // s2: MPNN branch (molstart FIRST — stream-ordered before adj kernels)
        dim3 blk(32, 8);
        molstart_kernel<<<32, 256, 0, s2>>>(seg);
        transpose_kernel<<<dim3(8, 8), blk, 0, s2>>>(w_g0, wg0T, HH, HH);
        transpose_kernel<<<dim3(8, 8), blk, 0, s2>>>(w_g1, wg1T, HH, HH);
        dim3 grid(HH / 64, (NATOMS + 127) / 128);
        // layer 0: hv = relu(embed_fp[fp] @ w_g0 + b_g0)  — gather fused into A
        gemm_f<<<grid, 256, GEMMF_SMEM, s2>>>(embed_fp, wg0T, b_g0, nullptr, hv,
                                              NATOMS, HH, HH, 1, fp);
        adj_kernel<<<NMOL, HH, 0, s2>>>(adj);
        // layer 1: hv = relu(v @ w_g1 + b_g1)
        gemm_f<<<grid, 256, GEMMF_SMEM, s2>>>(v, wg1T, b_g1, nullptr, hv,
                                              NATOMS, HH, HH, 1, nullptr);
        adj_molsum_kernel<<<NMOL, HH, 0, s2>>>(adj);
        // mpnn_emb = avgproj @ molsum  (M=200, N=256, K=600)
        gemm_s<<<dim3(8, 4), 128, 0, s2>>>(avgproj, molsumT, nullptr, nullptr, emb,
                                           LBL, HH, NMOL, 0);
        cudaEventRecord(evJoin2, s2);
    }

    // ---- main stream: prep + input projections (overlap the MPNN branch) ----
    prep_kernel<<<(2 * BB * HH + 255) / 256, 256>>>(mask);
    {
        dim3 grid(768 / 64, 8192 / 128);
        gemm_f<<<grid, 256, GEMMF_SMEM>>>(x_c, w_ih_c, b_ih_c, nullptr, xp,
                                          BB * SS, 3 * HH, II, 0, nullptr);
        gemm_f<<<grid, 256, GEMMF_SMEM>>>(x_p, w_ih_p, b_ih_p, nullptr,
                                          xp + (size_t)BB * SS * 3 * HH,
                                          BB * SS, 3 * HH, II, 0, nullptr);
    }

    // ---- join both side streams BEFORE the persistent GRU (GRU owns the chip) ----
    cudaStreamWaitEvent(0, evJoin2, 0);
    cudaStreamWaitEvent(0, evJoin3, 0);
    gru_persist_kernel<<<dim3(16, 4, 2), 256, GRU_SMEM>>>(w_hh_c, w_hh_p, b_hh_c, b_hh_p);

    // ---- tail (all on main stream — simple chain) ----
    // query = relu(concat) @ w_query + b_query   (M=256, N=256, K=512)
    gemm_s<<<dim3(8, 4), 128>>>(pat, wqT, b_query, nullptr, query, BB, HH, 2 * HH, 0);
    // match = sigmoid(query @ emb^T)   (M=256, N=200, K=256)
    gemm_s<<<dim3(7, 4), 128>>>(query, emb, nullptr, nullptr, match, BB, LBL, HH, 2);
    // x2 + layernorm -> att
    att_kernel<<<BB, 256>>>(w_out, b_out, ln_g, ln_b);
    // bip = query @ w_bip + b_bip  (N padded to 496)
    gemm_s<<<dim3(NSUBP / 32 + 1, 4), 128>>>(query, wbipT, bbip, nullptr, bip,
                                             BB, NSUBP, HH, 0);
    // out = (bip @ wmT^T) * mpnn_att  (K padded to 496)
    gemm_s<<<dim3(7, 4), 128>>>(bip, wmT, nullptr, att, outp, BB, LBL, NSUBP, 0);
}

// round 15
// speedup vs baseline: 2.5690x; 1.0243x over previous
#include <cuda_runtime.h>
#include <cstdint>
#include <cstddef>

// ---------------------------------------------------------------------------
// Problem constants
// ---------------------------------------------------------------------------
#define BB    256      // batch
#define SS    32       // seq len
#define II    128      // input dim
#define HH    256      // hidden
#define LBL   200      // label
#define NSUB  491
#define NSUBP 496      // NSUB padded to multiple of 4 floats
#define NATOMS 8000
#define NMOL  600

// ---------------------------------------------------------------------------
// Scratch (static __device__ — no allocation anywhere)
// ---------------------------------------------------------------------------
__device__ __align__(16) float g_xp[2 * BB * SS * 3 * HH];
__device__ __align__(16) float g_h[2][2 * BB * HH];
__device__ int   g_idxlast[BB];
__device__ int   g_molstart[NMOL + 1];
__device__ int   g_bar[8 * 32];                        // 8 barrier groups, 128B apart
__device__ __align__(16) float g_pat[BB * 2 * HH];     // relu(h_last) written by GRU
__device__ __align__(16) float g_query[BB * HH];
__device__ __align__(16) float g_v[NATOMS * HH];
__device__ __align__(16) float g_hv[NATOMS * HH];
__device__ __align__(16) float g_molsumT[HH * NMOL];   // transposed [H][NMOL]
__device__ __align__(16) float g_emb[LBL * HH];
__device__ __align__(16) float g_match[BB * LBL];
__device__ __align__(16) float g_att[BB * LBL];
__device__ __align__(16) float g_bip[BB * NSUBP];      // padded stride
__device__ __align__(16) float g_wmT[LBL * NSUBP];     // masked weight, transposed+padded
__device__ __align__(16) float g_bbip[NSUBP];          // padded bias
// pre-transposed weights (all fast GEMMs are transB with K-contiguous rows)
__device__ __align__(16) float g_wqT[HH * 2 * HH];     // [256][512]
__device__ __align__(16) float g_wg0T[HH * HH];
__device__ __align__(16) float g_wg1T[HH * HH];
__device__ __align__(16) float g_wbipT[NSUBP * HH];    // [496][256], rows 491..495 zero

// ---------------------------------------------------------------------------
// Helpers
// ---------------------------------------------------------------------------
__device__ __forceinline__ unsigned long long ffma2(unsigned long long a,
                                                    unsigned long long b,
                                                    unsigned long long c) {
#if defined(__CUDA_ARCH__) && (__CUDA_ARCH__ >= 1000)
    unsigned long long d;
    asm("fma.rn.f32x2 %0, %1, %2, %3;" : "=l"(d) : "l"(a), "l"(b), "l"(c));
    return d;
#else
    float2 af = *reinterpret_cast<float2*>(&a);
    float2 bf = *reinterpret_cast<float2*>(&b);
    float2 cf = *reinterpret_cast<float2*>(&c);
    float2 df;
    df.x = fmaf(af.x, bf.x, cf.x);
    df.y = fmaf(af.y, bf.y, cf.y);
    return *reinterpret_cast<unsigned long long*>(&df);
#endif
}

__device__ __forceinline__ unsigned long long lds64(const float* p) {
    return *reinterpret_cast<const unsigned long long*>(p);
}

__device__ __forceinline__ float unpack_sum(unsigned long long u) {
    return __uint_as_float((unsigned)u) + __uint_as_float((unsigned)(u >> 32));
}

__device__ __forceinline__ float sigmoidf_(float x) {
    return 1.f / (1.f + expf(-x));
}

__device__ __forceinline__ void cp16(float* dst, const float* src, bool p) {
    unsigned s = (unsigned)__cvta_generic_to_shared(dst);
    int n = p ? 16 : 0;
    asm volatile("cp.async.ca.shared.global [%0], [%1], 16, %2;"
                 :: "r"(s), "l"(src), "r"(n));
}
__device__ __forceinline__ void cp8(float* dst, const float* src, bool p) {
    unsigned s = (unsigned)__cvta_generic_to_shared(dst);
    int n = p ? 8 : 0;
    asm volatile("cp.async.ca.shared.global [%0], [%1], 8, %2;"
                 :: "r"(s), "l"(src), "r"(n));
}
__device__ __forceinline__ void cp_commit() { asm volatile("cp.async.commit_group;"); }
__device__ __forceinline__ void cp_wait0()  { asm volatile("cp.async.wait_group 0;"); }
__device__ __forceinline__ void cp_wait1()  { asm volatile("cp.async.wait_group 1;"); }

// ===========================================================================
// GEMM core (transB): acc += A-tile * B-tile^T, shared by all GEMM kernels.
// ===========================================================================

// ---------------------------------------------------------------------------
// Fast GEMM (transB): C[M,N] = act( A[M,K] * B[N,K]^T + bias )
// 128x64 block tile, 256 threads, double-buffered cp.async, f32x2 8x4 tile.
// Optional rowidx: A row gm is read from A[rowidx[gm]] (fused gather).
// ---------------------------------------------------------------------------
__global__ void __launch_bounds__(256, 1)
gemm_f(const float* __restrict__ A, const float* __restrict__ Bm,
       const float* __restrict__ bias,
       float* __restrict__ C, int M, int N, int K, int act,
       const int* __restrict__ rowidx)
{
    extern __shared__ float sm[];
    float* As = sm;                 // [2][128][32]
    float* Bs = sm + 2 * 128 * 32;  // [2][64][32]
    const int tid = threadIdx.x;
    const int tx = tid & 15, ty = tid >> 4;
    const int m0 = blockIdx.y * 128, n0 = blockIdx.x * 64;
    const int nchunks = (K + 31) / 32;

    unsigned long long acc[8][4];
#pragma unroll
    for (int q = 0; q < 8; q++)
#pragma unroll
        for (int p = 0; p < 4; p++) acc[q][p] = 0ull;

    auto stage = [&](int buf, int k0) {
        float* Ab = As + buf * (128 * 32);
        float* Bb = Bs + buf * (64 * 32);
#pragma unroll
        for (int j = 0; j < 4; j++) {
            int idx = tid + 256 * j;
            int r = idx >> 3, kf4 = idx & 7;
            int gm = m0 + r, gk = k0 + kf4 * 4;
            bool pr = (gm < M) && (gk < K);
            int grow = pr ? (rowidx ? rowidx[gm] : gm) : 0;
            const float* src = pr ? (A + (size_t)grow * K + gk) : A;
            cp16(Ab + r * 32 + ((kf4 ^ (r & 7)) << 2), src, pr);
        }
#pragma unroll
        for (int j = 0; j < 2; j++) {
            int idx = tid + 256 * j;
            int r = idx >> 3, kf4 = idx & 7;
            int gn = n0 + r, gk = k0 + kf4 * 4;
            bool pr = (gn < N) && (gk < K);
            const float* src = pr ? (Bm + (size_t)gn * K + gk) : Bm;
            cp16(Bb + r * 32 + ((kf4 ^ (r & 7)) << 2), src, pr);
        }
        cp_commit();
    };

    stage(0, 0);
    int buf = 0;
    for (int c = 0; c < nchunks; c++) {
        cp_wait0();
        __syncthreads();
        if (c + 1 < nchunks) stage(buf ^ 1, (c + 1) * 32);
        const float* Ab = As + buf * (128 * 32);
        const float* Bb = Bs + buf * (64 * 32);
#pragma unroll
        for (int k4 = 0; k4 < 8; k4++) {
            ulonglong2 a[8], b[4];
#pragma unroll
            for (int q = 0; q < 8; q++) {
                int r = ty + 16 * q;
                a[q] = *reinterpret_cast<const ulonglong2*>(
                    Ab + r * 32 + ((k4 ^ (r & 7)) << 2));
            }
#pragma unroll
            for (int p = 0; p < 4; p++) {
                int r = tx + 16 * p;
                b[p] = *reinterpret_cast<const ulonglong2*>(
                    Bb + r * 32 + ((k4 ^ (r & 7)) << 2));
            }
#pragma unroll
            for (int q = 0; q < 8; q++)
#pragma unroll
                for (int p = 0; p < 4; p++) {
                    acc[q][p] = ffma2(a[q].x, b[p].x, acc[q][p]);
                    acc[q][p] = ffma2(a[q].y, b[p].y, acc[q][p]);
                }
        }
        buf ^= 1;
    }

#pragma unroll
    for (int q = 0; q < 8; q++) {
        int gm = m0 + ty + 16 * q;
        if (gm >= M) continue;
#pragma unroll
        for (int p = 0; p < 4; p++) {
            int gn = n0 + tx + 16 * p;
            if (gn >= N) continue;
            float v = unpack_sum(acc[q][p]);
            if (bias) v += bias[gn];
            if (act == 1) v = fmaxf(v, 0.f);
            C[(size_t)gm * N + gn] = v;
        }
    }
}

// ---------------------------------------------------------------------------
// Both GRU input projections in ONE launch: z selects (x, w, b, out).
// xp_z = x_z @ w_ih_z^T + b_ih_z    (M=8192, N=768, K=128)
// ---------------------------------------------------------------------------
__global__ void __launch_bounds__(256, 1)
gemm_proj(const float* __restrict__ A0, const float* __restrict__ A1,
          const float* __restrict__ B0, const float* __restrict__ B1,
          const float* __restrict__ bias0, const float* __restrict__ bias1,
          float* __restrict__ C0, float* __restrict__ C1)
{
    const int M = BB * SS, N = 3 * HH, K = II;
    const float* A    = blockIdx.z ? A1 : A0;
    const float* Bm   = blockIdx.z ? B1 : B0;
    const float* bias = blockIdx.z ? bias1 : bias0;
    float* C          = blockIdx.z ? C1 : C0;

    extern __shared__ float sm[];
    float* As = sm;
    float* Bs = sm + 2 * 128 * 32;
    const int tid = threadIdx.x;
    const int tx = tid & 15, ty = tid >> 4;
    const int m0 = blockIdx.y * 128, n0 = blockIdx.x * 64;
    const int nchunks = K / 32;   // 4

    unsigned long long acc[8][4];
#pragma unroll
    for (int q = 0; q < 8; q++)
#pragma unroll
        for (int p = 0; p < 4; p++) acc[q][p] = 0ull;

    auto stage = [&](int buf, int k0) {
        float* Ab = As + buf * (128 * 32);
        float* Bb = Bs + buf * (64 * 32);
#pragma unroll
        for (int j = 0; j < 4; j++) {
            int idx = tid + 256 * j;
            int r = idx >> 3, kf4 = idx & 7;
            cp16(Ab + r * 32 + ((kf4 ^ (r & 7)) << 2),
                 A + (size_t)(m0 + r) * K + k0 + kf4 * 4, true);
        }
#pragma unroll
        for (int j = 0; j < 2; j++) {
            int idx = tid + 256 * j;
            int r = idx >> 3, kf4 = idx & 7;
            cp16(Bb + r * 32 + ((kf4 ^ (r & 7)) << 2),
                 Bm + (size_t)(n0 + r) * K + k0 + kf4 * 4, true);
        }
        cp_commit();
    };

    stage(0, 0);
    int buf = 0;
    for (int c = 0; c < nchunks; c++) {
        cp_wait0();
        __syncthreads();
        if (c + 1 < nchunks) stage(buf ^ 1, (c + 1) * 32);
        const float* Ab = As + buf * (128 * 32);
        const float* Bb = Bs + buf * (64 * 32);
#pragma unroll
        for (int k4 = 0; k4 < 8; k4++) {
            ulonglong2 a[8], b[4];
#pragma unroll
            for (int q = 0; q < 8; q++) {
                int r = ty + 16 * q;
                a[q] = *reinterpret_cast<const ulonglong2*>(
                    Ab + r * 32 + ((k4 ^ (r & 7)) << 2));
            }
#pragma unroll
            for (int p = 0; p < 4; p++) {
                int r = tx + 16 * p;
                b[p] = *reinterpret_cast<const ulonglong2*>(
                    Bb + r * 32 + ((k4 ^ (r & 7)) << 2));
            }
#pragma unroll
            for (int q = 0; q < 8; q++)
#pragma unroll
                for (int p = 0; p < 4; p++) {
                    acc[q][p] = ffma2(a[q].x, b[p].x, acc[q][p]);
                    acc[q][p] = ffma2(a[q].y, b[p].y, acc[q][p]);
                }
        }
        buf ^= 1;
    }

#pragma unroll
    for (int q = 0; q < 8; q++) {
        int gm = m0 + ty + 16 * q;
#pragma unroll
        for (int p = 0; p < 4; p++) {
            int gn = n0 + tx + 16 * p;
            C[(size_t)gm * N + gn] = unpack_sum(acc[q][p]) + bias[gn];
        }
    }
}

// ---------------------------------------------------------------------------
// Small-M GEMM (transB): 64x32 block tile, 128 threads.
//   mul: optional elementwise multiplier on the output.
// ---------------------------------------------------------------------------
__global__ void __launch_bounds__(128)
gemm_s(const float* __restrict__ A, const float* __restrict__ Bm,
       const float* __restrict__ bias, const float* __restrict__ mul,
       float* __restrict__ C, int M, int N, int K, int act)
{
    __shared__ float As[2][64 * 32];
    __shared__ float Bs[2][32 * 32];
    const int tid = threadIdx.x;
    const int tx = tid & 7, ty = tid >> 3;
    const int m0 = blockIdx.y * 64, n0 = blockIdx.x * 32;
    if (n0 >= N) return;
    const int nchunks = (K + 31) / 32;

    unsigned long long acc[4][4];
#pragma unroll
    for (int q = 0; q < 4; q++)
#pragma unroll
        for (int p = 0; p < 4; p++) acc[q][p] = 0ull;

    auto stage = [&](int buf, int k0) {
#pragma unroll
        for (int j = 0; j < 4; j++) {
            int idx = tid + 128 * j;
            int r = idx >> 3, kf4 = idx & 7;
            int gm = m0 + r, gk = k0 + kf4 * 4;
            bool pr = (gm < M) && (gk < K);
            const float* src = pr ? (A + (size_t)gm * K + gk) : A;
            cp16(&As[buf][r * 32 + ((kf4 ^ (r & 7)) << 2)], src, pr);
        }
#pragma unroll
        for (int j = 0; j < 2; j++) {
            int idx = tid + 128 * j;
            int r = idx >> 3, kf4 = idx & 7;
            int gn = n0 + r, gk = k0 + kf4 * 4;
            bool pr = (gn < N) && (gk < K);
            const float* src = pr ? (Bm + (size_t)gn * K + gk) : Bm;
            cp16(&Bs[buf][r * 32 + ((kf4 ^ (r & 7)) << 2)], src, pr);
        }
        cp_commit();
    };

    stage(0, 0);
    int buf = 0;
    for (int c = 0; c < nchunks; c++) {
        cp_wait0();
        __syncthreads();
        if (c + 1 < nchunks) stage(buf ^ 1, (c + 1) * 32);
#pragma unroll
        for (int k4 = 0; k4 < 8; k4++) {
            ulonglong2 a[4], b[4];
#pragma unroll
            for (int q = 0; q < 4; q++) {
                int r = ty + 16 * q;
                a[q] = *reinterpret_cast<const ulonglong2*>(
                    &As[buf][r * 32 + ((k4 ^ (r & 7)) << 2)]);
            }
#pragma unroll
            for (int p = 0; p < 4; p++) {
                int r = tx + 8 * p;
                b[p] = *reinterpret_cast<const ulonglong2*>(
                    &Bs[buf][r * 32 + ((k4 ^ (r & 7)) << 2)]);
            }
#pragma unroll
            for (int q = 0; q < 4; q++)
#pragma unroll
                for (int p = 0; p < 4; p++) {
                    acc[q][p] = ffma2(a[q].x, b[p].x, acc[q][p]);
                    acc[q][p] = ffma2(a[q].y, b[p].y, acc[q][p]);
                }
        }
        buf ^= 1;
    }

#pragma unroll
    for (int q = 0; q < 4; q++) {
        int gm = m0 + ty + 16 * q;
        if (gm >= M) continue;
#pragma unroll
        for (int p = 0; p < 4; p++) {
            int gn = n0 + tx + 8 * p;
            if (gn >= N) continue;
            float v = unpack_sum(acc[q][p]);
            if (bias) v += bias[gn];
            if (act == 1) v = fmaxf(v, 0.f);
            else if (act == 2) v = sigmoidf_(v);
            if (mul) v *= mul[(size_t)gm * N + gn];
            C[(size_t)gm * N + gn] = v;
        }
    }
}

// ---------------------------------------------------------------------------
// Merged tail pair (both consume g_query):
//   z=0: match = sigmoid(query @ emb^T)          (N=200)
//   z=1: bip   = query @ wbipT^T + bbip          (N=496)
// Grid (16, 4, 2); blocks beyond N return early.
// ---------------------------------------------------------------------------
__global__ void __launch_bounds__(128)
gemm_tail2()
{
    const int z = blockIdx.z;
    const float* Bm   = z ? g_wbipT : g_emb;
    const float* bias = z ? g_bbip  : nullptr;
    float* C          = z ? g_bip   : g_match;
    const int N       = z ? NSUBP   : LBL;
    const int act     = z ? 0       : 2;
    const int M = BB, K = HH;

    __shared__ float As[2][64 * 32];
    __shared__ float Bs[2][32 * 32];
    const int tid = threadIdx.x;
    const int tx = tid & 7, ty = tid >> 3;
    const int m0 = blockIdx.y * 64, n0 = blockIdx.x * 32;
    if (n0 >= N) return;
    const int nchunks = K / 32;

    unsigned long long acc[4][4];
#pragma unroll
    for (int q = 0; q < 4; q++)
#pragma unroll
        for (int p = 0; p < 4; p++) acc[q][p] = 0ull;

    auto stage = [&](int buf, int k0) {
#pragma unroll
        for (int j = 0; j < 4; j++) {
            int idx = tid + 128 * j;
            int r = idx >> 3, kf4 = idx & 7;
            cp16(&As[buf][r * 32 + ((kf4 ^ (r & 7)) << 2)],
                 g_query + (size_t)(m0 + r) * K + k0 + kf4 * 4, true);
        }
#pragma unroll
        for (int j = 0; j < 2; j++) {
            int idx = tid + 128 * j;
            int r = idx >> 3, kf4 = idx & 7;
            int gn = n0 + r;
            bool pr = (gn < N);
            const float* src = pr ? (Bm + (size_t)gn * K + k0 + kf4 * 4) : Bm;
            cp16(&Bs[buf][r * 32 + ((kf4 ^ (r & 7)) << 2)], src, pr);
        }
        cp_commit();
    };

    stage(0, 0);
    int buf = 0;
    for (int c = 0; c < nchunks; c++) {
        cp_wait0();
        __syncthreads();
        if (c + 1 < nchunks) stage(buf ^ 1, (c + 1) * 32);
#pragma unroll
        for (int k4 = 0; k4 < 8; k4++) {
            ulonglong2 a[4], b[4];
#pragma unroll
            for (int q = 0; q < 4; q++) {
                int r = ty + 16 * q;
                a[q] = *reinterpret_cast<const ulonglong2*>(
                    &As[buf][r * 32 + ((k4 ^ (r & 7)) << 2)]);
            }
#pragma unroll
            for (int p = 0; p < 4; p++) {
                int r = tx + 8 * p;
                b[p] = *reinterpret_cast<const ulonglong2*>(
                    &Bs[buf][r * 32 + ((k4 ^ (r & 7)) << 2)]);
            }
#pragma unroll
            for (int q = 0; q < 4; q++)
#pragma unroll
                for (int p = 0; p < 4; p++) {
                    acc[q][p] = ffma2(a[q].x, b[p].x, acc[q][p]);
                    acc[q][p] = ffma2(a[q].y, b[p].y, acc[q][p]);
                }
        }
        buf ^= 1;
    }

#pragma unroll
    for (int q = 0; q < 4; q++) {
        int gm = m0 + ty + 16 * q;
#pragma unroll
        for (int p = 0; p < 4; p++) {
            int gn = n0 + tx + 8 * p;
            if (gn >= N) continue;
            float v = unpack_sum(acc[q][p]);
            if (bias) v += bias[gn];
            if (act == 2) v = sigmoidf_(v);
            C[(size_t)gm * N + gn] = v;
        }
    }
}

// ---------------------------------------------------------------------------
// ONE prep kernel: zero h/barriers, last-visit idx, molstart, all weight
// transposes, masked weight, padded bias. All sections independent.
// ---------------------------------------------------------------------------
__global__ void prep_all_kernel(const int* __restrict__ mask,
                                const int* __restrict__ seg,
                                const float* __restrict__ w_query,
                                const float* __restrict__ w_g0,
                                const float* __restrict__ w_g1,
                                const float* __restrict__ w_bip,
                                const float* __restrict__ w_masklin,
                                const float* __restrict__ ddi,
                                const float* __restrict__ b_bip)
{
    const int gid = blockIdx.x * blockDim.x + threadIdx.x;
    const int stride = gridDim.x * blockDim.x;

    for (int i = gid; i < 2 * BB * HH; i += stride) g_h[0][i] = 0.f;
    for (int i = gid; i < 8 * 32; i += stride) g_bar[i] = 0;
    for (int i = gid; i < BB; i += stride) {
        int s = 0;
        for (int j = 0; j < SS; j++) s += mask[i * SS + j];
        g_idxlast[i] = s - 1;
    }
    for (int i = gid; i < NATOMS; i += stride) {
        if (i == 0) {
            g_molstart[seg[0]] = 0;
            g_molstart[NMOL] = NATOMS;
        } else if (seg[i] != seg[i - 1]) {
            g_molstart[seg[i]] = i;
        }
    }
    // wqT[c][k] = w_query[k][c]   ([512,256] -> [256,512])
    for (int i = gid; i < HH * 2 * HH; i += stride) {
        int c = i / (2 * HH), k = i - c * (2 * HH);
        g_wqT[i] = w_query[k * HH + c];
    }
    // wg0T / wg1T ([256,256] transposes)
    for (int i = gid; i < HH * HH; i += stride) {
        int c = i / HH, k = i - c * HH;
        g_wg0T[i] = w_g0[k * HH + c];
        g_wg1T[i] = w_g1[k * HH + c];
    }
    // wbipT[k][c] = w_bip[c][k]   ([256,491] -> [496,256], pad rows zero)
    for (int i = gid; i < NSUBP * HH; i += stride) {
        int k = i / HH, c = i - k * HH;
        g_wbipT[i] = (k < NSUB) ? w_bip[c * NSUB + k] : 0.f;
    }
    // wmT[j][k] = w_masklin[k][j] * ddi[j][k]  (padded)
    for (int i = gid; i < LBL * NSUBP; i += stride) {
        int j = i / NSUBP, k = i - j * NSUBP;
        g_wmT[i] = (k < NSUB) ? w_masklin[k * LBL + j] * ddi[j * NSUB + k] : 0.f;
    }
    for (int i = gid; i < NSUBP; i += stride)
        g_bbip[i] = (i < NSUB) ? b_bip[i] : 0.f;
}

// ---------------------------------------------------------------------------
// Persistent GRU (unchanged from R13): single launch, 32 steps, split-K
// cp.async staging, tid0-fence inter-block barrier. 128 blocks x 256 thr.
// ---------------------------------------------------------------------------
__global__ void __launch_bounds__(256)
gru_persist_kernel(const float* __restrict__ whh_c, const float* __restrict__ whh_p,
                   const float* __restrict__ bhh_c, const float* __restrict__ bhh_p)
{
    extern __shared__ float sm[];
    float* w_s = sm;                 // [48][258]
    float* h_s = sm + 48 * 258;      // [64][256]
    const int tid = threadIdx.x;
    const int c = tid & 15;
    const int bq = tid >> 4;
    const int g  = blockIdx.z;
    const int c0 = blockIdx.x * 16;
    const int b0 = blockIdx.y * 64;
    const int grp = blockIdx.y + 4 * blockIdx.z;
    const float* whh = g ? whh_p : whh_c;
    const float* bhh = g ? bhh_p : bhh_c;
    const int col = c0 + c;

#pragma unroll
    for (int j = 0; j < 24; j++) {
        int idx = tid + 256 * j;
        int r = idx >> 7, f2 = idx & 127;
        int grow = (r >> 4) * HH + c0 + (r & 15);
        cp8(w_s + r * 258 + f2 * 2, whh + (size_t)grow * HH + f2 * 2, true);
    }
    cp_commit();

    const float bh_r = bhh[col];
    const float bh_z = bhh[HH + col];
    const float bh_n = bhh[2 * HH + col];
    const int idxl[4] = {g_idxlast[b0 + bq], g_idxlast[b0 + bq + 16],
                         g_idxlast[b0 + bq + 32], g_idxlast[b0 + bq + 48]};

    for (int t = 0; t < SS; t++) {
        const float* hsrc = g_h[t & 1] + g * (BB * HH);
#pragma unroll
        for (int j = 0; j < 8; j++) {
            int idx = tid + 256 * j;
            int r = idx >> 5, f4 = idx & 31;
            cp16(h_s + r * 256 + f4 * 4, hsrc + (b0 + r) * HH + f4 * 4, true);
        }
        cp_commit();                                   // group A
#pragma unroll
        for (int j = 0; j < 8; j++) {
            int idx = tid + 256 * j;
            int r = idx >> 5, f4 = idx & 31;
            cp16(h_s + r * 256 + 128 + f4 * 4,
                 hsrc + (b0 + r) * HH + 128 + f4 * 4, true);
        }
        cp_commit();                                   // group B

        float xr[4][3];
#pragma unroll
        for (int i = 0; i < 4; i++) {
            int b = b0 + bq + 16 * i;
            const float* xp = g_xp + ((size_t)g * BB * SS + (size_t)b * SS + t) * (3 * HH);
            xr[i][0] = __ldg(xp + col);
            xr[i][1] = __ldg(xp + HH + col);
            xr[i][2] = __ldg(xp + 2 * HH + col);
        }

        unsigned long long acc[4][3];
#pragma unroll
        for (int i = 0; i < 4; i++)
#pragma unroll
            for (int gt = 0; gt < 3; gt++) acc[i][gt] = 0ull;

        cp_wait1();
        __syncthreads();

#pragma unroll 8
        for (int k2 = 0; k2 < 64; k2++) {
            unsigned long long h2[4], w2[3];
#pragma unroll
            for (int i = 0; i < 4; i++)
                h2[i] = lds64(h_s + (bq + 16 * i) * 256 + 2 * k2);
#pragma unroll
            for (int gt = 0; gt < 3; gt++)
                w2[gt] = lds64(w_s + (gt * 16 + c) * 258 + 2 * k2);
#pragma unroll
            for (int i = 0; i < 4; i++)
#pragma unroll
                for (int gt = 0; gt < 3; gt++)
                    acc[i][gt] = ffma2(h2[i], w2[gt], acc[i][gt]);
        }

        cp_wait0();
        __syncthreads();

#pragma unroll 8
        for (int k2 = 64; k2 < 128; k2++) {
            unsigned long long h2[4], w2[3];
#pragma unroll
            for (int i = 0; i < 4; i++)
                h2[i] = lds64(h_s + (bq + 16 * i) * 256 + 2 * k2);
#pragma unroll
            for (int gt = 0; gt < 3; gt++)
                w2[gt] = lds64(w_s + (gt * 16 + c) * 258 + 2 * k2);
#pragma unroll
            for (int i = 0; i < 4; i++)
#pragma unroll
                for (int gt = 0; gt < 3; gt++)
                    acc[i][gt] = ffma2(h2[i], w2[gt], acc[i][gt]);
        }

        float* hdst = g_h[(t + 1) & 1] + g * (BB * HH);
#pragma unroll
        for (int i = 0; i < 4; i++) {
            int b = b0 + bq + 16 * i;
            float hr = unpack_sum(acc[i][0]) + bh_r;
            float hz = unpack_sum(acc[i][1]) + bh_z;
            float hn = unpack_sum(acc[i][2]) + bh_n;
            float r = sigmoidf_(xr[i][0] + hr);
            float z = sigmoidf_(xr[i][1] + hz);
            float n = tanhf(xr[i][2] + r * hn);
            float hp = h_s[(bq + 16 * i) * 256 + col];
            float hnew = (1.f - z) * n + z * hp;
            hdst[b * HH + col] = hnew;
            if (t == idxl[i])
                g_pat[b * (2 * HH) + g * HH + col] = fmaxf(hnew, 0.f);
        }

        if (t + 1 < SS) {
            __syncthreads();
            if (tid == 0) {
                __threadfence();
                atomicAdd(&g_bar[grp * 32], 1);
                int tgt = 16 * (t + 1);
                while (*(volatile int*)&g_bar[grp * 32] < tgt) {
                    __nanosleep(64);
                }
                __threadfence();
            }
            __syncthreads();
        }
    }
}

// ---------------------------------------------------------------------------
// Block-diagonal adjacency pass 1: v = hv + adj_block @ hv (per molecule)
// ---------------------------------------------------------------------------
__global__ void adj_kernel(const float* __restrict__ adj) {
    int m = blockIdx.x, tid = threadIdx.x;
    int s = g_molstart[m], e = g_molstart[m + 1];
    int na = e - s;
    __shared__ float hs[14][HH];
    __shared__ float as[14][14];
    for (int a = 0; a < na; a++) hs[a][tid] = g_hv[(s + a) * HH + tid];
    for (int idx = tid; idx < na * na; idx += 256) {
        int i = idx / na, j = idx - i * na;
        as[i][j] = adj[(size_t)(s + i) * NATOMS + (s + j)];
    }
    __syncthreads();
    for (int i = 0; i < na; i++) {
        float acc = hs[i][tid];
        for (int j = 0; j < na; j++) acc = fmaf(as[i][j], hs[j][tid], acc);
        g_v[(s + i) * HH + tid] = acc;
    }
}

// ---------------------------------------------------------------------------
// Fused adjacency pass 2 + segment sum -> molsumT [H][NMOL]
// ---------------------------------------------------------------------------
__global__ void adj_molsum_kernel(const float* __restrict__ adj) {
    int m = blockIdx.x, tid = threadIdx.x;
    int s = g_molstart[m], e = g_molstart[m + 1];
    int na = e - s;
    __shared__ float hs[14][HH];
    __shared__ float as[14][14];
    for (int a = 0; a < na; a++) hs[a][tid] = g_hv[(s + a) * HH + tid];
    for (int idx = tid; idx < na * na; idx += 256) {
        int i = idx / na, j = idx - i * na;
        as[i][j] = adj[(size_t)(s + i) * NATOMS + (s + j)];
    }
    __syncthreads();
    float sum = 0.f;
    for (int i = 0; i < na; i++) {
        float acc = hs[i][tid];
        for (int j = 0; j < na; j++) acc = fmaf(as[i][j], hs[j][tid], acc);
        sum += acc;
    }
    g_molsumT[tid * NMOL + m] = sum;
}

// ---------------------------------------------------------------------------
// x2 = match + match @ w_out + b_out; layernorm -> g_att
// ---------------------------------------------------------------------------
__global__ void att_kernel(const float* __restrict__ w_out, const float* __restrict__ b_out,
                           const float* __restrict__ gamma, const float* __restrict__ beta)
{
    int b = blockIdx.x, tid = threadIdx.x;
    __shared__ float mrow[LBL];
    __shared__ float red[256];
    if (tid < LBL) mrow[tid] = g_match[b * LBL + tid];
    __syncthreads();
    float x2 = 0.f;
    if (tid < LBL) {
        float acc = 0.f;
        for (int k = 0; k < LBL; k++) acc = fmaf(mrow[k], w_out[k * LBL + tid], acc);
        x2 = mrow[tid] + acc + b_out[tid];
    }
    red[tid] = (tid < LBL) ? x2 : 0.f;
    __syncthreads();
    for (int s2 = 128; s2 > 0; s2 >>= 1) {
        if (tid < s2) red[tid] += red[tid + s2];
        __syncthreads();
    }
    float mean = red[0] * (1.f / LBL);
    __syncthreads();
    float d = x2 - mean;
    red[tid] = (tid < LBL) ? d * d : 0.f;
    __syncthreads();
    for (int s2 = 128; s2 > 0; s2 >>= 1) {
        if (tid < s2) red[tid] += red[tid + s2];
        __syncthreads();
    }
    float var = red[0] * (1.f / LBL);
    if (tid < LBL)
        g_att[b * LBL + tid] = d * rsqrtf(var + 1e-5f) * gamma[tid] + beta[tid];
}

// ---------------------------------------------------------------------------
// Launch orchestration — 11 kernels, 2 events, 2 streams
// ---------------------------------------------------------------------------
extern "C" void kernel_launch(void* const* d_in, const int* in_sizes, int n_in,
                              void* d_out, int out_size) {
    const float* x_c      = (const float*)d_in[0];
    const float* x_p      = (const float*)d_in[1];
    const int*   mask     = (const int*)  d_in[2];
    const float* w_ih_c   = (const float*)d_in[3];
    const float* w_hh_c   = (const float*)d_in[4];
    const float* b_ih_c   = (const float*)d_in[5];
    const float* b_hh_c   = (const float*)d_in[6];
    const float* w_ih_p   = (const float*)d_in[7];
    const float* w_hh_p   = (const float*)d_in[8];
    const float* b_ih_p   = (const float*)d_in[9];
    const float* b_hh_p   = (const float*)d_in[10];
    const float* w_query  = (const float*)d_in[11];
    const float* b_query  = (const float*)d_in[12];
    const float* w_bip    = (const float*)d_in[13];
    const float* b_bip    = (const float*)d_in[14];
    const float* w_mlin   = (const float*)d_in[15];
    const float* ddi      = (const float*)d_in[16];
    const float* embed_fp = (const float*)d_in[17];
    const int*   fp       = (const int*)  d_in[18];
    const float* adj      = (const float*)d_in[19];
    const int*   seg      = (const int*)  d_in[20];
    const float* w_g0     = (const float*)d_in[21];
    const float* b_g0     = (const float*)d_in[22];
    const float* w_g1     = (const float*)d_in[23];
    const float* b_g1     = (const float*)d_in[24];
    const float* avgproj  = (const float*)d_in[25];
    const float* w_out    = (const float*)d_in[26];
    const float* b_out    = (const float*)d_in[27];
    const float* ln_g     = (const float*)d_in[28];
    const float* ln_b     = (const float*)d_in[29];
    float* outp = (float*)d_out;

    float *xp, *pat, *query, *v, *hv, *molsumT, *emb, *wmT, *att, *bip;
    float *wg0T, *wg1T, *wqT, *bbip;
    cudaGetSymbolAddress((void**)&xp,      g_xp);
    cudaGetSymbolAddress((void**)&pat,     g_pat);
    cudaGetSymbolAddress((void**)&query,   g_query);
    cudaGetSymbolAddress((void**)&v,       g_v);
    cudaGetSymbolAddress((void**)&hv,      g_hv);
    cudaGetSymbolAddress((void**)&molsumT, g_molsumT);
    cudaGetSymbolAddress((void**)&emb,     g_emb);
    cudaGetSymbolAddress((void**)&wmT,     g_wmT);
    cudaGetSymbolAddress((void**)&att,     g_att);
    cudaGetSymbolAddress((void**)&bip,     g_bip);
    cudaGetSymbolAddress((void**)&wg0T,    g_wg0T);
    cudaGetSymbolAddress((void**)&wg1T,    g_wg1T);
    cudaGetSymbolAddress((void**)&wqT,     g_wqT);
    cudaGetSymbolAddress((void**)&bbip,    g_bbip);

    const int GEMMF_SMEM = (2 * 128 * 32 + 2 * 64 * 32) * 4;        // 49152
    const int GRU_SMEM   = (48 * 258 + 64 * 256) * 4;               // 115072

    static cudaStream_t s2 = nullptr;
    static cudaEvent_t evFork = nullptr, evJoin2 = nullptr;
    if (!s2) {
        cudaStreamCreateWithFlags(&s2, cudaStreamNonBlocking);
        cudaEventCreateWithFlags(&evFork, cudaEventDisableTiming);
        cudaEventCreateWithFlags(&evJoin2, cudaEventDisableTiming);
        cudaFuncSetAttribute(gemm_f, cudaFuncAttributeMaxDynamicSharedMemorySize, GEMMF_SMEM);
        cudaFuncSetAttribute(gemm_proj, cudaFuncAttributeMaxDynamicSharedMemorySize, GEMMF_SMEM);
        cudaFuncSetAttribute(gru_persist_kernel, cudaFuncAttributeMaxDynamicSharedMemorySize, GRU_SMEM);
    }

    // 1. all prep in one kernel (main)
    prep_all_kernel<<<296, 256>>>(mask, seg, w_query, w_g0, w_g1, w_bip,
                                  w_mlin, ddi, b_bip);

    // fork MPNN branch (depends on prep_all outputs: wg0T/wg1T/molstart)
    cudaEventRecord(evFork, 0);
    cudaStreamWaitEvent(s2, evFork, 0);
    {
        dim3 grid(HH / 64, (NATOMS + 127) / 128);
        gemm_f<<<grid, 256, GEMMF_SMEM, s2>>>(embed_fp, wg0T, b_g0, hv,
                                              NATOMS, HH, HH, 1, fp);
        adj_kernel<<<NMOL, HH, 0, s2>>>(adj);
        gemm_f<<<grid, 256, GEMMF_SMEM, s2>>>(v, wg1T, b_g1, hv,
                                              NATOMS, HH, HH, 1, nullptr);
        adj_molsum_kernel<<<NMOL, HH, 0, s2>>>(adj);
        gemm_s<<<dim3(8, 4), 128, 0, s2>>>(avgproj, molsumT, nullptr, nullptr, emb,
                                           LBL, HH, NMOL, 0);
        cudaEventRecord(evJoin2, s2);
    }

    // 2. both input projections in one launch (main, overlaps MPNN)
    gemm_proj<<<dim3(12, 64, 2), 256, GEMMF_SMEM>>>(
        x_c, x_p, w_ih_c, w_ih_p, b_ih_c, b_ih_p,
        xp, xp + (size_t)BB * SS * 3 * HH);

    // 3. join MPNN, then persistent GRU owns the chip
    cudaStreamWaitEvent(0, evJoin2, 0);
    gru_persist_kernel<<<dim3(16, 4, 2), 256, GRU_SMEM>>>(w_hh_c, w_hh_p, b_hh_c, b_hh_p);

    // 4. tail (main): query -> (match,bip) -> att -> out
    gemm_s<<<dim3(8, 4), 128>>>(pat, wqT, b_query, nullptr, query, BB, HH, 2 * HH, 0);
    gemm_tail2<<<dim3(16, 4, 2), 128>>>();
    att_kernel<<<BB, 256>>>(w_out, b_out, ln_g, ln_b);
    gemm_s<<<dim3(7, 4), 128>>>(bip, wmT, nullptr, att, outp, BB, LBL, NSUBP, 0);
}

// round 16
// speedup vs baseline: 2.6010x; 1.0125x over previous
#include <cuda_runtime.h>
#include <cstdint>
#include <cstddef>

// ---------------------------------------------------------------------------
// Problem constants
// ---------------------------------------------------------------------------
#define BB    256      // batch
#define SS    32       // seq len
#define II    128      // input dim
#define HH    256      // hidden
#define LBL   200      // label
#define NSUB  491
#define NSUBP 496      // NSUB padded to multiple of 4 floats
#define NATOMS 8000
#define NMOL  600

// ---------------------------------------------------------------------------
// Scratch (static __device__ — no allocation anywhere)
// ---------------------------------------------------------------------------
__device__ __align__(16) float g_xp[2 * BB * SS * 3 * HH];
__device__ __align__(16) float g_h[2][2 * BB * HH];
__device__ int   g_idxlast[BB];
__device__ int   g_molstart[NMOL + 1];
__device__ int   g_bar[8 * 32];                        // 8 barrier groups, 128B apart
__device__ __align__(16) float g_pat[BB * 2 * HH];     // relu(h_last) written by GRU
__device__ __align__(16) float g_query[BB * HH];
__device__ __align__(16) float g_v[NATOMS * HH];
__device__ __align__(16) float g_hv[NATOMS * HH];
__device__ __align__(16) float g_molsumT[HH * NMOL];   // transposed [H][NMOL]
__device__ __align__(16) float g_emb[LBL * HH];
__device__ __align__(16) float g_match[BB * LBL];
__device__ __align__(16) float g_att[BB * LBL];
__device__ __align__(16) float g_bip[BB * NSUBP];      // padded stride
__device__ __align__(16) float g_wmT[LBL * NSUBP];     // masked weight, transposed+padded
__device__ __align__(16) float g_bbip[NSUBP];          // padded bias
// pre-transposed weights (all fast GEMMs are transB with K-contiguous rows)
__device__ __align__(16) float g_wqT[HH * 2 * HH];     // [256][512]
__device__ __align__(16) float g_wg0T[HH * HH];
__device__ __align__(16) float g_wg1T[HH * HH];
__device__ __align__(16) float g_wbipT[NSUBP * HH];    // [496][256], rows 491..495 zero

// ---------------------------------------------------------------------------
// Helpers
// ---------------------------------------------------------------------------
__device__ __forceinline__ unsigned long long ffma2(unsigned long long a,
                                                    unsigned long long b,
                                                    unsigned long long c) {
#if defined(__CUDA_ARCH__) && (__CUDA_ARCH__ >= 1000)
    unsigned long long d;
    asm("fma.rn.f32x2 %0, %1, %2, %3;" : "=l"(d) : "l"(a), "l"(b), "l"(c));
    return d;
#else
    float2 af = *reinterpret_cast<float2*>(&a);
    float2 bf = *reinterpret_cast<float2*>(&b);
    float2 cf = *reinterpret_cast<float2*>(&c);
    float2 df;
    df.x = fmaf(af.x, bf.x, cf.x);
    df.y = fmaf(af.y, bf.y, cf.y);
    return *reinterpret_cast<unsigned long long*>(&df);
#endif
}

__device__ __forceinline__ unsigned long long lds64(const float* p) {
    return *reinterpret_cast<const unsigned long long*>(p);
}

__device__ __forceinline__ float unpack_sum(unsigned long long u) {
    return __uint_as_float((unsigned)u) + __uint_as_float((unsigned)(u >> 32));
}

__device__ __forceinline__ float sigmoidf_(float x) {
    return 1.f / (1.f + expf(-x));
}

__device__ __forceinline__ void cp16(float* dst, const float* src, bool p) {
    unsigned s = (unsigned)__cvta_generic_to_shared(dst);
    int n = p ? 16 : 0;
    asm volatile("cp.async.ca.shared.global [%0], [%1], 16, %2;"
                 :: "r"(s), "l"(src), "r"(n));
}
__device__ __forceinline__ void cp8(float* dst, const float* src, bool p) {
    unsigned s = (unsigned)__cvta_generic_to_shared(dst);
    int n = p ? 8 : 0;
    asm volatile("cp.async.ca.shared.global [%0], [%1], 8, %2;"
                 :: "r"(s), "l"(src), "r"(n));
}
__device__ __forceinline__ void cp_commit() { asm volatile("cp.async.commit_group;"); }
__device__ __forceinline__ void cp_wait0()  { asm volatile("cp.async.wait_group 0;"); }
__device__ __forceinline__ void cp_wait1()  { asm volatile("cp.async.wait_group 1;"); }

// ---------------------------------------------------------------------------
// Fast GEMM (transB): C[M,N] = act( A[M,K] * B[N,K]^T + bias )
// 128x64 block tile, 256 threads, double-buffered cp.async smem AND
// double-buffered register fragments (hide the 29-cyc LDS latency).
// Optional rowidx: A row gm is read from A[rowidx[gm]] (fused gather).
// ---------------------------------------------------------------------------
__global__ void __launch_bounds__(256, 1)
gemm_f(const float* __restrict__ A, const float* __restrict__ Bm,
       const float* __restrict__ bias,
       float* __restrict__ C, int M, int N, int K, int act,
       const int* __restrict__ rowidx)
{
    extern __shared__ float sm[];
    float* As = sm;                 // [2][128][32]
    float* Bs = sm + 2 * 128 * 32;  // [2][64][32]
    const int tid = threadIdx.x;
    const int tx = tid & 15, ty = tid >> 4;
    const int m0 = blockIdx.y * 128, n0 = blockIdx.x * 64;
    const int nchunks = (K + 31) / 32;

    unsigned long long acc[8][4];
#pragma unroll
    for (int q = 0; q < 8; q++)
#pragma unroll
        for (int p = 0; p < 4; p++) acc[q][p] = 0ull;

    auto stage = [&](int buf, int k0) {
        float* Ab = As + buf * (128 * 32);
        float* Bb = Bs + buf * (64 * 32);
#pragma unroll
        for (int j = 0; j < 4; j++) {
            int idx = tid + 256 * j;
            int r = idx >> 3, kf4 = idx & 7;
            int gm = m0 + r, gk = k0 + kf4 * 4;
            bool pr = (gm < M) && (gk < K);
            int grow = pr ? (rowidx ? rowidx[gm] : gm) : 0;
            const float* src = pr ? (A + (size_t)grow * K + gk) : A;
            cp16(Ab + r * 32 + ((kf4 ^ (r & 7)) << 2), src, pr);
        }
#pragma unroll
        for (int j = 0; j < 2; j++) {
            int idx = tid + 256 * j;
            int r = idx >> 3, kf4 = idx & 7;
            int gn = n0 + r, gk = k0 + kf4 * 4;
            bool pr = (gn < N) && (gk < K);
            const float* src = pr ? (Bm + (size_t)gn * K + gk) : Bm;
            cp16(Bb + r * 32 + ((kf4 ^ (r & 7)) << 2), src, pr);
        }
        cp_commit();
    };

    stage(0, 0);
    int buf = 0;
    for (int c = 0; c < nchunks; c++) {
        cp_wait0();
        __syncthreads();
        if (c + 1 < nchunks) stage(buf ^ 1, (c + 1) * 32);
        const float* Ab = As + buf * (128 * 32);
        const float* Bb = Bs + buf * (64 * 32);

        ulonglong2 a[2][8], b[2][4];
        // preload fragments for k4 = 0
#pragma unroll
        for (int q = 0; q < 8; q++) {
            int r = ty + 16 * q;
            a[0][q] = *reinterpret_cast<const ulonglong2*>(
                Ab + r * 32 + (((0) ^ (r & 7)) << 2));
        }
#pragma unroll
        for (int p = 0; p < 4; p++) {
            int r = tx + 16 * p;
            b[0][p] = *reinterpret_cast<const ulonglong2*>(
                Bb + r * 32 + (((0) ^ (r & 7)) << 2));
        }
#pragma unroll
        for (int k4 = 0; k4 < 8; k4++) {
            const int cur = k4 & 1, nxt = cur ^ 1;
            if (k4 < 7) {
#pragma unroll
                for (int q = 0; q < 8; q++) {
                    int r = ty + 16 * q;
                    a[nxt][q] = *reinterpret_cast<const ulonglong2*>(
                        Ab + r * 32 + (((k4 + 1) ^ (r & 7)) << 2));
                }
#pragma unroll
                for (int p = 0; p < 4; p++) {
                    int r = tx + 16 * p;
                    b[nxt][p] = *reinterpret_cast<const ulonglong2*>(
                        Bb + r * 32 + (((k4 + 1) ^ (r & 7)) << 2));
                }
            }
#pragma unroll
            for (int q = 0; q < 8; q++)
#pragma unroll
                for (int p = 0; p < 4; p++) {
                    acc[q][p] = ffma2(a[cur][q].x, b[cur][p].x, acc[q][p]);
                    acc[q][p] = ffma2(a[cur][q].y, b[cur][p].y, acc[q][p]);
                }
        }
        buf ^= 1;
    }

#pragma unroll
    for (int q = 0; q < 8; q++) {
        int gm = m0 + ty + 16 * q;
        if (gm >= M) continue;
#pragma unroll
        for (int p = 0; p < 4; p++) {
            int gn = n0 + tx + 16 * p;
            if (gn >= N) continue;
            float v = unpack_sum(acc[q][p]);
            if (bias) v += bias[gn];
            if (act == 1) v = fmaxf(v, 0.f);
            C[(size_t)gm * N + gn] = v;
        }
    }
}

// ---------------------------------------------------------------------------
// Both GRU input projections in ONE launch: z selects (x, w, b, out).
// Same register-fragment double buffering as gemm_f.
// ---------------------------------------------------------------------------
__global__ void __launch_bounds__(256, 1)
gemm_proj(const float* __restrict__ A0, const float* __restrict__ A1,
          const float* __restrict__ B0, const float* __restrict__ B1,
          const float* __restrict__ bias0, const float* __restrict__ bias1,
          float* __restrict__ C0, float* __restrict__ C1)
{
    const int M = BB * SS, N = 3 * HH, K = II;
    const float* A    = blockIdx.z ? A1 : A0;
    const float* Bm   = blockIdx.z ? B1 : B0;
    const float* bias = blockIdx.z ? bias1 : bias0;
    float* C          = blockIdx.z ? C1 : C0;

    extern __shared__ float sm[];
    float* As = sm;
    float* Bs = sm + 2 * 128 * 32;
    const int tid = threadIdx.x;
    const int tx = tid & 15, ty = tid >> 4;
    const int m0 = blockIdx.y * 128, n0 = blockIdx.x * 64;
    const int nchunks = K / 32;   // 4

    unsigned long long acc[8][4];
#pragma unroll
    for (int q = 0; q < 8; q++)
#pragma unroll
        for (int p = 0; p < 4; p++) acc[q][p] = 0ull;

    auto stage = [&](int buf, int k0) {
        float* Ab = As + buf * (128 * 32);
        float* Bb = Bs + buf * (64 * 32);
#pragma unroll
        for (int j = 0; j < 4; j++) {
            int idx = tid + 256 * j;
            int r = idx >> 3, kf4 = idx & 7;
            cp16(Ab + r * 32 + ((kf4 ^ (r & 7)) << 2),
                 A + (size_t)(m0 + r) * K + k0 + kf4 * 4, true);
        }
#pragma unroll
        for (int j = 0; j < 2; j++) {
            int idx = tid + 256 * j;
            int r = idx >> 3, kf4 = idx & 7;
            cp16(Bb + r * 32 + ((kf4 ^ (r & 7)) << 2),
                 Bm + (size_t)(n0 + r) * K + k0 + kf4 * 4, true);
        }
        cp_commit();
    };

    stage(0, 0);
    int buf = 0;
    for (int c = 0; c < nchunks; c++) {
        cp_wait0();
        __syncthreads();
        if (c + 1 < nchunks) stage(buf ^ 1, (c + 1) * 32);
        const float* Ab = As + buf * (128 * 32);
        const float* Bb = Bs + buf * (64 * 32);

        ulonglong2 a[2][8], b[2][4];
#pragma unroll
        for (int q = 0; q < 8; q++) {
            int r = ty + 16 * q;
            a[0][q] = *reinterpret_cast<const ulonglong2*>(
                Ab + r * 32 + (((0) ^ (r & 7)) << 2));
        }
#pragma unroll
        for (int p = 0; p < 4; p++) {
            int r = tx + 16 * p;
            b[0][p] = *reinterpret_cast<const ulonglong2*>(
                Bb + r * 32 + (((0) ^ (r & 7)) << 2));
        }
#pragma unroll
        for (int k4 = 0; k4 < 8; k4++) {
            const int cur = k4 & 1, nxt = cur ^ 1;
            if (k4 < 7) {
#pragma unroll
                for (int q = 0; q < 8; q++) {
                    int r = ty + 16 * q;
                    a[nxt][q] = *reinterpret_cast<const ulonglong2*>(
                        Ab + r * 32 + (((k4 + 1) ^ (r & 7)) << 2));
                }
#pragma unroll
                for (int p = 0; p < 4; p++) {
                    int r = tx + 16 * p;
                    b[nxt][p] = *reinterpret_cast<const ulonglong2*>(
                        Bb + r * 32 + (((k4 + 1) ^ (r & 7)) << 2));
                }
            }
#pragma unroll
            for (int q = 0; q < 8; q++)
#pragma unroll
                for (int p = 0; p < 4; p++) {
                    acc[q][p] = ffma2(a[cur][q].x, b[cur][p].x, acc[q][p]);
                    acc[q][p] = ffma2(a[cur][q].y, b[cur][p].y, acc[q][p]);
                }
        }
        buf ^= 1;
    }

#pragma unroll
    for (int q = 0; q < 8; q++) {
        int gm = m0 + ty + 16 * q;
#pragma unroll
        for (int p = 0; p < 4; p++) {
            int gn = n0 + tx + 16 * p;
            C[(size_t)gm * N + gn] = unpack_sum(acc[q][p]) + bias[gn];
        }
    }
}

// ---------------------------------------------------------------------------
// Small-M GEMM (transB): 64x32 block tile, 128 threads (unchanged).
// ---------------------------------------------------------------------------
__global__ void __launch_bounds__(128)
gemm_s(const float* __restrict__ A, const float* __restrict__ Bm,
       const float* __restrict__ bias, const float* __restrict__ mul,
       float* __restrict__ C, int M, int N, int K, int act)
{
    __shared__ float As[2][64 * 32];
    __shared__ float Bs[2][32 * 32];
    const int tid = threadIdx.x;
    const int tx = tid & 7, ty = tid >> 3;
    const int m0 = blockIdx.y * 64, n0 = blockIdx.x * 32;
    if (n0 >= N) return;
    const int nchunks = (K + 31) / 32;

    unsigned long long acc[4][4];
#pragma unroll
    for (int q = 0; q < 4; q++)
#pragma unroll
        for (int p = 0; p < 4; p++) acc[q][p] = 0ull;

    auto stage = [&](int buf, int k0) {
#pragma unroll
        for (int j = 0; j < 4; j++) {
            int idx = tid + 128 * j;
            int r = idx >> 3, kf4 = idx & 7;
            int gm = m0 + r, gk = k0 + kf4 * 4;
            bool pr = (gm < M) && (gk < K);
            const float* src = pr ? (A + (size_t)gm * K + gk) : A;
            cp16(&As[buf][r * 32 + ((kf4 ^ (r & 7)) << 2)], src, pr);
        }
#pragma unroll
        for (int j = 0; j < 2; j++) {
            int idx = tid + 128 * j;
            int r = idx >> 3, kf4 = idx & 7;
            int gn = n0 + r, gk = k0 + kf4 * 4;
            bool pr = (gn < N) && (gk < K);
            const float* src = pr ? (Bm + (size_t)gn * K + gk) : Bm;
            cp16(&Bs[buf][r * 32 + ((kf4 ^ (r & 7)) << 2)], src, pr);
        }
        cp_commit();
    };

    stage(0, 0);
    int buf = 0;
    for (int c = 0; c < nchunks; c++) {
        cp_wait0();
        __syncthreads();
        if (c + 1 < nchunks) stage(buf ^ 1, (c + 1) * 32);
#pragma unroll
        for (int k4 = 0; k4 < 8; k4++) {
            ulonglong2 a[4], b[4];
#pragma unroll
            for (int q = 0; q < 4; q++) {
                int r = ty + 16 * q;
                a[q] = *reinterpret_cast<const ulonglong2*>(
                    &As[buf][r * 32 + ((k4 ^ (r & 7)) << 2)]);
            }
#pragma unroll
            for (int p = 0; p < 4; p++) {
                int r = tx + 8 * p;
                b[p] = *reinterpret_cast<const ulonglong2*>(
                    &Bs[buf][r * 32 + ((k4 ^ (r & 7)) << 2)]);
            }
#pragma unroll
            for (int q = 0; q < 4; q++)
#pragma unroll
                for (int p = 0; p < 4; p++) {
                    acc[q][p] = ffma2(a[q].x, b[p].x, acc[q][p]);
                    acc[q][p] = ffma2(a[q].y, b[p].y, acc[q][p]);
                }
        }
        buf ^= 1;
    }

#pragma unroll
    for (int q = 0; q < 4; q++) {
        int gm = m0 + ty + 16 * q;
        if (gm >= M) continue;
#pragma unroll
        for (int p = 0; p < 4; p++) {
            int gn = n0 + tx + 8 * p;
            if (gn >= N) continue;
            float v = unpack_sum(acc[q][p]);
            if (bias) v += bias[gn];
            if (act == 1) v = fmaxf(v, 0.f);
            else if (act == 2) v = sigmoidf_(v);
            if (mul) v *= mul[(size_t)gm * N + gn];
            C[(size_t)gm * N + gn] = v;
        }
    }
}

// ---------------------------------------------------------------------------
// Merged tail pair (both consume g_query) — unchanged.
// ---------------------------------------------------------------------------
__global__ void __launch_bounds__(128)
gemm_tail2()
{
    const int z = blockIdx.z;
    const float* Bm   = z ? g_wbipT : g_emb;
    const float* bias = z ? g_bbip  : nullptr;
    float* C          = z ? g_bip   : g_match;
    const int N       = z ? NSUBP   : LBL;
    const int act     = z ? 0       : 2;
    const int M = BB, K = HH;

    __shared__ float As[2][64 * 32];
    __shared__ float Bs[2][32 * 32];
    const int tid = threadIdx.x;
    const int tx = tid & 7, ty = tid >> 3;
    const int m0 = blockIdx.y * 64, n0 = blockIdx.x * 32;
    if (n0 >= N) return;
    const int nchunks = K / 32;

    unsigned long long acc[4][4];
#pragma unroll
    for (int q = 0; q < 4; q++)
#pragma unroll
        for (int p = 0; p < 4; p++) acc[q][p] = 0ull;

    auto stage = [&](int buf, int k0) {
#pragma unroll
        for (int j = 0; j < 4; j++) {
            int idx = tid + 128 * j;
            int r = idx >> 3, kf4 = idx & 7;
            cp16(&As[buf][r * 32 + ((kf4 ^ (r & 7)) << 2)],
                 g_query + (size_t)(m0 + r) * K + k0 + kf4 * 4, true);
        }
#pragma unroll
        for (int j = 0; j < 2; j++) {
            int idx = tid + 128 * j;
            int r = idx >> 3, kf4 = idx & 7;
            int gn = n0 + r;
            bool pr = (gn < N);
            const float* src = pr ? (Bm + (size_t)gn * K + k0 + kf4 * 4) : Bm;
            cp16(&Bs[buf][r * 32 + ((kf4 ^ (r & 7)) << 2)], src, pr);
        }
        cp_commit();
    };

    stage(0, 0);
    int buf = 0;
    for (int c = 0; c < nchunks; c++) {
        cp_wait0();
        __syncthreads();
        if (c + 1 < nchunks) stage(buf ^ 1, (c + 1) * 32);
#pragma unroll
        for (int k4 = 0; k4 < 8; k4++) {
            ulonglong2 a[4], b[4];
#pragma unroll
            for (int q = 0; q < 4; q++) {
                int r = ty + 16 * q;
                a[q] = *reinterpret_cast<const ulonglong2*>(
                    &As[buf][r * 32 + ((k4 ^ (r & 7)) << 2)]);
            }
#pragma unroll
            for (int p = 0; p < 4; p++) {
                int r = tx + 8 * p;
                b[p] = *reinterpret_cast<const ulonglong2*>(
                    &Bs[buf][r * 32 + ((k4 ^ (r & 7)) << 2)]);
            }
#pragma unroll
            for (int q = 0; q < 4; q++)
#pragma unroll
                for (int p = 0; p < 4; p++) {
                    acc[q][p] = ffma2(a[q].x, b[p].x, acc[q][p]);
                    acc[q][p] = ffma2(a[q].y, b[p].y, acc[q][p]);
                }
        }
        buf ^= 1;
    }

#pragma unroll
    for (int q = 0; q < 4; q++) {
        int gm = m0 + ty + 16 * q;
#pragma unroll
        for (int p = 0; p < 4; p++) {
            int gn = n0 + tx + 8 * p;
            if (gn >= N) continue;
            float v = unpack_sum(acc[q][p]);
            if (bias) v += bias[gn];
            if (act == 2) v = sigmoidf_(v);
            C[(size_t)gm * N + gn] = v;
        }
    }
}

// ---------------------------------------------------------------------------
// ONE prep kernel (unchanged; now launched on s2)
// ---------------------------------------------------------------------------
__global__ void prep_all_kernel(const int* __restrict__ mask,
                                const int* __restrict__ seg,
                                const float* __restrict__ w_query,
                                const float* __restrict__ w_g0,
                                const float* __restrict__ w_g1,
                                const float* __restrict__ w_bip,
                                const float* __restrict__ w_masklin,
                                const float* __restrict__ ddi,
                                const float* __restrict__ b_bip)
{
    const int gid = blockIdx.x * blockDim.x + threadIdx.x;
    const int stride = gridDim.x * blockDim.x;

    for (int i = gid; i < 2 * BB * HH; i += stride) g_h[0][i] = 0.f;
    for (int i = gid; i < 8 * 32; i += stride) g_bar[i] = 0;
    for (int i = gid; i < BB; i += stride) {
        int s = 0;
        for (int j = 0; j < SS; j++) s += mask[i * SS + j];
        g_idxlast[i] = s - 1;
    }
    for (int i = gid; i < NATOMS; i += stride) {
        if (i == 0) {
            g_molstart[seg[0]] = 0;
            g_molstart[NMOL] = NATOMS;
        } else if (seg[i] != seg[i - 1]) {
            g_molstart[seg[i]] = i;
        }
    }
    for (int i = gid; i < HH * 2 * HH; i += stride) {
        int c = i / (2 * HH), k = i - c * (2 * HH);
        g_wqT[i] = w_query[k * HH + c];
    }
    for (int i = gid; i < HH * HH; i += stride) {
        int c = i / HH, k = i - c * HH;
        g_wg0T[i] = w_g0[k * HH + c];
        g_wg1T[i] = w_g1[k * HH + c];
    }
    for (int i = gid; i < NSUBP * HH; i += stride) {
        int k = i / HH, c = i - k * HH;
        g_wbipT[i] = (k < NSUB) ? w_bip[c * NSUB + k] : 0.f;
    }
    for (int i = gid; i < LBL * NSUBP; i += stride) {
        int j = i / NSUBP, k = i - j * NSUBP;
        g_wmT[i] = (k < NSUB) ? w_masklin[k * LBL + j] * ddi[j * NSUB + k] : 0.f;
    }
    for (int i = gid; i < NSUBP; i += stride)
        g_bbip[i] = (i < NSUB) ? b_bip[i] : 0.f;
}

// ---------------------------------------------------------------------------
// Persistent GRU: xp prefetched for t+1 before the barrier; pure busy-spin
// (no nanosleep). Grid (16, 4, 2) = 128 blocks, 256 threads.
// ---------------------------------------------------------------------------
__global__ void __launch_bounds__(256)
gru_persist_kernel(const float* __restrict__ whh_c, const float* __restrict__ whh_p,
                   const float* __restrict__ bhh_c, const float* __restrict__ bhh_p)
{
    extern __shared__ float sm[];
    float* w_s = sm;                 // [48][258]
    float* h_s = sm + 48 * 258;      // [64][256]
    const int tid = threadIdx.x;
    const int c = tid & 15;
    const int bq = tid >> 4;
    const int g  = blockIdx.z;
    const int c0 = blockIdx.x * 16;
    const int b0 = blockIdx.y * 64;
    const int grp = blockIdx.y + 4 * blockIdx.z;
    const float* whh = g ? whh_p : whh_c;
    const float* bhh = g ? bhh_p : bhh_c;
    const int col = c0 + c;

#pragma unroll
    for (int j = 0; j < 24; j++) {
        int idx = tid + 256 * j;
        int r = idx >> 7, f2 = idx & 127;
        int grow = (r >> 4) * HH + c0 + (r & 15);
        cp8(w_s + r * 258 + f2 * 2, whh + (size_t)grow * HH + f2 * 2, true);
    }
    cp_commit();

    const float bh_r = bhh[col];
    const float bh_z = bhh[HH + col];
    const float bh_n = bhh[2 * HH + col];
    const int idxl[4] = {g_idxlast[b0 + bq], g_idxlast[b0 + bq + 16],
                         g_idxlast[b0 + bq + 32], g_idxlast[b0 + bq + 48]};

    auto load_xr = [&](int t, float xr[4][3]) {
#pragma unroll
        for (int i = 0; i < 4; i++) {
            int b = b0 + bq + 16 * i;
            const float* xp = g_xp + ((size_t)g * BB * SS + (size_t)b * SS + t) * (3 * HH);
            xr[i][0] = __ldg(xp + col);
            xr[i][1] = __ldg(xp + HH + col);
            xr[i][2] = __ldg(xp + 2 * HH + col);
        }
    };

    float xr[4][3];
    load_xr(0, xr);                                   // prefetch t=0

    for (int t = 0; t < SS; t++) {
        const float* hsrc = g_h[t & 1] + g * (BB * HH);
#pragma unroll
        for (int j = 0; j < 8; j++) {
            int idx = tid + 256 * j;
            int r = idx >> 5, f4 = idx & 31;
            cp16(h_s + r * 256 + f4 * 4, hsrc + (b0 + r) * HH + f4 * 4, true);
        }
        cp_commit();                                   // group A
#pragma unroll
        for (int j = 0; j < 8; j++) {
            int idx = tid + 256 * j;
            int r = idx >> 5, f4 = idx & 31;
            cp16(h_s + r * 256 + 128 + f4 * 4,
                 hsrc + (b0 + r) * HH + 128 + f4 * 4, true);
        }
        cp_commit();                                   // group B

        unsigned long long acc[4][3];
#pragma unroll
        for (int i = 0; i < 4; i++)
#pragma unroll
            for (int gt = 0; gt < 3; gt++) acc[i][gt] = 0ull;

        cp_wait1();
        __syncthreads();

#pragma unroll 8
        for (int k2 = 0; k2 < 64; k2++) {
            unsigned long long h2[4], w2[3];
#pragma unroll
            for (int i = 0; i < 4; i++)
                h2[i] = lds64(h_s + (bq + 16 * i) * 256 + 2 * k2);
#pragma unroll
            for (int gt = 0; gt < 3; gt++)
                w2[gt] = lds64(w_s + (gt * 16 + c) * 258 + 2 * k2);
#pragma unroll
            for (int i = 0; i < 4; i++)
#pragma unroll
                for (int gt = 0; gt < 3; gt++)
                    acc[i][gt] = ffma2(h2[i], w2[gt], acc[i][gt]);
        }

        cp_wait0();
        __syncthreads();

#pragma unroll 8
        for (int k2 = 64; k2 < 128; k2++) {
            unsigned long long h2[4], w2[3];
#pragma unroll
            for (int i = 0; i < 4; i++)
                h2[i] = lds64(h_s + (bq + 16 * i) * 256 + 2 * k2);
#pragma unroll
            for (int gt = 0; gt < 3; gt++)
                w2[gt] = lds64(w_s + (gt * 16 + c) * 258 + 2 * k2);
#pragma unroll
            for (int i = 0; i < 4; i++)
#pragma unroll
                for (int gt = 0; gt < 3; gt++)
                    acc[i][gt] = ffma2(h2[i], w2[gt], acc[i][gt]);
        }

        float* hdst = g_h[(t + 1) & 1] + g * (BB * HH);
#pragma unroll
        for (int i = 0; i < 4; i++) {
            int b = b0 + bq + 16 * i;
            float hr = unpack_sum(acc[i][0]) + bh_r;
            float hz = unpack_sum(acc[i][1]) + bh_z;
            float hn = unpack_sum(acc[i][2]) + bh_n;
            float r = sigmoidf_(xr[i][0] + hr);
            float z = sigmoidf_(xr[i][1] + hz);
            float n = tanhf(xr[i][2] + r * hn);
            float hp = h_s[(bq + 16 * i) * 256 + col];
            float hnew = (1.f - z) * n + z * hp;
            hdst[b * HH + col] = hnew;
            if (t == idxl[i])
                g_pat[b * (2 * HH) + g * HH + col] = fmaxf(hnew, 0.f);
        }

        if (t + 1 < SS) {
            load_xr(t + 1, xr);                // prefetch next xp BEFORE barrier
            __syncthreads();
            if (tid == 0) {
                __threadfence();
                atomicAdd(&g_bar[grp * 32], 1);
                int tgt = 16 * (t + 1);
                while (*(volatile int*)&g_bar[grp * 32] < tgt) { }
                __threadfence();
            }
            __syncthreads();
        }
    }
}

// ---------------------------------------------------------------------------
// Block-diagonal adjacency pass 1 (unchanged)
// ---------------------------------------------------------------------------
__global__ void adj_kernel(const float* __restrict__ adj) {
    int m = blockIdx.x, tid = threadIdx.x;
    int s = g_molstart[m], e = g_molstart[m + 1];
    int na = e - s;
    __shared__ float hs[14][HH];
    __shared__ float as[14][14];
    for (int a = 0; a < na; a++) hs[a][tid] = g_hv[(s + a) * HH + tid];
    for (int idx = tid; idx < na * na; idx += 256) {
        int i = idx / na, j = idx - i * na;
        as[i][j] = adj[(size_t)(s + i) * NATOMS + (s + j)];
    }
    __syncthreads();
    for (int i = 0; i < na; i++) {
        float acc = hs[i][tid];
        for (int j = 0; j < na; j++) acc = fmaf(as[i][j], hs[j][tid], acc);
        g_v[(s + i) * HH + tid] = acc;
    }
}

// ---------------------------------------------------------------------------
// Fused adjacency pass 2 + segment sum (unchanged)
// ---------------------------------------------------------------------------
__global__ void adj_molsum_kernel(const float* __restrict__ adj) {
    int m = blockIdx.x, tid = threadIdx.x;
    int s = g_molstart[m], e = g_molstart[m + 1];
    int na = e - s;
    __shared__ float hs[14][HH];
    __shared__ float as[14][14];
    for (int a = 0; a < na; a++) hs[a][tid] = g_hv[(s + a) * HH + tid];
    for (int idx = tid; idx < na * na; idx += 256) {
        int i = idx / na, j = idx - i * na;
        as[i][j] = adj[(size_t)(s + i) * NATOMS + (s + j)];
    }
    __syncthreads();
    float sum = 0.f;
    for (int i = 0; i < na; i++) {
        float acc = hs[i][tid];
        for (int j = 0; j < na; j++) acc = fmaf(as[i][j], hs[j][tid], acc);
        sum += acc;
    }
    g_molsumT[tid * NMOL + m] = sum;
}

// ---------------------------------------------------------------------------
// x2 = match + match @ w_out + b_out; layernorm -> g_att (unchanged)
// ---------------------------------------------------------------------------
__global__ void att_kernel(const float* __restrict__ w_out, const float* __restrict__ b_out,
                           const float* __restrict__ gamma, const float* __restrict__ beta)
{
    int b = blockIdx.x, tid = threadIdx.x;
    __shared__ float mrow[LBL];
    __shared__ float red[256];
    if (tid < LBL) mrow[tid] = g_match[b * LBL + tid];
    __syncthreads();
    float x2 = 0.f;
    if (tid < LBL) {
        float acc = 0.f;
        for (int k = 0; k < LBL; k++) acc = fmaf(mrow[k], w_out[k * LBL + tid], acc);
        x2 = mrow[tid] + acc + b_out[tid];
    }
    red[tid] = (tid < LBL) ? x2 : 0.f;
    __syncthreads();
    for (int s2 = 128; s2 > 0; s2 >>= 1) {
        if (tid < s2) red[tid] += red[tid + s2];
        __syncthreads();
    }
    float mean = red[0] * (1.f / LBL);
    __syncthreads();
    float d = x2 - mean;
    red[tid] = (tid < LBL) ? d * d : 0.f;
    __syncthreads();
    for (int s2 = 128; s2 > 0; s2 >>= 1) {
        if (tid < s2) red[tid] += red[tid + s2];
        __syncthreads();
    }
    float var = red[0] * (1.f / LBL);
    if (tid < LBL)
        g_att[b * LBL + tid] = d * rsqrtf(var + 1e-5f) * gamma[tid] + beta[tid];
}

// ---------------------------------------------------------------------------
// Launch orchestration: s2 = prep + MPNN, main = proj ‖ then GRU + tail
// ---------------------------------------------------------------------------
extern "C" void kernel_launch(void* const* d_in, const int* in_sizes, int n_in,
                              void* d_out, int out_size) {
    const float* x_c      = (const float*)d_in[0];
    const float* x_p      = (const float*)d_in[1];
    const int*   mask     = (const int*)  d_in[2];
    const float* w_ih_c   = (const float*)d_in[3];
    const float* w_hh_c   = (const float*)d_in[4];
    const float* b_ih_c   = (const float*)d_in[5];
    const float* b_hh_c   = (const float*)d_in[6];
    const float* w_ih_p   = (const float*)d_in[7];
    const float* w_hh_p   = (const float*)d_in[8];
    const float* b_ih_p   = (const float*)d_in[9];
    const float* b_hh_p   = (const float*)d_in[10];
    const float* w_query  = (const float*)d_in[11];
    const float* b_query  = (const float*)d_in[12];
    const float* w_bip    = (const float*)d_in[13];
    const float* b_bip    = (const float*)d_in[14];
    const float* w_mlin   = (const float*)d_in[15];
    const float* ddi      = (const float*)d_in[16];
    const float* embed_fp = (const float*)d_in[17];
    const int*   fp       = (const int*)  d_in[18];
    const float* adj      = (const float*)d_in[19];
    const int*   seg      = (const int*)  d_in[20];
    const float* w_g0     = (const float*)d_in[21];
    const float* b_g0     = (const float*)d_in[22];
    const float* w_g1     = (const float*)d_in[23];
    const float* b_g1     = (const float*)d_in[24];
    const float* avgproj  = (const float*)d_in[25];
    const float* w_out    = (const float*)d_in[26];
    const float* b_out    = (const float*)d_in[27];
    const float* ln_g     = (const float*)d_in[28];
    const float* ln_b     = (const float*)d_in[29];
    float* outp = (float*)d_out;

    float *xp, *pat, *query, *v, *hv, *molsumT, *emb, *wmT, *att, *bip;
    float *wg0T, *wg1T, *wqT;
    cudaGetSymbolAddress((void**)&xp,      g_xp);
    cudaGetSymbolAddress((void**)&pat,     g_pat);
    cudaGetSymbolAddress((void**)&query,   g_query);
    cudaGetSymbolAddress((void**)&v,       g_v);
    cudaGetSymbolAddress((void**)&hv,      g_hv);
    cudaGetSymbolAddress((void**)&molsumT, g_molsumT);
    cudaGetSymbolAddress((void**)&emb,     g_emb);
    cudaGetSymbolAddress((void**)&wmT,     g_wmT);
    cudaGetSymbolAddress((void**)&att,     g_att);
    cudaGetSymbolAddress((void**)&bip,     g_bip);
    cudaGetSymbolAddress((void**)&wg0T,    g_wg0T);
    cudaGetSymbolAddress((void**)&wg1T,    g_wg1T);
    cudaGetSymbolAddress((void**)&wqT,     g_wqT);

    const int GEMMF_SMEM = (2 * 128 * 32 + 2 * 64 * 32) * 4;        // 49152
    const int GRU_SMEM   = (48 * 258 + 64 * 256) * 4;               // 115072

    static cudaStream_t s2 = nullptr;
    static cudaEvent_t evFork = nullptr, evJoin2 = nullptr;
    if (!s2) {
        cudaStreamCreateWithFlags(&s2, cudaStreamNonBlocking);
        cudaEventCreateWithFlags(&evFork, cudaEventDisableTiming);
        cudaEventCreateWithFlags(&evJoin2, cudaEventDisableTiming);
        cudaFuncSetAttribute(gemm_f, cudaFuncAttributeMaxDynamicSharedMemorySize, GEMMF_SMEM);
        cudaFuncSetAttribute(gemm_proj, cudaFuncAttributeMaxDynamicSharedMemorySize, GEMMF_SMEM);
        cudaFuncSetAttribute(gru_persist_kernel, cudaFuncAttributeMaxDynamicSharedMemorySize, GRU_SMEM);
    }

    // fork: s2 runs prep + MPNN; main runs proj concurrently
    cudaEventRecord(evFork, 0);
    cudaStreamWaitEvent(s2, evFork, 0);
    {
        prep_all_kernel<<<296, 256, 0, s2>>>(mask, seg, w_query, w_g0, w_g1, w_bip,
                                             w_mlin, ddi, b_bip);
        dim3 grid(HH / 64, (NATOMS + 127) / 128);
        gemm_f<<<grid, 256, GEMMF_SMEM, s2>>>(embed_fp, wg0T, b_g0, hv,
                                              NATOMS, HH, HH, 1, fp);
        adj_kernel<<<NMOL, HH, 0, s2>>>(adj);
        gemm_f<<<grid, 256, GEMMF_SMEM, s2>>>(v, wg1T, b_g1, hv,
                                              NATOMS, HH, HH, 1, nullptr);
        adj_molsum_kernel<<<NMOL, HH, 0, s2>>>(adj);
        gemm_s<<<dim3(8, 4), 128, 0, s2>>>(avgproj, molsumT, nullptr, nullptr, emb,
                                           LBL, HH, NMOL, 0);
        cudaEventRecord(evJoin2, s2);
    }

    // main: both input projections in one launch (overlaps s2)
    gemm_proj<<<dim3(12, 64, 2), 256, GEMMF_SMEM>>>(
        x_c, x_p, w_ih_c, w_ih_p, b_ih_c, b_ih_p,
        xp, xp + (size_t)BB * SS * 3 * HH);

    // join s2 (covers prep_all too), then persistent GRU owns the chip
    cudaStreamWaitEvent(0, evJoin2, 0);
    gru_persist_kernel<<<dim3(16, 4, 2), 256, GRU_SMEM>>>(w_hh_c, w_hh_p, b_hh_c, b_hh_p);

    // tail (main): query -> (match,bip) -> att -> out
    gemm_s<<<dim3(8, 4), 128>>>(pat, wqT, b_query, nullptr, query, BB, HH, 2 * HH, 0);
    gemm_tail2<<<dim3(16, 4, 2), 128>>>();
    att_kernel<<<BB, 256>>>(w_out, b_out, ln_g, ln_b);
    gemm_s<<<dim3(7, 4), 128>>>(bip, wmT, nullptr, att, outp, BB, LBL, NSUBP, 0);
}